// round 1
// baseline (speedup 1.0000x reference)
#include <cuda_runtime.h>
#include <math.h>

#define N_NODES 20000
#define N_EDGES 320000
#define FS      1000
#define XCOLS   1005      // 1 + 1000 + 1 + 3
#define K1      1755
#define K1P     1760      // padded to multiple of 16
#define F1      512
#define F2      256
#define F3      64

// ---------------- scratch (static device memory; no allocs) ----------------
__device__ float g_h0[(size_t)N_NODES * K1P];   // embedded features (padded)
__device__ float g_t [(size_t)N_NODES * F1];    // GEMM output (max width 512)
__device__ float g_agg[(size_t)N_NODES * F1];   // aggregation buffer
__device__ float g_h1[(size_t)N_NODES * F1];    // layer1 output / layer3 output
__device__ float g_h2[(size_t)N_NODES * F2];    // layer2 output
__device__ float g_W1p[(size_t)K1P * F1];       // padded W1
__device__ float g_dinv[N_NODES];               // deg accumulator -> rsqrt(deg+1)

// ---------------- small utility kernels ----------------
__global__ void zero_kernel(float4* p, int n4) {
    int i = blockIdx.x * blockDim.x + threadIdx.x;
    if (i < n4) p[i] = make_float4(0.f, 0.f, 0.f, 0.f);
}

__global__ void deg_kernel(const int* __restrict__ ei, const float* __restrict__ ea) {
    int e = blockIdx.x * blockDim.x + threadIdx.x;
    if (e < N_EDGES) atomicAdd(&g_dinv[ei[N_EDGES + e]], ea[e]);
}

__global__ void dinv_kernel() {
    int i = blockIdx.x * blockDim.x + threadIdx.x;
    if (i < N_NODES) g_dinv[i] = rsqrtf(g_dinv[i] + 1.0f);
}

__global__ void padW1_kernel(const float* __restrict__ W1) {
    int idx = blockIdx.x * blockDim.x + threadIdx.x;
    if (idx < K1P * F1) {
        int r = idx / F1, c = idx % F1;
        g_W1p[idx] = (r < K1) ? W1[(size_t)r * F1 + c] : 0.f;
    }
}

// ---------------- embedding construction ----------------
// h = [layer_table[li] (250) | resnet (1000) | rel_table[ri] (250) | color_table[ci] (3*85)] pad->1760
__global__ void embed_kernel(const float* __restrict__ x,
                             const float* __restrict__ layer_table,
                             const float* __restrict__ rel_table,
                             const float* __restrict__ color_table) {
    int i = blockIdx.x;
    const float* xr = x + (size_t)i * XCOLS;
    float* hr = g_h0 + (size_t)i * K1P;
    int li = (int)xr[0] - 1;                              // {1,2,3} -> {0,1,2}
    int ri = __float2int_rn(fabsf(xr[FS + 1]) * 10.0f);   // round-to-nearest-even (matches jnp.round)
    int c0 = (int)xr[XCOLS - 3];
    int c1 = (int)xr[XCOLS - 2];
    int c2 = (int)xr[XCOLS - 1];

    const float* le = layer_table + (size_t)li * 250;
    const float* re = rel_table   + (size_t)ri * 250;
    const float* e0 = color_table + (size_t)c0 * 85;
    const float* e1 = color_table + (size_t)c1 * 85;
    const float* e2 = color_table + (size_t)c2 * 85;

    for (int j = threadIdx.x; j < 250;  j += blockDim.x) hr[j]        = le[j];
    for (int j = threadIdx.x; j < 1000; j += blockDim.x) hr[250 + j]  = xr[1 + j];
    for (int j = threadIdx.x; j < 250;  j += blockDim.x) hr[1250 + j] = re[j];
    for (int j = threadIdx.x; j < 85;   j += blockDim.x) {
        hr[1500 + j] = e0[j];
        hr[1585 + j] = e1[j];
        hr[1670 + j] = e2[j];
    }
    for (int j = 1755 + threadIdx.x; j < K1P; j += blockDim.x) hr[j] = 0.f;
}

// ---------------- fp32 SGEMM: C[M,Nn] = A[M,K] @ B[K,Nn] ----------------
// BM=128, BN=64, BK=16, 256 threads, 8x4 per thread
__global__ __launch_bounds__(256) void sgemm_kernel(const float* __restrict__ A,
                                                    const float* __restrict__ B,
                                                    float* __restrict__ C,
                                                    int M, int K, int Nn) {
    __shared__ float As[16][128];
    __shared__ float Bs[16][64];
    int tid = threadIdx.x;
    int bm = blockIdx.y * 128;
    int bn = blockIdx.x * 64;

    int arow  = tid >> 2;          // 0..63
    int acol4 = (tid & 3) * 4;     // 0,4,8,12
    int brow  = tid >> 4;          // 0..15
    int bcol4 = (tid & 15) * 4;    // 0..60

    int ty = tid >> 4;             // 0..15 -> 8 rows each
    int tx = tid & 15;             // 0..15 -> 4 cols each

    float acc[8][4];
#pragma unroll
    for (int i = 0; i < 8; i++)
#pragma unroll
        for (int j = 0; j < 4; j++) acc[i][j] = 0.f;

    for (int k0 = 0; k0 < K; k0 += 16) {
#pragma unroll
        for (int p = 0; p < 2; p++) {
            int r = arow + p * 64;
            int gr = bm + r;
            float4 v = make_float4(0.f, 0.f, 0.f, 0.f);
            if (gr < M) v = *(const float4*)(A + (size_t)gr * K + k0 + acol4);
            As[acol4 + 0][r] = v.x;
            As[acol4 + 1][r] = v.y;
            As[acol4 + 2][r] = v.z;
            As[acol4 + 3][r] = v.w;
        }
        {
            float4 v = *(const float4*)(B + (size_t)(k0 + brow) * Nn + bn + bcol4);
            *(float4*)&Bs[brow][bcol4] = v;
        }
        __syncthreads();
#pragma unroll
        for (int kk = 0; kk < 16; kk++) {
            float4 a0 = *(const float4*)&As[kk][ty * 8];
            float4 a1 = *(const float4*)&As[kk][ty * 8 + 4];
            float4 b0 = *(const float4*)&Bs[kk][tx * 4];
            float ar[8] = {a0.x, a0.y, a0.z, a0.w, a1.x, a1.y, a1.z, a1.w};
            float br[4] = {b0.x, b0.y, b0.z, b0.w};
#pragma unroll
            for (int i = 0; i < 8; i++)
#pragma unroll
                for (int j = 0; j < 4; j++) acc[i][j] = fmaf(ar[i], br[j], acc[i][j]);
        }
        __syncthreads();
    }
#pragma unroll
    for (int i = 0; i < 8; i++) {
        int gr = bm + ty * 8 + i;
        if (gr < M) {
            float4 v = make_float4(acc[i][0], acc[i][1], acc[i][2], acc[i][3]);
            *(float4*)(C + (size_t)gr * Nn + bn + tx * 4) = v;
        }
    }
}

// ---------------- edge aggregation (scatter-add) ----------------
// agg[dst] += t[src] * (dinv[src] * ew * dinv[dst]); one warp per edge
__global__ void agg_kernel(const int* __restrict__ ei, const float* __restrict__ ea,
                           const float* __restrict__ t, float* __restrict__ agg, int F) {
    int gwarp = (blockIdx.x * blockDim.x + threadIdx.x) >> 5;
    int lane  = threadIdx.x & 31;
    if (gwarp >= N_EDGES) return;
    int src = ei[gwarp];
    int dst = ei[N_EDGES + gwarp];
    float norm = g_dinv[src] * ea[gwarp] * g_dinv[dst];
    const float* ts = t + (size_t)src * F;
    float* ad = agg + (size_t)dst * F;
    for (int j = lane; j < F; j += 32)
        atomicAdd(ad + j, ts[j] * norm);
}

// ---------------- epilogue: agg + self term + bias, leaky relu ----------------
__global__ void epi_kernel(const float* __restrict__ t, const float* __restrict__ agg,
                           const float* __restrict__ b, float* __restrict__ hout, int F) {
    size_t idx = (size_t)blockIdx.x * blockDim.x + threadIdx.x;
    if (idx < (size_t)N_NODES * F) {
        int i = (int)(idx / F);
        int j = (int)(idx % F);
        float d = g_dinv[i];
        float v = agg[idx] + t[idx] * d * d + b[j];
        hout[idx] = v > 0.f ? v : 0.01f * v;
    }
}

// ---------------- final projection: out = h3 @ Wp + bp ----------------
__global__ void proj_kernel(const float* __restrict__ h, const float* __restrict__ Wp,
                            const float* __restrict__ bp, float* __restrict__ out) {
    __shared__ float w[64 * 3];
    if (threadIdx.x < 192) w[threadIdx.x] = Wp[threadIdx.x];
    __syncthreads();
    int warp = threadIdx.x >> 5, lane = threadIdx.x & 31;
    int i = blockIdx.x * (blockDim.x >> 5) + warp;
    if (i >= N_NODES) return;
    const float* hr = h + (size_t)i * 64;
    float a0 = 0.f, a1 = 0.f, a2 = 0.f;
    for (int k = lane; k < 64; k += 32) {
        float hv = hr[k];
        a0 = fmaf(hv, w[k * 3 + 0], a0);
        a1 = fmaf(hv, w[k * 3 + 1], a1);
        a2 = fmaf(hv, w[k * 3 + 2], a2);
    }
#pragma unroll
    for (int off = 16; off; off >>= 1) {
        a0 += __shfl_down_sync(0xffffffffu, a0, off);
        a1 += __shfl_down_sync(0xffffffffu, a1, off);
        a2 += __shfl_down_sync(0xffffffffu, a2, off);
    }
    if (lane == 0) {
        out[(size_t)i * 3 + 0] = a0 + bp[0];
        out[(size_t)i * 3 + 1] = a1 + bp[1];
        out[(size_t)i * 3 + 2] = a2 + bp[2];
    }
}

// ---------------- launch ----------------
extern "C" void kernel_launch(void* const* d_in, const int* in_sizes, int n_in,
                              void* d_out, int out_size) {
    const float* x           = (const float*)d_in[0];
    const int*   edge_index  = (const int*)  d_in[1];
    const float* edge_attr   = (const float*)d_in[2];
    const float* layer_table = (const float*)d_in[3];
    const float* rel_table   = (const float*)d_in[4];
    const float* color_table = (const float*)d_in[5];
    const float* W1 = (const float*)d_in[6];
    const float* b1 = (const float*)d_in[7];
    const float* W2 = (const float*)d_in[8];
    const float* b2 = (const float*)d_in[9];
    const float* W3 = (const float*)d_in[10];
    const float* b3 = (const float*)d_in[11];
    const float* Wp = (const float*)d_in[12];
    const float* bp = (const float*)d_in[13];
    float* out = (float*)d_out;

    float *p_h0, *p_t, *p_agg, *p_h1, *p_h2, *p_W1p, *p_dinv;
    cudaGetSymbolAddress((void**)&p_h0,   g_h0);
    cudaGetSymbolAddress((void**)&p_t,    g_t);
    cudaGetSymbolAddress((void**)&p_agg,  g_agg);
    cudaGetSymbolAddress((void**)&p_h1,   g_h1);
    cudaGetSymbolAddress((void**)&p_h2,   g_h2);
    cudaGetSymbolAddress((void**)&p_W1p,  g_W1p);
    cudaGetSymbolAddress((void**)&p_dinv, g_dinv);

    const int T = 256;

    // degree -> dinv
    zero_kernel<<<(N_NODES / 4 + T - 1) / T, T>>>((float4*)p_dinv, N_NODES / 4);
    deg_kernel<<<(N_EDGES + T - 1) / T, T>>>(edge_index, edge_attr);
    dinv_kernel<<<(N_NODES + T - 1) / T, T>>>();

    // embedding + padded W1
    embed_kernel<<<N_NODES, T>>>(x, layer_table, rel_table, color_table);
    padW1_kernel<<<(K1P * F1 + T - 1) / T, T>>>(W1);

    dim3 g1(F1 / 64, (N_NODES + 127) / 128);
    dim3 g2(F2 / 64, (N_NODES + 127) / 128);
    dim3 g3(F3 / 64, (N_NODES + 127) / 128);
    int warps_grid = (N_EDGES * 32 + T - 1) / T;

    // ---- layer 1 (K=1760 -> 512) ----
    zero_kernel<<<((N_NODES * F1 / 4) + T - 1) / T, T>>>((float4*)p_agg, N_NODES * F1 / 4);
    sgemm_kernel<<<g1, T>>>(p_h0, p_W1p, p_t, N_NODES, K1P, F1);
    agg_kernel<<<warps_grid, T>>>(edge_index, edge_attr, p_t, p_agg, F1);
    epi_kernel<<<((size_t)N_NODES * F1 + T - 1) / T, T>>>(p_t, p_agg, b1, p_h1, F1);

    // ---- layer 2 (512 -> 256) ----
    zero_kernel<<<((N_NODES * F2 / 4) + T - 1) / T, T>>>((float4*)p_agg, N_NODES * F2 / 4);
    sgemm_kernel<<<g2, T>>>(p_h1, W2, p_t, N_NODES, F1, F2);
    agg_kernel<<<warps_grid, T>>>(edge_index, edge_attr, p_t, p_agg, F2);
    epi_kernel<<<((size_t)N_NODES * F2 + T - 1) / T, T>>>(p_t, p_agg, b2, p_h2, F2);

    // ---- layer 3 (256 -> 64) ----
    zero_kernel<<<((N_NODES * F3 / 4) + T - 1) / T, T>>>((float4*)p_agg, N_NODES * F3 / 4);
    sgemm_kernel<<<g3, T>>>(p_h2, W3, p_t, N_NODES, F2, F3);
    agg_kernel<<<warps_grid, T>>>(edge_index, edge_attr, p_t, p_agg, F3);
    epi_kernel<<<((size_t)N_NODES * F3 + T - 1) / T, T>>>(p_t, p_agg, b3, p_h1, F3);

    // ---- projection (64 -> 3) ----
    proj_kernel<<<(N_NODES * 32 + T - 1) / T, T>>>(p_h1, Wp, bp, out);
}

// round 2
// speedup vs baseline: 1.1432x; 1.1432x over previous
#include <cuda_runtime.h>
#include <math.h>

#define N_NODES 20000
#define N_EDGES 320000
#define FS      1000
#define XCOLS   1005
#define K1M     1008      // padded resnet K (multiple of 16)
#define F1      512
#define F2      256
#define F3      64

// ---------------- static scratch ----------------
__device__ float g_A   [(size_t)N_NODES * K1M];   // padded resnet slice of x
__device__ float g_W1m [(size_t)K1M * F1];        // padded W1 rows 250..1249
__device__ float g_base[(size_t)N_NODES * F1];    // table contributions to layer1
__device__ float g_t   [(size_t)N_NODES * F1];    // GEMM output
__device__ float g_agg [(size_t)N_NODES * F1];    // aggregation buffer
__device__ float g_h1  [(size_t)N_NODES * F1];    // layer1 / layer3 activations
__device__ float g_h2  [(size_t)N_NODES * F2];    // layer2 activations
__device__ float g_dinv[N_NODES];
__device__ float g_norm[N_EDGES];
__device__ float g_preL[3 * F1];
__device__ float g_preR[11 * F1];
__device__ float g_preC[3 * 256 * F1];

// ---------------- utility kernels ----------------
__global__ void zero_kernel(float4* p, int n4) {
    int i = blockIdx.x * blockDim.x + threadIdx.x;
    if (i < n4) p[i] = make_float4(0.f, 0.f, 0.f, 0.f);
}

__global__ void deg_kernel(const int* __restrict__ ei, const float* __restrict__ ea) {
    int e = blockIdx.x * blockDim.x + threadIdx.x;
    if (e < N_EDGES) atomicAdd(&g_dinv[ei[N_EDGES + e]], ea[e]);
}

__global__ void dinv_kernel() {
    int i = blockIdx.x * blockDim.x + threadIdx.x;
    if (i < N_NODES) g_dinv[i] = rsqrtf(g_dinv[i] + 1.0f);
}

__global__ void norm_kernel(const int* __restrict__ ei, const float* __restrict__ ea) {
    int e = blockIdx.x * blockDim.x + threadIdx.x;
    if (e < N_EDGES)
        g_norm[e] = g_dinv[ei[e]] * ea[e] * g_dinv[ei[N_EDGES + e]];
}

// copy resnet cols (x[:,1..1000]) into aligned padded buffer
__global__ void copy_resnet(const float* __restrict__ x) {
    int i = blockIdx.x;
    const float* xr = x + (size_t)i * XCOLS + 1;
    float* ar = g_A + (size_t)i * K1M;
    for (int j = threadIdx.x; j < K1M; j += blockDim.x)
        ar[j] = (j < FS) ? xr[j] : 0.f;
}

// W1 middle rows 250..1249 -> padded 1008 x 512
__global__ void padW1mid(const float* __restrict__ W1) {
    int idx = blockIdx.x * blockDim.x + threadIdx.x;
    if (idx < K1M * F1) {
        int r = idx / F1, c = idx % F1;
        g_W1m[idx] = (r < FS) ? W1[(size_t)(250 + r) * F1 + c] : 0.f;
    }
}

// out[r, :] = tab[r, :Kt] @ W1[off:off+Kt, :]   (512 threads, one block per row)
__global__ void pre_table(const float* __restrict__ tab, const float* __restrict__ W1,
                          float* __restrict__ out, int Kt, int off) {
    __shared__ float s[256];
    int r = blockIdx.x, j = threadIdx.x;
    if (j < Kt) s[j] = tab[(size_t)r * Kt + j];
    __syncthreads();
    float acc = 0.f;
    for (int k = 0; k < Kt; k++)
        acc = fmaf(s[k], W1[(size_t)(off + k) * F1 + j], acc);
    out[(size_t)r * F1 + j] = acc;
}

// preC[p,c,:] = color_table[c, :85] @ W1[1500+85p : 1585+85p, :]
__global__ void pre_color(const float* __restrict__ ct, const float* __restrict__ W1) {
    __shared__ float s[96];
    int p = blockIdx.x >> 8, c = blockIdx.x & 255, j = threadIdx.x;
    if (j < 85) s[j] = ct[(size_t)c * 85 + j];
    __syncthreads();
    int off = 1500 + 85 * p;
    float acc = 0.f;
    for (int k = 0; k < 85; k++)
        acc = fmaf(s[k], W1[(size_t)(off + k) * F1 + j], acc);
    g_preC[((size_t)blockIdx.x) * F1 + j] = acc;
}

// per-node table contribution: base[i] = preL[li] + preR[ri] + sum_p preC[p][cp]
__global__ void node_base(const float* __restrict__ x) {
    int i = blockIdx.x;
    const float* xr = x + (size_t)i * XCOLS;
    int li = (int)xr[0] - 1;
    int ri = __float2int_rn(fabsf(xr[FS + 1]) * 10.0f);
    int c0 = (int)xr[XCOLS - 3];
    int c1 = (int)xr[XCOLS - 2];
    int c2 = (int)xr[XCOLS - 1];
    const float4* pL = (const float4*)(g_preL + (size_t)li * F1);
    const float4* pR = (const float4*)(g_preR + (size_t)ri * F1);
    const float4* p0 = (const float4*)(g_preC + ((size_t)(0 * 256 + c0)) * F1);
    const float4* p1 = (const float4*)(g_preC + ((size_t)(1 * 256 + c1)) * F1);
    const float4* p2 = (const float4*)(g_preC + ((size_t)(2 * 256 + c2)) * F1);
    float4* bo = (float4*)(g_base + (size_t)i * F1);
    int j = threadIdx.x;   // 128 threads, one float4 each
    float4 a = pL[j], b = pR[j], u = p0[j], v = p1[j], w = p2[j];
    bo[j] = make_float4(a.x + b.x + u.x + v.x + w.x,
                        a.y + b.y + u.y + v.y + w.y,
                        a.z + b.z + u.z + v.z + w.z,
                        a.w + b.w + u.w + v.w + w.w);
}

// ---------------- SGEMM: C = A[M,K] @ B[K,Nn] (+ base), BM=128, BK=16 ----------------
template<int BN, int TN, bool ADD_BASE>
__global__ __launch_bounds__(256) void gemm_kernel(const float* __restrict__ A,
                                                   const float* __restrict__ B,
                                                   const float* __restrict__ base,
                                                   float* __restrict__ C,
                                                   int M, int K, int Nn) {
    constexpr int BM = 128, BK = 16, THREADS = 256;
    constexpr int TM = 8;
    constexpr int TX = BN / TN;           // 16
    constexpr int TY = THREADS / TX;      // 16
    constexpr int NA = BM * BK / 4 / THREADS;   // 2
    constexpr int NB = BK * BN / 4 / THREADS;   // 2 (BN=128) or 1 (BN=64)
    constexpr int BF4 = BN / 4;

    __shared__ float As[BK][BM];
    __shared__ float Bs[BK][BN];

    int tid = threadIdx.x;
    int bm = blockIdx.y * BM;
    int bn = blockIdx.x * BN;
    int ty = tid / TX, tx = tid % TX;

    float acc[TM][TN];
#pragma unroll
    for (int i = 0; i < TM; i++)
#pragma unroll
        for (int j = 0; j < TN; j++) acc[i][j] = 0.f;

    for (int k0 = 0; k0 < K; k0 += BK) {
#pragma unroll
        for (int l = 0; l < NA; l++) {
            int idx = tid + l * THREADS;
            int row = idx >> 2, col4 = (idx & 3) * 4;
            int gr = bm + row;
            float4 v = make_float4(0.f, 0.f, 0.f, 0.f);
            if (gr < M) v = *(const float4*)(A + (size_t)gr * K + k0 + col4);
            As[col4 + 0][row] = v.x;
            As[col4 + 1][row] = v.y;
            As[col4 + 2][row] = v.z;
            As[col4 + 3][row] = v.w;
        }
#pragma unroll
        for (int l = 0; l < NB; l++) {
            int idx = tid + l * THREADS;
            int row = idx / BF4, col4 = (idx % BF4) * 4;
            *(float4*)&Bs[row][col4] = *(const float4*)(B + (size_t)(k0 + row) * Nn + bn + col4);
        }
        __syncthreads();
#pragma unroll
        for (int kk = 0; kk < BK; kk++) {
            float ar[TM], br[TN];
#pragma unroll
            for (int q = 0; q < TM / 4; q++) {
                float4 v = *(const float4*)&As[kk][ty * TM + q * 4];
                ar[q * 4 + 0] = v.x; ar[q * 4 + 1] = v.y; ar[q * 4 + 2] = v.z; ar[q * 4 + 3] = v.w;
            }
#pragma unroll
            for (int q = 0; q < TN / 4; q++) {
                float4 v = *(const float4*)&Bs[kk][tx * TN + q * 4];
                br[q * 4 + 0] = v.x; br[q * 4 + 1] = v.y; br[q * 4 + 2] = v.z; br[q * 4 + 3] = v.w;
            }
#pragma unroll
            for (int i = 0; i < TM; i++)
#pragma unroll
                for (int j = 0; j < TN; j++) acc[i][j] = fmaf(ar[i], br[j], acc[i][j]);
        }
        __syncthreads();
    }
#pragma unroll
    for (int i = 0; i < TM; i++) {
        int gr = bm + ty * TM + i;
        if (gr < M) {
#pragma unroll
            for (int q = 0; q < TN / 4; q++) {
                float4 v = make_float4(acc[i][q * 4 + 0], acc[i][q * 4 + 1],
                                       acc[i][q * 4 + 2], acc[i][q * 4 + 3]);
                if (ADD_BASE) {
                    float4 bv = *(const float4*)(base + (size_t)gr * Nn + bn + tx * TN + q * 4);
                    v.x += bv.x; v.y += bv.y; v.z += bv.z; v.w += bv.w;
                }
                *(float4*)(C + (size_t)gr * Nn + bn + tx * TN + q * 4) = v;
            }
        }
    }
}

// ---------------- agg init: agg = t * dinv^2 + bias ----------------
__global__ void init_agg(const float* __restrict__ t, const float* __restrict__ b,
                         float* __restrict__ agg, int lgF4, int n4) {
    int idx = blockIdx.x * blockDim.x + threadIdx.x;
    if (idx >= n4) return;
    int i = idx >> lgF4;
    int jj = idx & ((1 << lgF4) - 1);
    float d = g_dinv[i];
    float dd = d * d;
    float4 tv = ((const float4*)t)[idx];
    float4 bv = ((const float4*)b)[jj];
    ((float4*)agg)[idx] = make_float4(fmaf(tv.x, dd, bv.x), fmaf(tv.y, dd, bv.y),
                                      fmaf(tv.z, dd, bv.z), fmaf(tv.w, dd, bv.w));
}

// ---------------- edge aggregation: vector atomics ----------------
__global__ void agg_kernel(const int* __restrict__ ei, const float* __restrict__ t,
                           float* __restrict__ agg, int lgF4) {
    int gtid = blockIdx.x * blockDim.x + threadIdx.x;
    int e = gtid >> lgF4;
    if (e >= N_EDGES) return;
    int ch = gtid & ((1 << lgF4) - 1);
    int src = ei[e];
    int dst = ei[N_EDGES + e];
    float nrm = g_norm[e];
    float4 v = ((const float4*)t)[((size_t)src << lgF4) + ch];
    float4* ad = (float4*)agg + (((size_t)dst << lgF4) + ch);
    asm volatile("red.global.add.v4.f32 [%0], {%1, %2, %3, %4};"
                 :: "l"(ad), "f"(v.x * nrm), "f"(v.y * nrm), "f"(v.z * nrm), "f"(v.w * nrm)
                 : "memory");
}

// ---------------- leaky relu ----------------
__global__ void epi_kernel(const float* __restrict__ agg, float* __restrict__ hout, int n4) {
    int idx = blockIdx.x * blockDim.x + threadIdx.x;
    if (idx >= n4) return;
    float4 v = ((const float4*)agg)[idx];
    v.x = v.x > 0.f ? v.x : 0.01f * v.x;
    v.y = v.y > 0.f ? v.y : 0.01f * v.y;
    v.z = v.z > 0.f ? v.z : 0.01f * v.z;
    v.w = v.w > 0.f ? v.w : 0.01f * v.w;
    ((float4*)hout)[idx] = v;
}

// ---------------- final projection: out = h3 @ Wp + bp ----------------
__global__ void proj_kernel(const float* __restrict__ h, const float* __restrict__ Wp,
                            const float* __restrict__ bp, float* __restrict__ out) {
    __shared__ float w[64 * 3];
    if (threadIdx.x < 192) w[threadIdx.x] = Wp[threadIdx.x];
    __syncthreads();
    int warp = threadIdx.x >> 5, lane = threadIdx.x & 31;
    int i = blockIdx.x * (blockDim.x >> 5) + warp;
    if (i >= N_NODES) return;
    const float* hr = h + (size_t)i * 64;
    float a0 = 0.f, a1 = 0.f, a2 = 0.f;
    for (int k = lane; k < 64; k += 32) {
        float hv = hr[k];
        a0 = fmaf(hv, w[k * 3 + 0], a0);
        a1 = fmaf(hv, w[k * 3 + 1], a1);
        a2 = fmaf(hv, w[k * 3 + 2], a2);
    }
#pragma unroll
    for (int off = 16; off; off >>= 1) {
        a0 += __shfl_down_sync(0xffffffffu, a0, off);
        a1 += __shfl_down_sync(0xffffffffu, a1, off);
        a2 += __shfl_down_sync(0xffffffffu, a2, off);
    }
    if (lane == 0) {
        out[(size_t)i * 3 + 0] = a0 + bp[0];
        out[(size_t)i * 3 + 1] = a1 + bp[1];
        out[(size_t)i * 3 + 2] = a2 + bp[2];
    }
}

// ---------------- launch ----------------
extern "C" void kernel_launch(void* const* d_in, const int* in_sizes, int n_in,
                              void* d_out, int out_size) {
    const float* x           = (const float*)d_in[0];
    const int*   edge_index  = (const int*)  d_in[1];
    const float* edge_attr   = (const float*)d_in[2];
    const float* layer_table = (const float*)d_in[3];
    const float* rel_table   = (const float*)d_in[4];
    const float* color_table = (const float*)d_in[5];
    const float* W1 = (const float*)d_in[6];
    const float* b1 = (const float*)d_in[7];
    const float* W2 = (const float*)d_in[8];
    const float* b2 = (const float*)d_in[9];
    const float* W3 = (const float*)d_in[10];
    const float* b3 = (const float*)d_in[11];
    const float* Wp = (const float*)d_in[12];
    const float* bp = (const float*)d_in[13];
    float* out = (float*)d_out;

    float *p_A, *p_W1m, *p_base, *p_t, *p_agg, *p_h1, *p_h2, *p_dinv, *p_preL, *p_preR;
    cudaGetSymbolAddress((void**)&p_A,    g_A);
    cudaGetSymbolAddress((void**)&p_W1m,  g_W1m);
    cudaGetSymbolAddress((void**)&p_base, g_base);
    cudaGetSymbolAddress((void**)&p_t,    g_t);
    cudaGetSymbolAddress((void**)&p_agg,  g_agg);
    cudaGetSymbolAddress((void**)&p_h1,   g_h1);
    cudaGetSymbolAddress((void**)&p_h2,   g_h2);
    cudaGetSymbolAddress((void**)&p_dinv, g_dinv);
    cudaGetSymbolAddress((void**)&p_preL, g_preL);
    cudaGetSymbolAddress((void**)&p_preR, g_preR);

    const int T = 256;

    // degree -> dinv -> per-edge norm (reused across all 3 layers)
    zero_kernel<<<(N_NODES / 4 + T - 1) / T, T>>>((float4*)p_dinv, N_NODES / 4);
    deg_kernel<<<(N_EDGES + T - 1) / T, T>>>(edge_index, edge_attr);
    dinv_kernel<<<(N_NODES + T - 1) / T, T>>>();
    norm_kernel<<<(N_EDGES + T - 1) / T, T>>>(edge_index, edge_attr);

    // inputs for decomposed GEMM1
    copy_resnet<<<N_NODES, T>>>(x);
    padW1mid<<<(K1M * F1 + T - 1) / T, T>>>(W1);
    pre_table<<<3, 512>>>(layer_table, W1, p_preL, 250, 0);
    pre_table<<<11, 512>>>(rel_table, W1, p_preR, 250, 1250);
    pre_color<<<768, 512>>>(color_table, W1);
    node_base<<<N_NODES, 128>>>(x);

    dim3 g1(F1 / 128, (N_NODES + 127) / 128);
    dim3 g2(F2 / 128, (N_NODES + 127) / 128);
    dim3 g3(F3 / 64,  (N_NODES + 127) / 128);

    // ---- layer 1: t = resnet @ W1mid + base ----
    gemm_kernel<128, 8, true><<<g1, T>>>(p_A, p_W1m, p_base, p_t, N_NODES, K1M, F1);
    {
        int n4 = N_NODES * F1 / 4, lg = 7;   // F1/4 = 128
        init_agg<<<(n4 + T - 1) / T, T>>>(p_t, b1, p_agg, lg, n4);
        long long th = (long long)N_EDGES << lg;
        agg_kernel<<<(int)((th + T - 1) / T), T>>>(edge_index, p_t, p_agg, lg);
        epi_kernel<<<(n4 + T - 1) / T, T>>>(p_agg, p_h1, n4);
    }

    // ---- layer 2 ----
    gemm_kernel<128, 8, false><<<g2, T>>>(p_h1, W2, nullptr, p_t, N_NODES, F1, F2);
    {
        int n4 = N_NODES * F2 / 4, lg = 6;   // F2/4 = 64
        init_agg<<<(n4 + T - 1) / T, T>>>(p_t, b2, p_agg, lg, n4);
        long long th = (long long)N_EDGES << lg;
        agg_kernel<<<(int)((th + T - 1) / T), T>>>(edge_index, p_t, p_agg, lg);
        epi_kernel<<<(n4 + T - 1) / T, T>>>(p_agg, p_h2, n4);
    }

    // ---- layer 3 ----
    gemm_kernel<64, 4, false><<<g3, T>>>(p_h2, W3, nullptr, p_t, N_NODES, F2, F3);
    {
        int n4 = N_NODES * F3 / 4, lg = 4;   // F3/4 = 16
        init_agg<<<(n4 + T - 1) / T, T>>>(p_t, b3, p_agg, lg, n4);
        long long th = (long long)N_EDGES << lg;
        agg_kernel<<<(int)((th + T - 1) / T), T>>>(edge_index, p_t, p_agg, lg);
        epi_kernel<<<(n4 + T - 1) / T, T>>>(p_agg, p_h1, n4);
    }

    // ---- projection ----
    proj_kernel<<<(N_NODES * 32 + T - 1) / T, T>>>(p_h1, Wp, bp, out);
}

// round 5
// speedup vs baseline: 2.2324x; 1.9528x over previous
#include <cuda_runtime.h>
#include <cuda_bf16.h>
#include <math.h>
#include <stdint.h>

#define N_NODES 20000
#define N_EDGES 320000
#define FS      1000
#define XCOLS   1005
#define F1      512
#define F2      256
#define F3      64
#define KP1     1024             // padded resnet K
#define K1E     (3 * KP1)        // 3072
#define K2E     (3 * F1)         // 1536
#define K3E     (3 * F2)         // 768

// ======================= static scratch =======================
__device__ __nv_bfloat16 g_A2 [(size_t)N_NODES * K1E];  // [Ahi|Ahi|Alo] resnet
__device__ __nv_bfloat16 g_WT [(size_t)F1 * K1E];       // [Bhi|Blo|Bhi] transposed weight (reused)
__device__ __nv_bfloat16 g_h2s[(size_t)N_NODES * K2E];  // [hi|hi|lo] activations (reused)
__device__ float g_base[(size_t)N_NODES * F1];
__device__ float g_t   [(size_t)N_NODES * F1];
__device__ float g_agg [(size_t)N_NODES * F1];
__device__ float g_h3  [(size_t)N_NODES * F3];
__device__ float g_dinv[N_NODES];
__device__ float g_norm[N_EDGES];
__device__ float g_preL[3 * F1];
__device__ float g_preR[11 * F1];
__device__ float g_preC[3 * 256 * F1];

// ======================= PTX helpers (portable, sm_80+) =======================
__device__ __forceinline__ uint32_t smem_u32(const void* p) {
    uint32_t a;
    asm("{ .reg .u64 t; cvta.to.shared.u64 t, %1; cvt.u32.u64 %0, t; }" : "=r"(a) : "l"(p));
    return a;
}
__device__ __forceinline__ void cp16(uint32_t dst, const void* src, bool pred) {
    int sz = pred ? 16 : 0;
    asm volatile("cp.async.cg.shared.global [%0], [%1], 16, %2;"
                 :: "r"(dst), "l"(src), "r"(sz) : "memory");
}
#define CP_COMMIT() asm volatile("cp.async.commit_group;" ::: "memory")
#define CP_WAIT1()  asm volatile("cp.async.wait_group 1;" ::: "memory")

__device__ __forceinline__ void ldsm_x4(uint32_t* r, uint32_t addr) {
    asm volatile("ldmatrix.sync.aligned.m8n8.x4.shared.b16 {%0,%1,%2,%3}, [%4];"
                 : "=r"(r[0]), "=r"(r[1]), "=r"(r[2]), "=r"(r[3]) : "r"(addr));
}
__device__ __forceinline__ void mma_bf16(float* d, const uint32_t* a, const uint32_t* b) {
    asm volatile("mma.sync.aligned.m16n8k16.row.col.f32.bf16.bf16.f32 "
                 "{%0,%1,%2,%3}, {%4,%5,%6,%7}, {%8,%9}, {%0,%1,%2,%3};"
                 : "+f"(d[0]), "+f"(d[1]), "+f"(d[2]), "+f"(d[3])
                 : "r"(a[0]), "r"(a[1]), "r"(a[2]), "r"(a[3]), "r"(b[0]), "r"(b[1]));
}
__device__ __forceinline__ uint32_t swz(uint32_t off) { return off ^ ((off >> 3) & 0x70); }

// ======================= small kernels =======================
__global__ void zero_kernel(float4* p, int n4) {
    int i = blockIdx.x * blockDim.x + threadIdx.x;
    if (i < n4) p[i] = make_float4(0.f, 0.f, 0.f, 0.f);
}
__global__ void deg_kernel(const int* __restrict__ ei, const float* __restrict__ ea) {
    int e = blockIdx.x * blockDim.x + threadIdx.x;
    if (e < N_EDGES) atomicAdd(&g_dinv[ei[N_EDGES + e]], ea[e]);
}
__global__ void dinv_kernel() {
    int i = blockIdx.x * blockDim.x + threadIdx.x;
    if (i < N_NODES) g_dinv[i] = rsqrtf(g_dinv[i] + 1.0f);
}
__global__ void norm_kernel(const int* __restrict__ ei, const float* __restrict__ ea) {
    int e = blockIdx.x * blockDim.x + threadIdx.x;
    if (e < N_EDGES) g_norm[e] = g_dinv[ei[e]] * ea[e] * g_dinv[ei[N_EDGES + e]];
}

// resnet slice -> [hi|hi|lo] bf16 blocks, padded to KP1
__global__ void split_x_kernel(const float* __restrict__ x) {
    int i = blockIdx.x;
    const float* xr = x + (size_t)i * XCOLS + 1;
    __nv_bfloat16* a = g_A2 + (size_t)i * K1E;
    for (int k = threadIdx.x; k < KP1; k += blockDim.x) {
        float v = (k < FS) ? xr[k] : 0.f;
        __nv_bfloat16 h = __float2bfloat16(v);
        __nv_bfloat16 l = __float2bfloat16(v - __bfloat162float(h));
        a[k]           = h;
        a[KP1 + k]     = h;
        a[2 * KP1 + k] = l;
    }
}

// W[K,Nn] rows [roff, roff+Ksrc) -> g_WT[Nn][3*Kp] = [hi|lo|hi] transposed
__global__ void splitT_kernel(const float* __restrict__ W, int Nn, int Kp, int Ksrc, int roff) {
    int idx = blockIdx.x * blockDim.x + threadIdx.x;
    if (idx >= Nn * Kp) return;
    int n = idx / Kp, k = idx % Kp;
    float v = (k < Ksrc) ? W[(size_t)(roff + k) * Nn + n] : 0.f;
    __nv_bfloat16 h = __float2bfloat16(v);
    __nv_bfloat16 l = __float2bfloat16(v - __bfloat162float(h));
    __nv_bfloat16* b = g_WT + (size_t)n * 3 * Kp;
    b[k]          = h;
    b[Kp + k]     = l;
    b[2 * Kp + k] = h;
}

// out[r,:] = tab[r,:Kt] @ W1[off:off+Kt,:]
__global__ void pre_table(const float* __restrict__ tab, const float* __restrict__ W1,
                          float* __restrict__ out, int Kt, int off) {
    __shared__ float s[256];
    int r = blockIdx.x, j = threadIdx.x;
    if (j < Kt) s[j] = tab[(size_t)r * Kt + j];
    __syncthreads();
    float acc = 0.f;
    for (int k = 0; k < Kt; k++) acc = fmaf(s[k], W1[(size_t)(off + k) * F1 + j], acc);
    out[(size_t)r * F1 + j] = acc;
}
__global__ void pre_color(const float* __restrict__ ct, const float* __restrict__ W1) {
    __shared__ float s[96];
    int p = blockIdx.x >> 8, c = blockIdx.x & 255, j = threadIdx.x;
    if (j < 85) s[j] = ct[(size_t)c * 85 + j];
    __syncthreads();
    int off = 1500 + 85 * p;
    float acc = 0.f;
    for (int k = 0; k < 85; k++) acc = fmaf(s[k], W1[(size_t)(off + k) * F1 + j], acc);
    g_preC[((size_t)blockIdx.x) * F1 + j] = acc;
}
__global__ void node_base(const float* __restrict__ x) {
    int i = blockIdx.x;
    const float* xr = x + (size_t)i * XCOLS;
    int li = (int)xr[0] - 1;
    int ri = __float2int_rn(fabsf(xr[FS + 1]) * 10.0f);
    int c0 = (int)xr[XCOLS - 3];
    int c1 = (int)xr[XCOLS - 2];
    int c2 = (int)xr[XCOLS - 1];
    const float4* pL = (const float4*)(g_preL + (size_t)li * F1);
    const float4* pR = (const float4*)(g_preR + (size_t)ri * F1);
    const float4* p0 = (const float4*)(g_preC + ((size_t)(0 * 256 + c0)) * F1);
    const float4* p1 = (const float4*)(g_preC + ((size_t)(1 * 256 + c1)) * F1);
    const float4* p2 = (const float4*)(g_preC + ((size_t)(2 * 256 + c2)) * F1);
    float4* bo = (float4*)(g_base + (size_t)i * F1);
    int j = threadIdx.x;
    float4 a = pL[j], b = pR[j], u = p0[j], v = p1[j], w = p2[j];
    bo[j] = make_float4(a.x + b.x + u.x + v.x + w.x, a.y + b.y + u.y + v.y + w.y,
                        a.z + b.z + u.z + v.z + w.z, a.w + b.w + u.w + v.w + w.w);
}

// ======================= mma.sync bf16 GEMM =======================
// C[M,Nn] = A[M,Keff] @ B[Nn,Keff]^T (+ base). CTA 128 x BN, BK=64, 256 thr, 8 warps.
template<int BN>
__device__ __forceinline__ void load_stage(const __nv_bfloat16* __restrict__ A,
                                           const __nv_bfloat16* __restrict__ B,
                                           int bm, int bn, int Keff, int k0, int M,
                                           uint32_t sA, uint32_t sB) {
    int t = threadIdx.x;
#pragma unroll
    for (int i = 0; i < 4; i++) {
        int idx = t + i * 256;
        int row = idx >> 3, seg = idx & 7;
        int gr = bm + row;
        bool p = gr < M;
        const void* src = A + (size_t)(p ? gr : 0) * Keff + k0 + seg * 8;
        cp16(sA + swz(row * 128 + seg * 16), src, p);
    }
#pragma unroll
    for (int i = 0; i < BN * 8 / 256; i++) {
        int idx = t + i * 256;
        int row = idx >> 3, seg = idx & 7;
        const void* src = B + (size_t)(bn + row) * Keff + k0 + seg * 8;
        cp16(sB + swz(row * 128 + seg * 16), src, true);
    }
}

template<int BN, bool ADD_BASE>
__global__ __launch_bounds__(256) void mma_gemm(const __nv_bfloat16* __restrict__ A,
                                                const __nv_bfloat16* __restrict__ B,
                                                const float* __restrict__ base,
                                                float* __restrict__ C,
                                                int M, int Keff, int Nn) {
    extern __shared__ char smem[];
    constexpr int WN = BN / 2;               // warp N extent
    constexpr int SS = (128 + BN) * 128;     // bytes per stage
    uint32_t sb = smem_u32(smem);
    int tid = threadIdx.x, wid = tid >> 5, lane = tid & 31;
    int bm = blockIdx.y * 128, bn = blockIdx.x * BN;
    int wm = (wid & 3) * 32;
    int wn = (wid >> 2) * WN;

    float acc[2][WN / 8][4];
#pragma unroll
    for (int i = 0; i < 2; i++)
#pragma unroll
        for (int j = 0; j < WN / 8; j++)
#pragma unroll
            for (int q = 0; q < 4; q++) acc[i][j][q] = 0.f;

    int nT = Keff >> 6;
    load_stage<BN>(A, B, bm, bn, Keff, 0, M, sb, sb + 128 * 128);
    CP_COMMIT();

    for (int t = 0; t < nT; t++) {
        if (t + 1 < nT) {
            uint32_t s1 = sb + ((t + 1) & 1) * SS;
            load_stage<BN>(A, B, bm, bn, Keff, (t + 1) * 64, M, s1, s1 + 128 * 128);
        }
        CP_COMMIT();
        CP_WAIT1();
        __syncthreads();

        uint32_t sA = sb + (t & 1) * SS;
        uint32_t sB = sA + 128 * 128;
#pragma unroll
        for (int ks = 0; ks < 4; ks++) {
            uint32_t af[2][4];
#pragma unroll
            for (int mi = 0; mi < 2; mi++) {
                int row = wm + mi * 16 + (lane & 15);
                ldsm_x4(af[mi], sA + swz(row * 128 + ks * 32 + ((lane >> 4) << 4)));
            }
#pragma unroll
            for (int nj = 0; nj < WN / 16; nj++) {
                uint32_t bf[4];
                int row = wn + nj * 16 + (lane & 7) + ((lane >> 4) << 3);
                ldsm_x4(bf, sB + swz(row * 128 + ks * 32 + (((lane >> 3) & 1) << 4)));
                mma_bf16(acc[0][2 * nj],     af[0], bf);
                mma_bf16(acc[0][2 * nj + 1], af[0], bf + 2);
                mma_bf16(acc[1][2 * nj],     af[1], bf);
                mma_bf16(acc[1][2 * nj + 1], af[1], bf + 2);
            }
        }
        __syncthreads();
    }

    // epilogue
#pragma unroll
    for (int mi = 0; mi < 2; mi++) {
#pragma unroll
        for (int nj = 0; nj < WN / 8; nj++) {
            int row = bm + wm + mi * 16 + (lane >> 2);
            int col = bn + wn + nj * 8 + (lane & 3) * 2;
#pragma unroll
            for (int h = 0; h < 2; h++) {
                int r = row + h * 8;
                if (r < M) {
                    float2 v = make_float2(acc[mi][nj][h * 2], acc[mi][nj][h * 2 + 1]);
                    if (ADD_BASE) {
                        float2 b2 = *(const float2*)(base + (size_t)r * Nn + col);
                        v.x += b2.x; v.y += b2.y;
                    }
                    *(float2*)(C + (size_t)r * Nn + col) = v;
                }
            }
        }
    }
}

// ======================= agg pipeline =======================
__global__ void init_agg(const float* __restrict__ t, const float* __restrict__ b,
                         float* __restrict__ agg, int lgF4, int n4) {
    int idx = blockIdx.x * blockDim.x + threadIdx.x;
    if (idx >= n4) return;
    int i = idx >> lgF4;
    int jj = idx & ((1 << lgF4) - 1);
    float d = g_dinv[i];
    float dd = d * d;
    float4 tv = ((const float4*)t)[idx];
    float4 bv = ((const float4*)b)[jj];
    ((float4*)agg)[idx] = make_float4(fmaf(tv.x, dd, bv.x), fmaf(tv.y, dd, bv.y),
                                      fmaf(tv.z, dd, bv.z), fmaf(tv.w, dd, bv.w));
}
__global__ void agg_kernel(const int* __restrict__ ei, const float* __restrict__ t,
                           float* __restrict__ agg, int lgF4) {
    int gtid = blockIdx.x * blockDim.x + threadIdx.x;
    int e = gtid >> lgF4;
    if (e >= N_EDGES) return;
    int ch = gtid & ((1 << lgF4) - 1);
    int src = ei[e];
    int dst = ei[N_EDGES + e];
    float nrm = g_norm[e];
    float4 v = ((const float4*)t)[((size_t)src << lgF4) + ch];
    float4* ad = (float4*)agg + (((size_t)dst << lgF4) + ch);
    asm volatile("red.global.add.v4.f32 [%0], {%1, %2, %3, %4};"
                 :: "l"(ad), "f"(v.x * nrm), "f"(v.y * nrm), "f"(v.z * nrm), "f"(v.w * nrm) : "memory");
}

// leaky-relu -> [hi|hi|lo] bf16 blocks (feeds next GEMM as A operand)
__global__ void epi_split_kernel(const float* __restrict__ agg, __nv_bfloat16* __restrict__ hs,
                                 int lgF4, int n4) {
    int idx = blockIdx.x * blockDim.x + threadIdx.x;
    if (idx >= n4) return;
    int i = idx >> lgF4;
    int j4 = idx & ((1 << lgF4) - 1);
    int F = 4 << lgF4;
    float4 v = ((const float4*)agg)[idx];
    float f[4] = {v.x, v.y, v.z, v.w};
    __nv_bfloat16 h[4], l[4];
#pragma unroll
    for (int q = 0; q < 4; q++) {
        float u = f[q] > 0.f ? f[q] : 0.01f * f[q];
        h[q] = __float2bfloat16(u);
        l[q] = __float2bfloat16(u - __bfloat162float(h[q]));
    }
    __nv_bfloat16* row = hs + (size_t)i * 3 * F;
    *(uint2*)(row + j4 * 4)         = *(uint2*)h;
    *(uint2*)(row + F + j4 * 4)     = *(uint2*)h;
    *(uint2*)(row + 2 * F + j4 * 4) = *(uint2*)l;
}
__global__ void epi_f32_kernel(const float* __restrict__ agg, float* __restrict__ hout, int n4) {
    int idx = blockIdx.x * blockDim.x + threadIdx.x;
    if (idx >= n4) return;
    float4 v = ((const float4*)agg)[idx];
    v.x = v.x > 0.f ? v.x : 0.01f * v.x;
    v.y = v.y > 0.f ? v.y : 0.01f * v.y;
    v.z = v.z > 0.f ? v.z : 0.01f * v.z;
    v.w = v.w > 0.f ? v.w : 0.01f * v.w;
    ((float4*)hout)[idx] = v;
}

__global__ void proj_kernel(const float* __restrict__ h, const float* __restrict__ Wp,
                            const float* __restrict__ bp, float* __restrict__ out) {
    __shared__ float w[64 * 3];
    if (threadIdx.x < 192) w[threadIdx.x] = Wp[threadIdx.x];
    __syncthreads();
    int warp = threadIdx.x >> 5, lane = threadIdx.x & 31;
    int i = blockIdx.x * (blockDim.x >> 5) + warp;
    if (i >= N_NODES) return;
    const float* hr = h + (size_t)i * 64;
    float a0 = 0.f, a1 = 0.f, a2 = 0.f;
    for (int k = lane; k < 64; k += 32) {
        float hv = hr[k];
        a0 = fmaf(hv, w[k * 3 + 0], a0);
        a1 = fmaf(hv, w[k * 3 + 1], a1);
        a2 = fmaf(hv, w[k * 3 + 2], a2);
    }
#pragma unroll
    for (int off = 16; off; off >>= 1) {
        a0 += __shfl_down_sync(0xffffffffu, a0, off);
        a1 += __shfl_down_sync(0xffffffffu, a1, off);
        a2 += __shfl_down_sync(0xffffffffu, a2, off);
    }
    if (lane == 0) {
        out[(size_t)i * 3 + 0] = a0 + bp[0];
        out[(size_t)i * 3 + 1] = a1 + bp[1];
        out[(size_t)i * 3 + 2] = a2 + bp[2];
    }
}

// ======================= launch =======================
extern "C" void kernel_launch(void* const* d_in, const int* in_sizes, int n_in,
                              void* d_out, int out_size) {
    const float* x           = (const float*)d_in[0];
    const int*   edge_index  = (const int*)  d_in[1];
    const float* edge_attr   = (const float*)d_in[2];
    const float* layer_table = (const float*)d_in[3];
    const float* rel_table   = (const float*)d_in[4];
    const float* color_table = (const float*)d_in[5];
    const float* W1 = (const float*)d_in[6];
    const float* b1 = (const float*)d_in[7];
    const float* W2 = (const float*)d_in[8];
    const float* b2 = (const float*)d_in[9];
    const float* W3 = (const float*)d_in[10];
    const float* b3 = (const float*)d_in[11];
    const float* Wp = (const float*)d_in[12];
    const float* bp = (const float*)d_in[13];
    float* out = (float*)d_out;

    __nv_bfloat16 *p_A2, *p_WT, *p_h2s;
    float *p_base, *p_t, *p_agg, *p_h3, *p_dinv, *p_preL, *p_preR;
    cudaGetSymbolAddress((void**)&p_A2,   g_A2);
    cudaGetSymbolAddress((void**)&p_WT,   g_WT);
    cudaGetSymbolAddress((void**)&p_h2s,  g_h2s);
    cudaGetSymbolAddress((void**)&p_base, g_base);
    cudaGetSymbolAddress((void**)&p_t,    g_t);
    cudaGetSymbolAddress((void**)&p_agg,  g_agg);
    cudaGetSymbolAddress((void**)&p_h3,   g_h3);
    cudaGetSymbolAddress((void**)&p_dinv, g_dinv);
    cudaGetSymbolAddress((void**)&p_preL, g_preL);
    cudaGetSymbolAddress((void**)&p_preR, g_preR);

    const int T = 256;
    const int SM128 = 2 * (128 + 128) * 128;   // 65536
    const int SM64  = 2 * (128 + 64) * 128;    // 49152
    cudaFuncSetAttribute(mma_gemm<128, true>,  cudaFuncAttributeMaxDynamicSharedMemorySize, SM128);
    cudaFuncSetAttribute(mma_gemm<128, false>, cudaFuncAttributeMaxDynamicSharedMemorySize, SM128);
    cudaFuncSetAttribute(mma_gemm<64,  false>, cudaFuncAttributeMaxDynamicSharedMemorySize, SM64);

    // degree -> dinv -> edge norms
    zero_kernel<<<(N_NODES / 4 + T - 1) / T, T>>>((float4*)p_dinv, N_NODES / 4);
    deg_kernel<<<(N_EDGES + T - 1) / T, T>>>(edge_index, edge_attr);
    dinv_kernel<<<(N_NODES + T - 1) / T, T>>>();
    norm_kernel<<<(N_EDGES + T - 1) / T, T>>>(edge_index, edge_attr);

    // GEMM1 inputs
    split_x_kernel<<<N_NODES, T>>>(x);
    splitT_kernel<<<(F1 * KP1 + T - 1) / T, T>>>(W1, F1, KP1, FS, 250);
    pre_table<<<3, 512>>>(layer_table, W1, p_preL, 250, 0);
    pre_table<<<11, 512>>>(rel_table, W1, p_preR, 250, 1250);
    pre_color<<<768, 512>>>(color_table, W1);
    node_base<<<N_NODES, 128>>>(x);

    const int MT = (N_NODES + 127) / 128;   // 157

    // ---- layer 1: t = resnet @ W1mid + base ----
    mma_gemm<128, true><<<dim3(F1 / 128, MT), T, SM128>>>(p_A2, p_WT, p_base, p_t, N_NODES, K1E, F1);
    {
        int n4 = N_NODES * F1 / 4, lg = 7;
        init_agg<<<(n4 + T - 1) / T, T>>>(p_t, b1, p_agg, lg, n4);
        long long th = (long long)N_EDGES << lg;
        agg_kernel<<<(int)((th + T - 1) / T), T>>>(edge_index, p_t, p_agg, lg);
        epi_split_kernel<<<(n4 + T - 1) / T, T>>>(p_agg, p_h2s, lg, n4);
    }

    // ---- layer 2 ----
    splitT_kernel<<<(F2 * F1 + T - 1) / T, T>>>(W2, F2, F1, F1, 0);
    mma_gemm<128, false><<<dim3(F2 / 128, MT), T, SM128>>>(p_h2s, p_WT, nullptr, p_t, N_NODES, K2E, F2);
    {
        int n4 = N_NODES * F2 / 4, lg = 6;
        init_agg<<<(n4 + T - 1) / T, T>>>(p_t, b2, p_agg, lg, n4);
        long long th = (long long)N_EDGES << lg;
        agg_kernel<<<(int)((th + T - 1) / T), T>>>(edge_index, p_t, p_agg, lg);
        epi_split_kernel<<<(n4 + T - 1) / T, T>>>(p_agg, p_h2s, lg, n4);
    }

    // ---- layer 3 ----
    splitT_kernel<<<(F3 * F2 + T - 1) / T, T>>>(W3, F3, F2, F2, 0);
    mma_gemm<64, false><<<dim3(F3 / 64, MT), T, SM64>>>(p_h2s, p_WT, nullptr, p_t, N_NODES, K3E, F3);
    {
        int n4 = N_NODES * F3 / 4, lg = 4;
        init_agg<<<(n4 + T - 1) / T, T>>>(p_t, b3, p_agg, lg, n4);
        long long th = (long long)N_EDGES << lg;
        agg_kernel<<<(int)((th + T - 1) / T), T>>>(edge_index, p_t, p_agg, lg);
        epi_f32_kernel<<<(n4 + T - 1) / T, T>>>(p_agg, p_h3, n4);
    }

    // ---- projection ----
    proj_kernel<<<(N_NODES * 32 + T - 1) / T, T>>>(p_h3, Wp, bp, out);
}

// round 6
// speedup vs baseline: 2.7300x; 1.2229x over previous
#include <cuda_runtime.h>
#include <cuda_bf16.h>
#include <math.h>
#include <stdint.h>

#define N_NODES 20000
#define N_EDGES 320000
#define FS      1000
#define XCOLS   1005
#define F1      512
#define F2      256
#define F3      64
#define KP1     1024             // padded resnet K

// ======================= static scratch =======================
__device__ __nv_bfloat16 g_A2 [(size_t)N_NODES * 2 * KP1]; // compact [hi|lo] resnet
__device__ __nv_bfloat16 g_WT [(size_t)F1 * 2 * KP1];      // compact [hi|lo] transposed weight
__device__ __nv_bfloat16 g_h2s[(size_t)N_NODES * 2 * F1];  // compact [hi|lo] activations
__device__ float g_base[(size_t)N_NODES * F1];
__device__ float g_t   [(size_t)N_NODES * F1];
__device__ float g_h3  [(size_t)N_NODES * F3];
__device__ float g_dinv[N_NODES];
__device__ float g_preL[3 * F1];
__device__ float g_preR[11 * F1];
__device__ float g_preC[3 * 256 * F1];
// CSR
__device__ int   g_degi[N_NODES];
__device__ int   g_rp[N_NODES + 1];
__device__ int   g_cursor[N_NODES];
__device__ int   g_csrc[N_EDGES];
__device__ float g_cw[N_EDGES];

// ======================= PTX helpers (portable, sm_80+) =======================
__device__ __forceinline__ uint32_t smem_u32(const void* p) {
    uint32_t a;
    asm("{ .reg .u64 t; cvta.to.shared.u64 t, %1; cvt.u32.u64 %0, t; }" : "=r"(a) : "l"(p));
    return a;
}
__device__ __forceinline__ void cp16(uint32_t dst, const void* src, bool pred) {
    int sz = pred ? 16 : 0;
    asm volatile("cp.async.cg.shared.global [%0], [%1], 16, %2;"
                 :: "r"(dst), "l"(src), "r"(sz) : "memory");
}
#define CP_COMMIT() asm volatile("cp.async.commit_group;" ::: "memory")
#define CP_WAIT1()  asm volatile("cp.async.wait_group 1;" ::: "memory")

__device__ __forceinline__ void ldsm_x4(uint32_t* r, uint32_t addr) {
    asm volatile("ldmatrix.sync.aligned.m8n8.x4.shared.b16 {%0,%1,%2,%3}, [%4];"
                 : "=r"(r[0]), "=r"(r[1]), "=r"(r[2]), "=r"(r[3]) : "r"(addr));
}
__device__ __forceinline__ void mma_bf16(float* d, const uint32_t* a, const uint32_t* b) {
    asm volatile("mma.sync.aligned.m16n8k16.row.col.f32.bf16.bf16.f32 "
                 "{%0,%1,%2,%3}, {%4,%5,%6,%7}, {%8,%9}, {%0,%1,%2,%3};"
                 : "+f"(d[0]), "+f"(d[1]), "+f"(d[2]), "+f"(d[3])
                 : "r"(a[0]), "r"(a[1]), "r"(a[2]), "r"(a[3]), "r"(b[0]), "r"(b[1]));
}
__device__ __forceinline__ uint32_t swz(uint32_t off) { return off ^ ((off >> 3) & 0x70); }

// ======================= prep kernels =======================
__global__ void zero_f(float* p, int n) {
    int i = blockIdx.x * blockDim.x + threadIdx.x;
    if (i < n) p[i] = 0.f;
}
__global__ void zero_i(int* p, int n) {
    int i = blockIdx.x * blockDim.x + threadIdx.x;
    if (i < n) p[i] = 0;
}
// weighted degree (float) + integer in-degree count, one pass
__global__ void deg_kernel(const int* __restrict__ ei, const float* __restrict__ ea) {
    int e = blockIdx.x * blockDim.x + threadIdx.x;
    if (e < N_EDGES) {
        int dst = ei[N_EDGES + e];
        atomicAdd(&g_dinv[dst], ea[e]);
        atomicAdd(&g_degi[dst], 1);
    }
}
__global__ void dinv_kernel() {
    int i = blockIdx.x * blockDim.x + threadIdx.x;
    if (i < N_NODES) g_dinv[i] = rsqrtf(g_dinv[i] + 1.0f);
}
// single-block exclusive scan of g_degi -> g_rp, also copy to g_cursor
__global__ void scan_kernel() {
    __shared__ int sh[1024];
    const int CH = (N_NODES + 1023) / 1024;
    int tid = threadIdx.x;
    int base = tid * CH;
    int s = 0;
    for (int j = 0; j < CH; j++) {
        int i = base + j;
        if (i < N_NODES) s += g_degi[i];
    }
    sh[tid] = s;
    __syncthreads();
    for (int off = 1; off < 1024; off <<= 1) {
        int v = (tid >= off) ? sh[tid - off] : 0;
        __syncthreads();
        sh[tid] += v;
        __syncthreads();
    }
    int run = tid ? sh[tid - 1] : 0;
    for (int j = 0; j < CH; j++) {
        int i = base + j;
        if (i < N_NODES) {
            g_rp[i] = run;
            g_cursor[i] = run;
            run += g_degi[i];
        }
    }
    if (tid == 1023) g_rp[N_NODES] = sh[1023];
}
// scatter edges into CSR with precomputed norm weight
__global__ void scatter_kernel(const int* __restrict__ ei, const float* __restrict__ ea) {
    int e = blockIdx.x * blockDim.x + threadIdx.x;
    if (e >= N_EDGES) return;
    int src = ei[e];
    int dst = ei[N_EDGES + e];
    float w = g_dinv[src] * ea[e] * g_dinv[dst];
    int pos = atomicAdd(&g_cursor[dst], 1);
    g_csrc[pos] = src;
    g_cw[pos] = w;
}

// resnet slice -> compact [hi|lo] bf16 blocks, padded to KP1
__global__ void split_x_kernel(const float* __restrict__ x) {
    int i = blockIdx.x;
    const float* xr = x + (size_t)i * XCOLS + 1;
    __nv_bfloat16* a = g_A2 + (size_t)i * 2 * KP1;
    for (int k = threadIdx.x; k < KP1; k += blockDim.x) {
        float v = (k < FS) ? xr[k] : 0.f;
        __nv_bfloat16 h = __float2bfloat16(v);
        a[k]       = h;
        a[KP1 + k] = __float2bfloat16(v - __bfloat162float(h));
    }
}
// W[K,Nn] rows [roff, roff+Ksrc) -> g_WT[Nn][2*Kp] compact [hi|lo] transposed
__global__ void splitT_kernel(const float* __restrict__ W, int Nn, int Kp, int Ksrc, int roff) {
    int idx = blockIdx.x * blockDim.x + threadIdx.x;
    if (idx >= Nn * Kp) return;
    int n = idx / Kp, k = idx % Kp;
    float v = (k < Ksrc) ? W[(size_t)(roff + k) * Nn + n] : 0.f;
    __nv_bfloat16 h = __float2bfloat16(v);
    __nv_bfloat16* b = g_WT + (size_t)n * 2 * Kp;
    b[k]      = h;
    b[Kp + k] = __float2bfloat16(v - __bfloat162float(h));
}

// out[r,:] = tab[r,:Kt] @ W1[off:off+Kt,:]
__global__ void pre_table(const float* __restrict__ tab, const float* __restrict__ W1,
                          float* __restrict__ out, int Kt, int off) {
    __shared__ float s[256];
    int r = blockIdx.x, j = threadIdx.x;
    if (j < Kt) s[j] = tab[(size_t)r * Kt + j];
    __syncthreads();
    float acc = 0.f;
    for (int k = 0; k < Kt; k++) acc = fmaf(s[k], W1[(size_t)(off + k) * F1 + j], acc);
    out[(size_t)r * F1 + j] = acc;
}
__global__ void pre_color(const float* __restrict__ ct, const float* __restrict__ W1) {
    __shared__ float s[96];
    int p = blockIdx.x >> 8, c = blockIdx.x & 255, j = threadIdx.x;
    if (j < 85) s[j] = ct[(size_t)c * 85 + j];
    __syncthreads();
    int off = 1500 + 85 * p;
    float acc = 0.f;
    for (int k = 0; k < 85; k++) acc = fmaf(s[k], W1[(size_t)(off + k) * F1 + j], acc);
    g_preC[((size_t)blockIdx.x) * F1 + j] = acc;
}
__global__ void node_base(const float* __restrict__ x) {
    int i = blockIdx.x;
    const float* xr = x + (size_t)i * XCOLS;
    int li = (int)xr[0] - 1;
    int ri = __float2int_rn(fabsf(xr[FS + 1]) * 10.0f);
    int c0 = (int)xr[XCOLS - 3];
    int c1 = (int)xr[XCOLS - 2];
    int c2 = (int)xr[XCOLS - 1];
    const float4* pL = (const float4*)(g_preL + (size_t)li * F1);
    const float4* pR = (const float4*)(g_preR + (size_t)ri * F1);
    const float4* p0 = (const float4*)(g_preC + ((size_t)(0 * 256 + c0)) * F1);
    const float4* p1 = (const float4*)(g_preC + ((size_t)(1 * 256 + c1)) * F1);
    const float4* p2 = (const float4*)(g_preC + ((size_t)(2 * 256 + c2)) * F1);
    float4* bo = (float4*)(g_base + (size_t)i * F1);
    int j = threadIdx.x;
    float4 a = pL[j], b = pR[j], u = p0[j], v = p1[j], w = p2[j];
    bo[j] = make_float4(a.x + b.x + u.x + v.x + w.x, a.y + b.y + u.y + v.y + w.y,
                        a.z + b.z + u.z + v.z + w.z, a.w + b.w + u.w + v.w + w.w);
}

// ======================= mma.sync bf16 GEMM =======================
// Logical A blocks [hi|hi|lo], B blocks [hi|lo|hi] over Keff=3*Kp; storage compact [hi|lo]
// with per-chunk k remap. CTA 128 x BN, BK=64, 256 thr, 8 warps.
template<int BN>
__device__ __forceinline__ void load_stage(const __nv_bfloat16* __restrict__ A,
                                           const __nv_bfloat16* __restrict__ B,
                                           int bm, int bn, int strideA, int strideB,
                                           int kA, int kB, int M,
                                           uint32_t sA, uint32_t sB) {
    int t = threadIdx.x;
#pragma unroll
    for (int i = 0; i < 4; i++) {
        int idx = t + i * 256;
        int row = idx >> 3, seg = idx & 7;
        int gr = bm + row;
        bool p = gr < M;
        const void* src = A + (size_t)(p ? gr : 0) * strideA + kA + seg * 8;
        cp16(sA + swz(row * 128 + seg * 16), src, p);
    }
#pragma unroll
    for (int i = 0; i < BN * 8 / 256; i++) {
        int idx = t + i * 256;
        int row = idx >> 3, seg = idx & 7;
        const void* src = B + (size_t)(bn + row) * strideB + kB + seg * 8;
        cp16(sB + swz(row * 128 + seg * 16), src, true);
    }
}

template<int BN, bool ADD_BASE>
__global__ __launch_bounds__(256) void mma_gemm(const __nv_bfloat16* __restrict__ A,
                                                const __nv_bfloat16* __restrict__ B,
                                                const float* __restrict__ base,
                                                float* __restrict__ C,
                                                int M, int Kp, int Nn) {
    extern __shared__ char smem[];
    constexpr int WN = BN / 2;
    constexpr int SS = (128 + BN) * 128;
    uint32_t sb = smem_u32(smem);
    int tid = threadIdx.x, wid = tid >> 5, lane = tid & 31;
    int bm = blockIdx.y * 128, bn = blockIdx.x * BN;
    int wm = (wid & 3) * 32;
    int wn = (wid >> 2) * WN;
    int strideA = 2 * Kp, strideB = 2 * Kp;

    float acc[2][WN / 8][4];
#pragma unroll
    for (int i = 0; i < 2; i++)
#pragma unroll
        for (int j = 0; j < WN / 8; j++)
#pragma unroll
            for (int q = 0; q < 4; q++) acc[i][j][q] = 0.f;

    int nT = (3 * Kp) >> 6;
    load_stage<BN>(A, B, bm, bn, strideA, strideB, 0, 0, M, sb, sb + 128 * 128);
    CP_COMMIT();

    for (int t = 0; t < nT; t++) {
        if (t + 1 < nT) {
            int k0 = (t + 1) * 64;
            int kA = (k0 < Kp) ? k0 : k0 - Kp;          // [hi|hi|lo] from [hi|lo]
            int kB = (k0 < 2 * Kp) ? k0 : k0 - 2 * Kp;  // [hi|lo|hi] from [hi|lo]
            uint32_t s1 = sb + ((t + 1) & 1) * SS;
            load_stage<BN>(A, B, bm, bn, strideA, strideB, kA, kB, M, s1, s1 + 128 * 128);
        }
        CP_COMMIT();
        CP_WAIT1();
        __syncthreads();

        uint32_t sA = sb + (t & 1) * SS;
        uint32_t sB = sA + 128 * 128;
#pragma unroll
        for (int ks = 0; ks < 4; ks++) {
            uint32_t af[2][4];
#pragma unroll
            for (int mi = 0; mi < 2; mi++) {
                int row = wm + mi * 16 + (lane & 15);
                ldsm_x4(af[mi], sA + swz(row * 128 + ks * 32 + ((lane >> 4) << 4)));
            }
#pragma unroll
            for (int nj = 0; nj < WN / 16; nj++) {
                uint32_t bf[4];
                int row = wn + nj * 16 + (lane & 7) + ((lane >> 4) << 3);
                ldsm_x4(bf, sB + swz(row * 128 + ks * 32 + (((lane >> 3) & 1) << 4)));
                mma_bf16(acc[0][2 * nj],     af[0], bf);
                mma_bf16(acc[0][2 * nj + 1], af[0], bf + 2);
                mma_bf16(acc[1][2 * nj],     af[1], bf);
                mma_bf16(acc[1][2 * nj + 1], af[1], bf + 2);
            }
        }
        __syncthreads();
    }

#pragma unroll
    for (int mi = 0; mi < 2; mi++) {
#pragma unroll
        for (int nj = 0; nj < WN / 8; nj++) {
            int row = bm + wm + mi * 16 + (lane >> 2);
            int col = bn + wn + nj * 8 + (lane & 3) * 2;
#pragma unroll
            for (int h = 0; h < 2; h++) {
                int r = row + h * 8;
                if (r < M) {
                    float2 v = make_float2(acc[mi][nj][h * 2], acc[mi][nj][h * 2 + 1]);
                    if (ADD_BASE) {
                        float2 b2 = *(const float2*)(base + (size_t)r * Nn + col);
                        v.x += b2.x; v.y += b2.y;
                    }
                    *(float2*)(C + (size_t)r * Nn + col) = v;
                }
            }
        }
    }
}

// ======================= fused CSR aggregation =======================
// h_out[n] = leakyrelu( sum_{in-edges} t[src]*w + t[n]*dinv[n]^2 + bias )
// SPLIT: write compact [hi|lo] bf16 row (feeds next GEMM); else fp32.
template<int F, int NPB, bool SPLIT>
__global__ __launch_bounds__(128) void csr_agg(const float* __restrict__ t,
                                               const float* __restrict__ b,
                                               __nv_bfloat16* __restrict__ hs,
                                               float* __restrict__ fout) {
    constexpr int C = F / 4;                 // float4 channels per node
    int node = blockIdx.x * NPB + threadIdx.x / C;
    int ch = threadIdx.x % C;
    if (node >= N_NODES) return;
    int beg = g_rp[node], end = g_rp[node + 1];
    const float4* tv = (const float4*)t;
    float d = g_dinv[node];
    float dd = d * d;
    float4 self = tv[(size_t)node * C + ch];
    float4 bv = ((const float4*)b)[ch];
    float4 acc = make_float4(fmaf(self.x, dd, bv.x), fmaf(self.y, dd, bv.y),
                             fmaf(self.z, dd, bv.z), fmaf(self.w, dd, bv.w));
    int i = beg;
    for (; i + 2 <= end; i += 2) {
        int s0 = g_csrc[i], s1 = g_csrc[i + 1];
        float w0 = g_cw[i], w1 = g_cw[i + 1];
        float4 v0 = tv[(size_t)s0 * C + ch];
        float4 v1 = tv[(size_t)s1 * C + ch];
        acc.x += v0.x * w0 + v1.x * w1;
        acc.y += v0.y * w0 + v1.y * w1;
        acc.z += v0.z * w0 + v1.z * w1;
        acc.w += v0.w * w0 + v1.w * w1;
    }
    if (i < end) {
        int s0 = g_csrc[i];
        float w0 = g_cw[i];
        float4 v0 = tv[(size_t)s0 * C + ch];
        acc.x += v0.x * w0; acc.y += v0.y * w0; acc.z += v0.z * w0; acc.w += v0.w * w0;
    }
    float f[4] = {acc.x, acc.y, acc.z, acc.w};
#pragma unroll
    for (int q = 0; q < 4; q++) f[q] = f[q] > 0.f ? f[q] : 0.01f * f[q];
    if (SPLIT) {
        __nv_bfloat16 h[4], l[4];
#pragma unroll
        for (int q = 0; q < 4; q++) {
            h[q] = __float2bfloat16(f[q]);
            l[q] = __float2bfloat16(f[q] - __bfloat162float(h[q]));
        }
        __nv_bfloat16* row = hs + (size_t)node * 2 * F;
        *(uint2*)(row + ch * 4)     = *(uint2*)h;
        *(uint2*)(row + F + ch * 4) = *(uint2*)l;
    } else {
        *(float4*)(fout + (size_t)node * F + ch * 4) = make_float4(f[0], f[1], f[2], f[3]);
    }
}

__global__ void proj_kernel(const float* __restrict__ h, const float* __restrict__ Wp,
                            const float* __restrict__ bp, float* __restrict__ out) {
    __shared__ float w[64 * 3];
    if (threadIdx.x < 192) w[threadIdx.x] = Wp[threadIdx.x];
    __syncthreads();
    int warp = threadIdx.x >> 5, lane = threadIdx.x & 31;
    int i = blockIdx.x * (blockDim.x >> 5) + warp;
    if (i >= N_NODES) return;
    const float* hr = h + (size_t)i * 64;
    float a0 = 0.f, a1 = 0.f, a2 = 0.f;
    for (int k = lane; k < 64; k += 32) {
        float hv = hr[k];
        a0 = fmaf(hv, w[k * 3 + 0], a0);
        a1 = fmaf(hv, w[k * 3 + 1], a1);
        a2 = fmaf(hv, w[k * 3 + 2], a2);
    }
#pragma unroll
    for (int off = 16; off; off >>= 1) {
        a0 += __shfl_down_sync(0xffffffffu, a0, off);
        a1 += __shfl_down_sync(0xffffffffu, a1, off);
        a2 += __shfl_down_sync(0xffffffffu, a2, off);
    }
    if (lane == 0) {
        out[(size_t)i * 3 + 0] = a0 + bp[0];
        out[(size_t)i * 3 + 1] = a1 + bp[1];
        out[(size_t)i * 3 + 2] = a2 + bp[2];
    }
}

// ======================= launch =======================
extern "C" void kernel_launch(void* const* d_in, const int* in_sizes, int n_in,
                              void* d_out, int out_size) {
    const float* x           = (const float*)d_in[0];
    const int*   edge_index  = (const int*)  d_in[1];
    const float* edge_attr   = (const float*)d_in[2];
    const float* layer_table = (const float*)d_in[3];
    const float* rel_table   = (const float*)d_in[4];
    const float* color_table = (const float*)d_in[5];
    const float* W1 = (const float*)d_in[6];
    const float* b1 = (const float*)d_in[7];
    const float* W2 = (const float*)d_in[8];
    const float* b2 = (const float*)d_in[9];
    const float* W3 = (const float*)d_in[10];
    const float* b3 = (const float*)d_in[11];
    const float* Wp = (const float*)d_in[12];
    const float* bp = (const float*)d_in[13];
    float* out = (float*)d_out;

    __nv_bfloat16 *p_A2, *p_WT, *p_h2s;
    float *p_base, *p_t, *p_h3, *p_dinv, *p_preL, *p_preR;
    int *p_degi;
    cudaGetSymbolAddress((void**)&p_A2,   g_A2);
    cudaGetSymbolAddress((void**)&p_WT,   g_WT);
    cudaGetSymbolAddress((void**)&p_h2s,  g_h2s);
    cudaGetSymbolAddress((void**)&p_base, g_base);
    cudaGetSymbolAddress((void**)&p_t,    g_t);
    cudaGetSymbolAddress((void**)&p_h3,   g_h3);
    cudaGetSymbolAddress((void**)&p_dinv, g_dinv);
    cudaGetSymbolAddress((void**)&p_preL, g_preL);
    cudaGetSymbolAddress((void**)&p_preR, g_preR);
    cudaGetSymbolAddress((void**)&p_degi, g_degi);

    const int T = 256;
    const int SM128 = 2 * (128 + 128) * 128;   // 65536
    const int SM64  = 2 * (128 + 64) * 128;    // 49152
    cudaFuncSetAttribute(mma_gemm<128, true>,  cudaFuncAttributeMaxDynamicSharedMemorySize, SM128);
    cudaFuncSetAttribute(mma_gemm<128, false>, cudaFuncAttributeMaxDynamicSharedMemorySize, SM128);
    cudaFuncSetAttribute(mma_gemm<64,  false>, cudaFuncAttributeMaxDynamicSharedMemorySize, SM64);

    // degrees -> dinv -> CSR (dst-sorted, weights fused)
    zero_f<<<(N_NODES + T - 1) / T, T>>>(p_dinv, N_NODES);
    zero_i<<<(N_NODES + T - 1) / T, T>>>(p_degi, N_NODES);
    deg_kernel<<<(N_EDGES + T - 1) / T, T>>>(edge_index, edge_attr);
    dinv_kernel<<<(N_NODES + T - 1) / T, T>>>();
    scan_kernel<<<1, 1024>>>();
    scatter_kernel<<<(N_EDGES + T - 1) / T, T>>>(edge_index, edge_attr);

    // GEMM1 inputs
    split_x_kernel<<<N_NODES, T>>>(x);
    splitT_kernel<<<(F1 * KP1 + T - 1) / T, T>>>(W1, F1, KP1, FS, 250);
    pre_table<<<3, 512>>>(layer_table, W1, p_preL, 250, 0);
    pre_table<<<11, 512>>>(rel_table, W1, p_preR, 250, 1250);
    pre_color<<<768, 512>>>(color_table, W1);
    node_base<<<N_NODES, 128>>>(x);

    const int MT = (N_NODES + 127) / 128;   // 157

    // ---- layer 1 ----
    mma_gemm<128, true><<<dim3(F1 / 128, MT), T, SM128>>>(p_A2, p_WT, p_base, p_t, N_NODES, KP1, F1);
    csr_agg<F1, 1, true><<<N_NODES, 128>>>(p_t, b1, p_h2s, nullptr);

    // ---- layer 2 ----
    splitT_kernel<<<(F2 * F1 + T - 1) / T, T>>>(W2, F2, F1, F1, 0);
    mma_gemm<128, false><<<dim3(F2 / 128, MT), T, SM128>>>(p_h2s, p_WT, nullptr, p_t, N_NODES, F1, F2);
    csr_agg<F2, 2, true><<<(N_NODES + 1) / 2, 128>>>(p_t, b2, p_h2s, nullptr);

    // ---- layer 3 ----
    splitT_kernel<<<(F3 * F2 + T - 1) / T, T>>>(W3, F3, F2, F2, 0);
    mma_gemm<64, false><<<dim3(F3 / 64, MT), T, SM64>>>(p_h2s, p_WT, nullptr, p_t, N_NODES, F2, F3);
    csr_agg<F3, 8, false><<<(N_NODES + 7) / 8, 128>>>(p_t, b3, nullptr, p_h3);

    // ---- projection ----
    proj_kernel<<<(N_NODES * 32 + T - 1) / T, T>>>(p_h3, Wp, bp, out);
}

// round 7
// speedup vs baseline: 3.0275x; 1.1090x over previous
#include <cuda_runtime.h>
#include <cuda_bf16.h>
#include <math.h>
#include <stdint.h>

#define N_NODES 20000
#define N_EDGES 320000
#define FS      1000
#define XCOLS   1005
#define F1      512
#define F2      256
#define F3      64
#define KP1     1024             // padded resnet K

// ======================= static scratch =======================
__device__ __nv_bfloat16 g_A2 [(size_t)N_NODES * 2 * KP1]; // compact [hi|lo] resnet
__device__ __nv_bfloat16 g_WT [(size_t)F1 * 2 * KP1];      // compact [hi|lo] transposed weight
__device__ __nv_bfloat16 g_h2s[(size_t)N_NODES * 2 * F1];  // compact [hi|lo] activations
__device__ float g_base[(size_t)N_NODES * F1];
__device__ float g_t   [(size_t)N_NODES * F1];
__device__ float g_h3  [(size_t)N_NODES * F3];
__device__ float g_dinv[N_NODES];
__device__ float g_preL[3 * F1];
__device__ float g_preR[11 * F1];
__device__ float g_preC[3 * 256 * F1];
// CSR
__device__ int   g_degi[N_NODES];
__device__ int   g_rp[N_NODES + 1];
__device__ int   g_cursor[N_NODES];
__device__ int   g_csrc[N_EDGES];
__device__ float g_cw[N_EDGES];

// ======================= PTX helpers (portable, sm_80+) =======================
__device__ __forceinline__ uint32_t smem_u32(const void* p) {
    uint32_t a;
    asm("{ .reg .u64 t; cvta.to.shared.u64 t, %1; cvt.u32.u64 %0, t; }" : "=r"(a) : "l"(p));
    return a;
}
__device__ __forceinline__ void cp16(uint32_t dst, const void* src, bool pred) {
    int sz = pred ? 16 : 0;
    asm volatile("cp.async.cg.shared.global [%0], [%1], 16, %2;"
                 :: "r"(dst), "l"(src), "r"(sz) : "memory");
}
#define CP_COMMIT() asm volatile("cp.async.commit_group;" ::: "memory")
#define CP_WAIT2()  asm volatile("cp.async.wait_group 2;" ::: "memory")

__device__ __forceinline__ void ldsm_x4(uint32_t* r, uint32_t addr) {
    asm volatile("ldmatrix.sync.aligned.m8n8.x4.shared.b16 {%0,%1,%2,%3}, [%4];"
                 : "=r"(r[0]), "=r"(r[1]), "=r"(r[2]), "=r"(r[3]) : "r"(addr));
}
__device__ __forceinline__ void mma_bf16(float* d, const uint32_t* a, const uint32_t* b) {
    asm volatile("mma.sync.aligned.m16n8k16.row.col.f32.bf16.bf16.f32 "
                 "{%0,%1,%2,%3}, {%4,%5,%6,%7}, {%8,%9}, {%0,%1,%2,%3};"
                 : "+f"(d[0]), "+f"(d[1]), "+f"(d[2]), "+f"(d[3])
                 : "r"(a[0]), "r"(a[1]), "r"(a[2]), "r"(a[3]), "r"(b[0]), "r"(b[1]));
}
__device__ __forceinline__ uint32_t swz(uint32_t off) { return off ^ ((off >> 3) & 0x70); }

// ======================= prep kernels (fused) =======================
__global__ void zero_both() {
    int i = blockIdx.x * blockDim.x + threadIdx.x;
    if (i < N_NODES) { g_dinv[i] = 0.f; g_degi[i] = 0; }
}
__global__ void deg_kernel(const int* __restrict__ ei, const float* __restrict__ ea) {
    int e = blockIdx.x * blockDim.x + threadIdx.x;
    if (e < N_EDGES) {
        int dst = ei[N_EDGES + e];
        atomicAdd(&g_dinv[dst], ea[e]);
        atomicAdd(&g_degi[dst], 1);
    }
}
// single-block: dinv finalize + exclusive scan of degi -> rp/cursor
__global__ void scan_kernel() {
    __shared__ int sh[1024];
    const int CH = (N_NODES + 1023) / 1024;
    int tid = threadIdx.x;
    int base = tid * CH;
    int s = 0;
    for (int j = 0; j < CH; j++) {
        int i = base + j;
        if (i < N_NODES) {
            g_dinv[i] = rsqrtf(g_dinv[i] + 1.0f);
            s += g_degi[i];
        }
    }
    sh[tid] = s;
    __syncthreads();
    for (int off = 1; off < 1024; off <<= 1) {
        int v = (tid >= off) ? sh[tid - off] : 0;
        __syncthreads();
        sh[tid] += v;
        __syncthreads();
    }
    int run = tid ? sh[tid - 1] : 0;
    for (int j = 0; j < CH; j++) {
        int i = base + j;
        if (i < N_NODES) {
            g_rp[i] = run;
            g_cursor[i] = run;
            run += g_degi[i];
        }
    }
    if (tid == 1023) g_rp[N_NODES] = sh[1023];
}
__global__ void scatter_kernel(const int* __restrict__ ei, const float* __restrict__ ea) {
    int e = blockIdx.x * blockDim.x + threadIdx.x;
    if (e >= N_EDGES) return;
    int src = ei[e];
    int dst = ei[N_EDGES + e];
    float w = g_dinv[src] * ea[e] * g_dinv[dst];
    int pos = atomicAdd(&g_cursor[dst], 1);
    g_csrc[pos] = src;
    g_cw[pos] = w;
}

// fused: all table @ W1 precomputations. blocks 0-2: layer, 3-13: rel, 14-781: color
__global__ void pre_all(const float* __restrict__ layer_table, const float* __restrict__ rel_table,
                        const float* __restrict__ color_table, const float* __restrict__ W1) {
    __shared__ float s[256];
    int b = blockIdx.x, j = threadIdx.x;
    const float* tab;
    float* outp;
    int Kt, off;
    if (b < 3)       { tab = layer_table + (size_t)b * 250;        outp = g_preL + (size_t)b * F1;        Kt = 250; off = 0; }
    else if (b < 14) { tab = rel_table + (size_t)(b - 3) * 250;    outp = g_preR + (size_t)(b - 3) * F1;  Kt = 250; off = 1250; }
    else {
        int q = b - 14;
        int p = q >> 8, c = q & 255;
        tab = color_table + (size_t)c * 85;
        outp = g_preC + (size_t)q * F1;
        Kt = 85; off = 1500 + 85 * p;
    }
    if (j < Kt) s[j] = tab[j];
    __syncthreads();
    float acc = 0.f;
    for (int k = 0; k < Kt; k++) acc = fmaf(s[k], W1[(size_t)(off + k) * F1 + j], acc);
    outp[j] = acc;
}

// fused: resnet split + node base. one block (256 thr) per node.
__global__ void split_base(const float* __restrict__ x) {
    int i = blockIdx.x;
    const float* xr = x + (size_t)i * XCOLS;
    __nv_bfloat16* a = g_A2 + (size_t)i * 2 * KP1;
    for (int k = threadIdx.x; k < KP1; k += blockDim.x) {
        float v = (k < FS) ? xr[1 + k] : 0.f;
        __nv_bfloat16 h = __float2bfloat16(v);
        a[k]       = h;
        a[KP1 + k] = __float2bfloat16(v - __bfloat162float(h));
    }
    int j = threadIdx.x;
    if (j < 128) {
        int li = (int)xr[0] - 1;
        int ri = __float2int_rn(fabsf(xr[FS + 1]) * 10.0f);
        int c0 = (int)xr[XCOLS - 3];
        int c1 = (int)xr[XCOLS - 2];
        int c2 = (int)xr[XCOLS - 1];
        float4 pa = ((const float4*)(g_preL + (size_t)li * F1))[j];
        float4 pb = ((const float4*)(g_preR + (size_t)ri * F1))[j];
        float4 u = ((const float4*)(g_preC + ((size_t)(0 * 256 + c0)) * F1))[j];
        float4 v = ((const float4*)(g_preC + ((size_t)(1 * 256 + c1)) * F1))[j];
        float4 w = ((const float4*)(g_preC + ((size_t)(2 * 256 + c2)) * F1))[j];
        ((float4*)(g_base + (size_t)i * F1))[j] =
            make_float4(pa.x + pb.x + u.x + v.x + w.x, pa.y + pb.y + u.y + v.y + w.y,
                        pa.z + pb.z + u.z + v.z + w.z, pa.w + pb.w + u.w + v.w + w.w);
    }
}

// W[K,Nn] rows [roff, roff+Ksrc) -> g_WT[Nn][2*Kp] compact [hi|lo] transposed
__global__ void splitT_kernel(const float* __restrict__ W, int Nn, int Kp, int Ksrc, int roff) {
    int idx = blockIdx.x * blockDim.x + threadIdx.x;
    if (idx >= Nn * Kp) return;
    int n = idx / Kp, k = idx % Kp;
    float v = (k < Ksrc) ? W[(size_t)(roff + k) * Nn + n] : 0.f;
    __nv_bfloat16 h = __float2bfloat16(v);
    __nv_bfloat16* b = g_WT + (size_t)n * 2 * Kp;
    b[k]      = h;
    b[Kp + k] = __float2bfloat16(v - __bfloat162float(h));
}

// ======================= mma.sync bf16 GEMM (3-stage) =======================
// Logical A blocks [hi|hi|lo], B blocks [hi|lo|hi] over Keff=3*Kp; storage compact [hi|lo].
template<int BN>
__device__ __forceinline__ void load_stage(const __nv_bfloat16* __restrict__ A,
                                           const __nv_bfloat16* __restrict__ B,
                                           int bm, int bn, int stride,
                                           int kA, int kB, int M,
                                           uint32_t sA, uint32_t sB) {
    int t = threadIdx.x;
#pragma unroll
    for (int i = 0; i < 4; i++) {
        int idx = t + i * 256;
        int row = idx >> 3, seg = idx & 7;
        int gr = bm + row;
        bool p = gr < M;
        const void* src = A + (size_t)(p ? gr : 0) * stride + kA + seg * 8;
        cp16(sA + swz(row * 128 + seg * 16), src, p);
    }
#pragma unroll
    for (int i = 0; i < BN * 8 / 256; i++) {
        int idx = t + i * 256;
        int row = idx >> 3, seg = idx & 7;
        const void* src = B + (size_t)(bn + row) * stride + kB + seg * 8;
        cp16(sB + swz(row * 128 + seg * 16), src, true);
    }
}

template<int BN, bool ADD_BASE>
__global__ __launch_bounds__(256) void mma_gemm(const __nv_bfloat16* __restrict__ A,
                                                const __nv_bfloat16* __restrict__ B,
                                                const float* __restrict__ base,
                                                float* __restrict__ C,
                                                int M, int Kp, int Nn) {
    extern __shared__ char smem[];
    constexpr int WN = BN / 2;
    constexpr int SS = (128 + BN) * 128;     // bytes per stage
    uint32_t sb = smem_u32(smem);
    int tid = threadIdx.x, wid = tid >> 5, lane = tid & 31;
    int bm = blockIdx.y * 128, bn = blockIdx.x * BN;
    int wm = (wid & 3) * 32;
    int wn = (wid >> 2) * WN;
    int stride = 2 * Kp;

    float acc[2][WN / 8][4];
#pragma unroll
    for (int i = 0; i < 2; i++)
#pragma unroll
        for (int j = 0; j < WN / 8; j++)
#pragma unroll
            for (int q = 0; q < 4; q++) acc[i][j][q] = 0.f;

    int nT = (3 * Kp) >> 6;
    // prologue: stages 0,1
#pragma unroll
    for (int s = 0; s < 2; s++) {
        int k0 = s * 64;
        int kA = (k0 < Kp) ? k0 : k0 - Kp;
        int kB = (k0 < 2 * Kp) ? k0 : k0 - 2 * Kp;
        uint32_t sp = sb + (uint32_t)s * SS;
        load_stage<BN>(A, B, bm, bn, stride, kA, kB, M, sp, sp + 128 * 128);
        CP_COMMIT();
    }

    for (int t = 0; t < nT; t++) {
        if (t + 2 < nT) {
            int k0 = (t + 2) * 64;
            int kA = (k0 < Kp) ? k0 : k0 - Kp;          // [hi|hi|lo]
            int kB = (k0 < 2 * Kp) ? k0 : k0 - 2 * Kp;  // [hi|lo|hi]
            uint32_t sp = sb + (uint32_t)((t + 2) % 3) * SS;
            load_stage<BN>(A, B, bm, bn, stride, kA, kB, M, sp, sp + 128 * 128);
        }
        CP_COMMIT();
        CP_WAIT2();
        __syncthreads();

        uint32_t sA = sb + (uint32_t)(t % 3) * SS;
        uint32_t sB = sA + 128 * 128;
#pragma unroll
        for (int ks = 0; ks < 4; ks++) {
            uint32_t af[2][4];
#pragma unroll
            for (int mi = 0; mi < 2; mi++) {
                int row = wm + mi * 16 + (lane & 15);
                ldsm_x4(af[mi], sA + swz(row * 128 + ks * 32 + ((lane >> 4) << 4)));
            }
#pragma unroll
            for (int nj = 0; nj < WN / 16; nj++) {
                uint32_t bf[4];
                int row = wn + nj * 16 + (lane & 7) + ((lane >> 4) << 3);
                ldsm_x4(bf, sB + swz(row * 128 + ks * 32 + (((lane >> 3) & 1) << 4)));
                mma_bf16(acc[0][2 * nj],     af[0], bf);
                mma_bf16(acc[0][2 * nj + 1], af[0], bf + 2);
                mma_bf16(acc[1][2 * nj],     af[1], bf);
                mma_bf16(acc[1][2 * nj + 1], af[1], bf + 2);
            }
        }
        __syncthreads();
    }

#pragma unroll
    for (int mi = 0; mi < 2; mi++) {
#pragma unroll
        for (int nj = 0; nj < WN / 8; nj++) {
            int row = bm + wm + mi * 16 + (lane >> 2);
            int col = bn + wn + nj * 8 + (lane & 3) * 2;
#pragma unroll
            for (int h = 0; h < 2; h++) {
                int r = row + h * 8;
                if (r < M) {
                    float2 v = make_float2(acc[mi][nj][h * 2], acc[mi][nj][h * 2 + 1]);
                    if (ADD_BASE) {
                        float2 b2 = *(const float2*)(base + (size_t)r * Nn + col);
                        v.x += b2.x; v.y += b2.y;
                    }
                    *(float2*)(C + (size_t)r * Nn + col) = v;
                }
            }
        }
    }
}

// ======================= fused CSR aggregation =======================
template<int F, int NPB, bool SPLIT>
__global__ __launch_bounds__(128) void csr_agg(const float* __restrict__ t,
                                               const float* __restrict__ b,
                                               __nv_bfloat16* __restrict__ hs,
                                               float* __restrict__ fout) {
    constexpr int C = F / 4;
    int node = blockIdx.x * NPB + threadIdx.x / C;
    int ch = threadIdx.x % C;
    if (node >= N_NODES) return;
    int beg = g_rp[node], end = g_rp[node + 1];
    const float4* tv = (const float4*)t;
    float d = g_dinv[node];
    float dd = d * d;
    float4 self = tv[(size_t)node * C + ch];
    float4 bv = ((const float4*)b)[ch];
    float4 acc = make_float4(fmaf(self.x, dd, bv.x), fmaf(self.y, dd, bv.y),
                             fmaf(self.z, dd, bv.z), fmaf(self.w, dd, bv.w));
    int i = beg;
    for (; i + 4 <= end; i += 4) {
        int s0 = g_csrc[i], s1 = g_csrc[i + 1], s2 = g_csrc[i + 2], s3 = g_csrc[i + 3];
        float w0 = g_cw[i], w1 = g_cw[i + 1], w2 = g_cw[i + 2], w3 = g_cw[i + 3];
        float4 v0 = tv[(size_t)s0 * C + ch];
        float4 v1 = tv[(size_t)s1 * C + ch];
        float4 v2 = tv[(size_t)s2 * C + ch];
        float4 v3 = tv[(size_t)s3 * C + ch];
        acc.x += v0.x * w0 + v1.x * w1 + v2.x * w2 + v3.x * w3;
        acc.y += v0.y * w0 + v1.y * w1 + v2.y * w2 + v3.y * w3;
        acc.z += v0.z * w0 + v1.z * w1 + v2.z * w2 + v3.z * w3;
        acc.w += v0.w * w0 + v1.w * w1 + v2.w * w2 + v3.w * w3;
    }
    for (; i < end; i++) {
        int s0 = g_csrc[i];
        float w0 = g_cw[i];
        float4 v0 = tv[(size_t)s0 * C + ch];
        acc.x += v0.x * w0; acc.y += v0.y * w0; acc.z += v0.z * w0; acc.w += v0.w * w0;
    }
    float f[4] = {acc.x, acc.y, acc.z, acc.w};
#pragma unroll
    for (int q = 0; q < 4; q++) f[q] = f[q] > 0.f ? f[q] : 0.01f * f[q];
    if (SPLIT) {
        __nv_bfloat16 h[4], l[4];
#pragma unroll
        for (int q = 0; q < 4; q++) {
            h[q] = __float2bfloat16(f[q]);
            l[q] = __float2bfloat16(f[q] - __bfloat162float(h[q]));
        }
        __nv_bfloat16* row = hs + (size_t)node * 2 * F;
        *(uint2*)(row + ch * 4)     = *(uint2*)h;
        *(uint2*)(row + F + ch * 4) = *(uint2*)l;
    } else {
        *(float4*)(fout + (size_t)node * F + ch * 4) = make_float4(f[0], f[1], f[2], f[3]);
    }
}

__global__ void proj_kernel(const float* __restrict__ h, const float* __restrict__ Wp,
                            const float* __restrict__ bp, float* __restrict__ out) {
    __shared__ float w[64 * 3];
    if (threadIdx.x < 192) w[threadIdx.x] = Wp[threadIdx.x];
    __syncthreads();
    int warp = threadIdx.x >> 5, lane = threadIdx.x & 31;
    int i = blockIdx.x * (blockDim.x >> 5) + warp;
    if (i >= N_NODES) return;
    const float* hr = h + (size_t)i * 64;
    float a0 = 0.f, a1 = 0.f, a2 = 0.f;
    for (int k = lane; k < 64; k += 32) {
        float hv = hr[k];
        a0 = fmaf(hv, w[k * 3 + 0], a0);
        a1 = fmaf(hv, w[k * 3 + 1], a1);
        a2 = fmaf(hv, w[k * 3 + 2], a2);
    }
#pragma unroll
    for (int off = 16; off; off >>= 1) {
        a0 += __shfl_down_sync(0xffffffffu, a0, off);
        a1 += __shfl_down_sync(0xffffffffu, a1, off);
        a2 += __shfl_down_sync(0xffffffffu, a2, off);
    }
    if (lane == 0) {
        out[(size_t)i * 3 + 0] = a0 + bp[0];
        out[(size_t)i * 3 + 1] = a1 + bp[1];
        out[(size_t)i * 3 + 2] = a2 + bp[2];
    }
}

// ======================= launch =======================
extern "C" void kernel_launch(void* const* d_in, const int* in_sizes, int n_in,
                              void* d_out, int out_size) {
    const float* x           = (const float*)d_in[0];
    const int*   edge_index  = (const int*)  d_in[1];
    const float* edge_attr   = (const float*)d_in[2];
    const float* layer_table = (const float*)d_in[3];
    const float* rel_table   = (const float*)d_in[4];
    const float* color_table = (const float*)d_in[5];
    const float* W1 = (const float*)d_in[6];
    const float* b1 = (const float*)d_in[7];
    const float* W2 = (const float*)d_in[8];
    const float* b2 = (const float*)d_in[9];
    const float* W3 = (const float*)d_in[10];
    const float* b3 = (const float*)d_in[11];
    const float* Wp = (const float*)d_in[12];
    const float* bp = (const float*)d_in[13];
    float* out = (float*)d_out;

    __nv_bfloat16 *p_A2, *p_WT, *p_h2s;
    float *p_base, *p_t, *p_h3;
    cudaGetSymbolAddress((void**)&p_A2,   g_A2);
    cudaGetSymbolAddress((void**)&p_WT,   g_WT);
    cudaGetSymbolAddress((void**)&p_h2s,  g_h2s);
    cudaGetSymbolAddress((void**)&p_base, g_base);
    cudaGetSymbolAddress((void**)&p_t,    g_t);
    cudaGetSymbolAddress((void**)&p_h3,   g_h3);

    const int T = 256;
    const int SM128 = 3 * (128 + 128) * 128;   // 98304
    const int SM64  = 3 * (128 + 64) * 128;    // 73728
    cudaFuncSetAttribute(mma_gemm<128, true>,  cudaFuncAttributeMaxDynamicSharedMemorySize, SM128);
    cudaFuncSetAttribute(mma_gemm<128, false>, cudaFuncAttributeMaxDynamicSharedMemorySize, SM128);
    cudaFuncSetAttribute(mma_gemm<64,  false>, cudaFuncAttributeMaxDynamicSharedMemorySize, SM64);

    // graph prep: degrees -> dinv+scan -> CSR scatter (weights fused)
    zero_both<<<(N_NODES + T - 1) / T, T>>>();
    deg_kernel<<<(N_EDGES + T - 1) / T, T>>>(edge_index, edge_attr);
    scan_kernel<<<1, 1024>>>();
    scatter_kernel<<<(N_EDGES + T - 1) / T, T>>>(edge_index, edge_attr);

    // GEMM1 inputs
    pre_all<<<782, 512>>>(layer_table, rel_table, color_table, W1);
    splitT_kernel<<<(F1 * KP1 + T - 1) / T, T>>>(W1, F1, KP1, FS, 250);
    split_base<<<N_NODES, T>>>(x);

    const int MT = (N_NODES + 127) / 128;   // 157

    // ---- layer 1 ----
    mma_gemm<128, true><<<dim3(F1 / 128, MT), T, SM128>>>(p_A2, p_WT, p_base, p_t, N_NODES, KP1, F1);
    csr_agg<F1, 1, true><<<N_NODES, 128>>>(p_t, b1, p_h2s, nullptr);

    // ---- layer 2 ----
    splitT_kernel<<<(F2 * F1 + T - 1) / T, T>>>(W2, F2, F1, F1, 0);
    mma_gemm<128, false><<<dim3(F2 / 128, MT), T, SM128>>>(p_h2s, p_WT, nullptr, p_t, N_NODES, F1, F2);
    csr_agg<F2, 2, true><<<(N_NODES + 1) / 2, 128>>>(p_t, b2, p_h2s, nullptr);

    // ---- layer 3 ----
    splitT_kernel<<<(F3 * F2 + T - 1) / T, T>>>(W3, F3, F2, F2, 0);
    mma_gemm<64, false><<<dim3(F3 / 64, MT), T, SM64>>>(p_h2s, p_WT, nullptr, p_t, N_NODES, F2, F3);
    csr_agg<F3, 8, false><<<(N_NODES + 7) / 8, 128>>>(p_t, b3, nullptr, p_h3);

    // ---- projection ----
    proj_kernel<<<(N_NODES * 32 + T - 1) / T, T>>>(p_h3, Wp, bp, out);
}

// round 8
// speedup vs baseline: 3.4597x; 1.1428x over previous
#include <cuda_runtime.h>
#include <cuda_fp16.h>
#include <math.h>
#include <stdint.h>

#define N_NODES 20000
#define N_EDGES 320000
#define FS      1000
#define XCOLS   1005
#define F1      512
#define F2      256
#define F3      64
#define KP1     1024             // padded resnet K

// ======================= static scratch =======================
__device__ __half g_A2 [(size_t)N_NODES * KP1];     // fp16 hi of resnet (A operand, layer1)
__device__ __half g_WT [(size_t)F1 * 2 * KP1];      // [hi|lo] fp16 transposed weight (reused)
__device__ __half g_h2s[(size_t)N_NODES * F1];      // fp16 hi activations (A operand, layers 2-3)
__device__ float g_base[(size_t)N_NODES * F1];
__device__ float g_t   [(size_t)N_NODES * F1];
__device__ float g_dinv[N_NODES];
__device__ float g_preL[3 * F1];
__device__ float g_preR[11 * F1];
__device__ float g_preC[3 * 256 * F1];
// CSR
__device__ int   g_degi[N_NODES];
__device__ int   g_rp[N_NODES + 1];
__device__ int   g_cursor[N_NODES];
__device__ int   g_csrc[N_EDGES];
__device__ float g_cw[N_EDGES];

// ======================= PTX helpers (portable, sm_80+) =======================
__device__ __forceinline__ uint32_t smem_u32(const void* p) {
    uint32_t a;
    asm("{ .reg .u64 t; cvta.to.shared.u64 t, %1; cvt.u32.u64 %0, t; }" : "=r"(a) : "l"(p));
    return a;
}
__device__ __forceinline__ void cp16(uint32_t dst, const void* src, bool pred) {
    int sz = pred ? 16 : 0;
    asm volatile("cp.async.cg.shared.global [%0], [%1], 16, %2;"
                 :: "r"(dst), "l"(src), "r"(sz) : "memory");
}
#define CP_COMMIT() asm volatile("cp.async.commit_group;" ::: "memory")
#define CP_WAIT2()  asm volatile("cp.async.wait_group 2;" ::: "memory")

__device__ __forceinline__ void ldsm_x4(uint32_t* r, uint32_t addr) {
    asm volatile("ldmatrix.sync.aligned.m8n8.x4.shared.b16 {%0,%1,%2,%3}, [%4];"
                 : "=r"(r[0]), "=r"(r[1]), "=r"(r[2]), "=r"(r[3]) : "r"(addr));
}
__device__ __forceinline__ void mma_f16(float* d, const uint32_t* a, const uint32_t* b) {
    asm volatile("mma.sync.aligned.m16n8k16.row.col.f32.f16.f16.f32 "
                 "{%0,%1,%2,%3}, {%4,%5,%6,%7}, {%8,%9}, {%0,%1,%2,%3};"
                 : "+f"(d[0]), "+f"(d[1]), "+f"(d[2]), "+f"(d[3])
                 : "r"(a[0]), "r"(a[1]), "r"(a[2]), "r"(a[3]), "r"(b[0]), "r"(b[1]));
}
__device__ __forceinline__ uint32_t swz(uint32_t off) { return off ^ ((off >> 3) & 0x70); }

// ======================= prep kernels =======================
__global__ void zero_both() {
    int i = blockIdx.x * blockDim.x + threadIdx.x;
    if (i < N_NODES) { g_dinv[i] = 0.f; g_degi[i] = 0; }
}
__global__ void deg_kernel(const int* __restrict__ ei, const float* __restrict__ ea) {
    int e = blockIdx.x * blockDim.x + threadIdx.x;
    if (e < N_EDGES) {
        int dst = ei[N_EDGES + e];
        atomicAdd(&g_dinv[dst], ea[e]);
        atomicAdd(&g_degi[dst], 1);
    }
}
__global__ void scan_kernel() {
    __shared__ int sh[1024];
    const int CH = (N_NODES + 1023) / 1024;
    int tid = threadIdx.x;
    int base = tid * CH;
    int s = 0;
    for (int j = 0; j < CH; j++) {
        int i = base + j;
        if (i < N_NODES) {
            g_dinv[i] = rsqrtf(g_dinv[i] + 1.0f);
            s += g_degi[i];
        }
    }
    sh[tid] = s;
    __syncthreads();
    for (int off = 1; off < 1024; off <<= 1) {
        int v = (tid >= off) ? sh[tid - off] : 0;
        __syncthreads();
        sh[tid] += v;
        __syncthreads();
    }
    int run = tid ? sh[tid - 1] : 0;
    for (int j = 0; j < CH; j++) {
        int i = base + j;
        if (i < N_NODES) {
            g_rp[i] = run;
            g_cursor[i] = run;
            run += g_degi[i];
        }
    }
    if (tid == 1023) g_rp[N_NODES] = sh[1023];
}
__global__ void scatter_kernel(const int* __restrict__ ei, const float* __restrict__ ea) {
    int e = blockIdx.x * blockDim.x + threadIdx.x;
    if (e >= N_EDGES) return;
    int src = ei[e];
    int dst = ei[N_EDGES + e];
    float w = g_dinv[src] * ea[e] * g_dinv[dst];
    int pos = atomicAdd(&g_cursor[dst], 1);
    g_csrc[pos] = src;
    g_cw[pos] = w;
}

// fused: all table @ W1 precomputations. blocks 0-2: layer, 3-13: rel, 14-781: color
__global__ void pre_all(const float* __restrict__ layer_table, const float* __restrict__ rel_table,
                        const float* __restrict__ color_table, const float* __restrict__ W1) {
    __shared__ float s[256];
    int b = blockIdx.x, j = threadIdx.x;
    const float* tab;
    float* outp;
    int Kt, off;
    if (b < 3)       { tab = layer_table + (size_t)b * 250;        outp = g_preL + (size_t)b * F1;        Kt = 250; off = 0; }
    else if (b < 14) { tab = rel_table + (size_t)(b - 3) * 250;    outp = g_preR + (size_t)(b - 3) * F1;  Kt = 250; off = 1250; }
    else {
        int q = b - 14;
        int p = q >> 8, c = q & 255;
        tab = color_table + (size_t)c * 85;
        outp = g_preC + (size_t)q * F1;
        Kt = 85; off = 1500 + 85 * p;
    }
    if (j < Kt) s[j] = tab[j];
    __syncthreads();
    float acc = 0.f;
    for (int k = 0; k < Kt; k++) acc = fmaf(s[k], W1[(size_t)(off + k) * F1 + j], acc);
    outp[j] = acc;
}

// fused: resnet -> fp16 hi + node base. one block (256 thr) per node.
__global__ void split_base(const float* __restrict__ x) {
    int i = blockIdx.x;
    const float* xr = x + (size_t)i * XCOLS;
    __half* a = g_A2 + (size_t)i * KP1;
    for (int k = threadIdx.x; k < KP1; k += blockDim.x) {
        float v = (k < FS) ? xr[1 + k] : 0.f;
        a[k] = __float2half(v);
    }
    int j = threadIdx.x;
    if (j < 128) {
        int li = (int)xr[0] - 1;
        int ri = __float2int_rn(fabsf(xr[FS + 1]) * 10.0f);
        int c0 = (int)xr[XCOLS - 3];
        int c1 = (int)xr[XCOLS - 2];
        int c2 = (int)xr[XCOLS - 1];
        float4 pa = ((const float4*)(g_preL + (size_t)li * F1))[j];
        float4 pb = ((const float4*)(g_preR + (size_t)ri * F1))[j];
        float4 u = ((const float4*)(g_preC + ((size_t)(0 * 256 + c0)) * F1))[j];
        float4 v = ((const float4*)(g_preC + ((size_t)(1 * 256 + c1)) * F1))[j];
        float4 w = ((const float4*)(g_preC + ((size_t)(2 * 256 + c2)) * F1))[j];
        ((float4*)(g_base + (size_t)i * F1))[j] =
            make_float4(pa.x + pb.x + u.x + v.x + w.x, pa.y + pb.y + u.y + v.y + w.y,
                        pa.z + pb.z + u.z + v.z + w.z, pa.w + pb.w + u.w + v.w + w.w);
    }
}

// W[K,Nn] rows [roff, roff+Ksrc) -> g_WT[Nn][2*Kp] fp16 [hi|lo] transposed
__global__ void splitT_kernel(const float* __restrict__ W, int Nn, int Kp, int Ksrc, int roff) {
    int idx = blockIdx.x * blockDim.x + threadIdx.x;
    if (idx >= Nn * Kp) return;
    int n = idx / Kp, k = idx % Kp;
    float v = (k < Ksrc) ? W[(size_t)(roff + k) * Nn + n] : 0.f;
    __half h = __float2half(v);
    __half* b = g_WT + (size_t)n * 2 * Kp;
    b[k]      = h;
    b[Kp + k] = __float2half(v - __half2float(h));
}

// ======================= mma.sync fp16 GEMM (3-stage) =======================
// Logical blocks over Keff=2*Kp: A = [Ah|Ah] (stored hi, stride Kp), B = [Bh|Bl] (stride 2Kp).
template<int BN>
__device__ __forceinline__ void load_stage(const __half* __restrict__ A,
                                           const __half* __restrict__ B,
                                           int bm, int bn, int Kp,
                                           int kA, int kB, int M,
                                           uint32_t sA, uint32_t sB) {
    int t = threadIdx.x;
#pragma unroll
    for (int i = 0; i < 4; i++) {
        int idx = t + i * 256;
        int row = idx >> 3, seg = idx & 7;
        int gr = bm + row;
        bool p = gr < M;
        const void* src = A + (size_t)(p ? gr : 0) * Kp + kA + seg * 8;
        cp16(sA + swz(row * 128 + seg * 16), src, p);
    }
#pragma unroll
    for (int i = 0; i < BN * 8 / 256; i++) {
        int idx = t + i * 256;
        int row = idx >> 3, seg = idx & 7;
        const void* src = B + (size_t)(bn + row) * 2 * Kp + kB + seg * 8;
        cp16(sB + swz(row * 128 + seg * 16), src, true);
    }
}

template<int BN, bool ADD_BASE>
__global__ __launch_bounds__(256) void mma_gemm(const __half* __restrict__ A,
                                                const __half* __restrict__ B,
                                                const float* __restrict__ base,
                                                float* __restrict__ C,
                                                int M, int Kp, int Nn) {
    extern __shared__ char smem[];
    constexpr int WN = BN / 2;
    constexpr int SS = (128 + BN) * 128;     // bytes per stage
    uint32_t sb = smem_u32(smem);
    int tid = threadIdx.x, wid = tid >> 5, lane = tid & 31;
    int bm = blockIdx.y * 128, bn = blockIdx.x * BN;
    int wm = (wid & 3) * 32;
    int wn = (wid >> 2) * WN;

    float acc[2][WN / 8][4];
#pragma unroll
    for (int i = 0; i < 2; i++)
#pragma unroll
        for (int j = 0; j < WN / 8; j++)
#pragma unroll
            for (int q = 0; q < 4; q++) acc[i][j][q] = 0.f;

    int nT = (2 * Kp) >> 6;
    // prologue: stages 0,1
#pragma unroll
    for (int s = 0; s < 2; s++) {
        int k0 = s * 64;
        int kA = (k0 < Kp) ? k0 : k0 - Kp;   // A = [hi|hi]
        uint32_t sp = sb + (uint32_t)s * SS;
        load_stage<BN>(A, B, bm, bn, Kp, kA, k0, M, sp, sp + 128 * 128);
        CP_COMMIT();
    }

    for (int t = 0; t < nT; t++) {
        if (t + 2 < nT) {
            int k0 = (t + 2) * 64;
            int kA = (k0 < Kp) ? k0 : k0 - Kp;
            uint32_t sp = sb + (uint32_t)((t + 2) % 3) * SS;
            load_stage<BN>(A, B, bm, bn, Kp, kA, k0, M, sp, sp + 128 * 128);
        }
        CP_COMMIT();
        CP_WAIT2();
        __syncthreads();

        uint32_t sA = sb + (uint32_t)(t % 3) * SS;
        uint32_t sB = sA + 128 * 128;
#pragma unroll
        for (int ks = 0; ks < 4; ks++) {
            uint32_t af[2][4];
#pragma unroll
            for (int mi = 0; mi < 2; mi++) {
                int row = wm + mi * 16 + (lane & 15);
                ldsm_x4(af[mi], sA + swz(row * 128 + ks * 32 + ((lane >> 4) << 4)));
            }
#pragma unroll
            for (int nj = 0; nj < WN / 16; nj++) {
                uint32_t bf[4];
                int row = wn + nj * 16 + (lane & 7) + ((lane >> 4) << 3);
                ldsm_x4(bf, sB + swz(row * 128 + ks * 32 + (((lane >> 3) & 1) << 4)));
                mma_f16(acc[0][2 * nj],     af[0], bf);
                mma_f16(acc[0][2 * nj + 1], af[0], bf + 2);
                mma_f16(acc[1][2 * nj],     af[1], bf);
                mma_f16(acc[1][2 * nj + 1], af[1], bf + 2);
            }
        }
        __syncthreads();
    }

#pragma unroll
    for (int mi = 0; mi < 2; mi++) {
#pragma unroll
        for (int nj = 0; nj < WN / 8; nj++) {
            int row = bm + wm + mi * 16 + (lane >> 2);
            int col = bn + wn + nj * 8 + (lane & 3) * 2;
#pragma unroll
            for (int h = 0; h < 2; h++) {
                int r = row + h * 8;
                if (r < M) {
                    float2 v = make_float2(acc[mi][nj][h * 2], acc[mi][nj][h * 2 + 1]);
                    if (ADD_BASE) {
                        float2 b2 = *(const float2*)(base + (size_t)r * Nn + col);
                        v.x += b2.x; v.y += b2.y;
                    }
                    *(float2*)(C + (size_t)r * Nn + col) = v;
                }
            }
        }
    }
}

// ======================= fused CSR aggregation =======================
// h_out[n] = leakyrelu( sum_in t[src]*w + t[n]*dinv^2 + bias )
// SPLIT: write fp16 hi row (next GEMM A operand). PROJ: fuse final 64->3 projection.
template<int F, int NPB, bool SPLIT, bool PROJ>
__global__ __launch_bounds__(128) void csr_agg(const float* __restrict__ t,
                                               const float* __restrict__ b,
                                               __half* __restrict__ hs,
                                               const float* __restrict__ Wp,
                                               const float* __restrict__ bp,
                                               float* __restrict__ out) {
    constexpr int C = F / 4;
    int node = blockIdx.x * NPB + threadIdx.x / C;
    int ch = threadIdx.x % C;
    if (node >= N_NODES) return;
    int beg = g_rp[node], end = g_rp[node + 1];
    const float4* tv = (const float4*)t;
    float d = g_dinv[node];
    float dd = d * d;
    float4 self = tv[(size_t)node * C + ch];
    float4 bv = ((const float4*)b)[ch];
    float4 acc = make_float4(fmaf(self.x, dd, bv.x), fmaf(self.y, dd, bv.y),
                             fmaf(self.z, dd, bv.z), fmaf(self.w, dd, bv.w));
    int i = beg;
    for (; i + 4 <= end; i += 4) {
        int s0 = g_csrc[i], s1 = g_csrc[i + 1], s2 = g_csrc[i + 2], s3 = g_csrc[i + 3];
        float w0 = g_cw[i], w1 = g_cw[i + 1], w2 = g_cw[i + 2], w3 = g_cw[i + 3];
        float4 v0 = tv[(size_t)s0 * C + ch];
        float4 v1 = tv[(size_t)s1 * C + ch];
        float4 v2 = tv[(size_t)s2 * C + ch];
        float4 v3 = tv[(size_t)s3 * C + ch];
        acc.x += v0.x * w0 + v1.x * w1 + v2.x * w2 + v3.x * w3;
        acc.y += v0.y * w0 + v1.y * w1 + v2.y * w2 + v3.y * w3;
        acc.z += v0.z * w0 + v1.z * w1 + v2.z * w2 + v3.z * w3;
        acc.w += v0.w * w0 + v1.w * w1 + v2.w * w2 + v3.w * w3;
    }
    for (; i < end; i++) {
        int s0 = g_csrc[i];
        float w0 = g_cw[i];
        float4 v0 = tv[(size_t)s0 * C + ch];
        acc.x += v0.x * w0; acc.y += v0.y * w0; acc.z += v0.z * w0; acc.w += v0.w * w0;
    }
    float f[4] = {acc.x, acc.y, acc.z, acc.w};
#pragma unroll
    for (int q = 0; q < 4; q++) f[q] = f[q] > 0.f ? f[q] : 0.01f * f[q];
    if (SPLIT) {
        __half h[4];
#pragma unroll
        for (int q = 0; q < 4; q++) h[q] = __float2half(f[q]);
        *(uint2*)(hs + (size_t)node * F + ch * 4) = *(uint2*)h;
    }
    if (PROJ) {
        float a0 = 0.f, a1 = 0.f, a2 = 0.f;
#pragma unroll
        for (int q = 0; q < 4; q++) {
            int k = ch * 4 + q;
            a0 = fmaf(f[q], __ldg(Wp + k * 3 + 0), a0);
            a1 = fmaf(f[q], __ldg(Wp + k * 3 + 1), a1);
            a2 = fmaf(f[q], __ldg(Wp + k * 3 + 2), a2);
        }
#pragma unroll
        for (int off = C / 2; off; off >>= 1) {
            a0 += __shfl_down_sync(0xffffffffu, a0, off, C);
            a1 += __shfl_down_sync(0xffffffffu, a1, off, C);
            a2 += __shfl_down_sync(0xffffffffu, a2, off, C);
        }
        if (ch == 0) {
            out[(size_t)node * 3 + 0] = a0 + bp[0];
            out[(size_t)node * 3 + 1] = a1 + bp[1];
            out[(size_t)node * 3 + 2] = a2 + bp[2];
        }
    }
}

// ======================= launch =======================
extern "C" void kernel_launch(void* const* d_in, const int* in_sizes, int n_in,
                              void* d_out, int out_size) {
    const float* x           = (const float*)d_in[0];
    const int*   edge_index  = (const int*)  d_in[1];
    const float* edge_attr   = (const float*)d_in[2];
    const float* layer_table = (const float*)d_in[3];
    const float* rel_table   = (const float*)d_in[4];
    const float* color_table = (const float*)d_in[5];
    const float* W1 = (const float*)d_in[6];
    const float* b1 = (const float*)d_in[7];
    const float* W2 = (const float*)d_in[8];
    const float* b2 = (const float*)d_in[9];
    const float* W3 = (const float*)d_in[10];
    const float* b3 = (const float*)d_in[11];
    const float* Wp = (const float*)d_in[12];
    const float* bp = (const float*)d_in[13];
    float* out = (float*)d_out;

    __half *p_A2, *p_WT, *p_h2s;
    float *p_base, *p_t;
    cudaGetSymbolAddress((void**)&p_A2,   g_A2);
    cudaGetSymbolAddress((void**)&p_WT,   g_WT);
    cudaGetSymbolAddress((void**)&p_h2s,  g_h2s);
    cudaGetSymbolAddress((void**)&p_base, g_base);
    cudaGetSymbolAddress((void**)&p_t,    g_t);

    const int T = 256;
    const int SM128 = 3 * (128 + 128) * 128;   // 98304
    const int SM64  = 3 * (128 + 64) * 128;    // 73728
    cudaFuncSetAttribute(mma_gemm<128, true>,  cudaFuncAttributeMaxDynamicSharedMemorySize, SM128);
    cudaFuncSetAttribute(mma_gemm<128, false>, cudaFuncAttributeMaxDynamicSharedMemorySize, SM128);
    cudaFuncSetAttribute(mma_gemm<64,  false>, cudaFuncAttributeMaxDynamicSharedMemorySize, SM64);

    // graph prep
    zero_both<<<(N_NODES + T - 1) / T, T>>>();
    deg_kernel<<<(N_EDGES + T - 1) / T, T>>>(edge_index, edge_attr);
    scan_kernel<<<1, 1024>>>();
    scatter_kernel<<<(N_EDGES + T - 1) / T, T>>>(edge_index, edge_attr);

    // GEMM1 inputs
    pre_all<<<782, 512>>>(layer_table, rel_table, color_table, W1);
    splitT_kernel<<<(F1 * KP1 + T - 1) / T, T>>>(W1, F1, KP1, FS, 250);
    split_base<<<N_NODES, T>>>(x);

    const int MT = (N_NODES + 127) / 128;   // 157

    // ---- layer 1 ----
    mma_gemm<128, true><<<dim3(F1 / 128, MT), T, SM128>>>(p_A2, p_WT, p_base, p_t, N_NODES, KP1, F1);
    csr_agg<F1, 1, true, false><<<N_NODES, 128>>>(p_t, b1, p_h2s, nullptr, nullptr, nullptr);

    // ---- layer 2 ----
    splitT_kernel<<<(F2 * F1 + T - 1) / T, T>>>(W2, F2, F1, F1, 0);
    mma_gemm<128, false><<<dim3(F2 / 128, MT), T, SM128>>>(p_h2s, p_WT, nullptr, p_t, N_NODES, F1, F2);
    csr_agg<F2, 2, true, false><<<(N_NODES + 1) / 2, 128>>>(p_t, b2, p_h2s, nullptr, nullptr, nullptr);

    // ---- layer 3 (projection fused) ----
    splitT_kernel<<<(F3 * F2 + T - 1) / T, T>>>(W3, F3, F2, F2, 0);
    mma_gemm<64, false><<<dim3(F3 / 64, MT), T, SM64>>>(p_h2s, p_WT, nullptr, p_t, N_NODES, F2, F3);
    csr_agg<F3, 8, false, true><<<(N_NODES + 7) / 8, 128>>>(p_t, b3, nullptr, Wp, bp, out);
}

// round 9
// speedup vs baseline: 4.6059x; 1.3313x over previous
#include <cuda_runtime.h>
#include <cuda_fp16.h>
#include <math.h>
#include <stdint.h>

#define N_NODES 20000
#define N_EDGES 320000
#define FS      1000
#define XCOLS   1005
#define F1      512
#define F2      256
#define F3      64
#define KP1     1024             // padded resnet K

// ======================= static scratch =======================
__device__ __half g_A2 [(size_t)N_NODES * KP1];     // fp16 resnet (A operand, layer1)
__device__ __half g_h2s[(size_t)N_NODES * F1];      // fp16 activations (A operand, layers 2-3)
__device__ __half g_W1T[(size_t)F1 * KP1];          // fp16 transposed weights
__device__ __half g_W2T[(size_t)F2 * F1];
__device__ __half g_W3T[(size_t)F3 * F2];
__device__ float g_base[(size_t)N_NODES * F1];
__device__ float g_t   [(size_t)N_NODES * F1];
__device__ float g_dinv[N_NODES];
__device__ float g_preL[3 * F1];
__device__ float g_preR[11 * F1];
__device__ float g_preC[3 * 256 * F1];
// CSR
__device__ int   g_degi[N_NODES];
__device__ int   g_rp[N_NODES + 1];
__device__ int   g_cursor[N_NODES];
__device__ int   g_csrc[N_EDGES];
__device__ float g_cw[N_EDGES];

// ======================= PTX helpers (portable, sm_80+) =======================
__device__ __forceinline__ uint32_t smem_u32(const void* p) {
    uint32_t a;
    asm("{ .reg .u64 t; cvta.to.shared.u64 t, %1; cvt.u32.u64 %0, t; }" : "=r"(a) : "l"(p));
    return a;
}
__device__ __forceinline__ void cp16(uint32_t dst, const void* src, bool pred) {
    int sz = pred ? 16 : 0;
    asm volatile("cp.async.cg.shared.global [%0], [%1], 16, %2;"
                 :: "r"(dst), "l"(src), "r"(sz) : "memory");
}
#define CP_COMMIT() asm volatile("cp.async.commit_group;" ::: "memory")
#define CP_WAIT2()  asm volatile("cp.async.wait_group 2;" ::: "memory")

__device__ __forceinline__ void ldsm_x4(uint32_t* r, uint32_t addr) {
    asm volatile("ldmatrix.sync.aligned.m8n8.x4.shared.b16 {%0,%1,%2,%3}, [%4];"
                 : "=r"(r[0]), "=r"(r[1]), "=r"(r[2]), "=r"(r[3]) : "r"(addr));
}
__device__ __forceinline__ void mma_f16(float* d, const uint32_t* a, const uint32_t* b) {
    asm volatile("mma.sync.aligned.m16n8k16.row.col.f32.f16.f16.f32 "
                 "{%0,%1,%2,%3}, {%4,%5,%6,%7}, {%8,%9}, {%0,%1,%2,%3};"
                 : "+f"(d[0]), "+f"(d[1]), "+f"(d[2]), "+f"(d[3])
                 : "r"(a[0]), "r"(a[1]), "r"(a[2]), "r"(a[3]), "r"(b[0]), "r"(b[1]));
}
__device__ __forceinline__ uint32_t swz(uint32_t off) { return off ^ ((off >> 3) & 0x70); }

// ======================= prep kernels =======================
__global__ void zero_both() {
    int i = blockIdx.x * blockDim.x + threadIdx.x;
    if (i < N_NODES) { g_dinv[i] = 0.f; g_degi[i] = 0; }
}
__global__ void deg_kernel(const int* __restrict__ ei, const float* __restrict__ ea) {
    int e = blockIdx.x * blockDim.x + threadIdx.x;
    if (e < N_EDGES) {
        int dst = ei[N_EDGES + e];
        atomicAdd(&g_dinv[dst], ea[e]);
        atomicAdd(&g_degi[dst], 1);
    }
}
__global__ void scan_kernel() {
    __shared__ int sh[1024];
    const int CH = (N_NODES + 1023) / 1024;
    int tid = threadIdx.x;
    int base = tid * CH;
    int s = 0;
    for (int j = 0; j < CH; j++) {
        int i = base + j;
        if (i < N_NODES) {
            g_dinv[i] = rsqrtf(g_dinv[i] + 1.0f);
            s += g_degi[i];
        }
    }
    sh[tid] = s;
    __syncthreads();
    for (int off = 1; off < 1024; off <<= 1) {
        int v = (tid >= off) ? sh[tid - off] : 0;
        __syncthreads();
        sh[tid] += v;
        __syncthreads();
    }
    int run = tid ? sh[tid - 1] : 0;
    for (int j = 0; j < CH; j++) {
        int i = base + j;
        if (i < N_NODES) {
            g_rp[i] = run;
            g_cursor[i] = run;
            run += g_degi[i];
        }
    }
    if (tid == 1023) g_rp[N_NODES] = sh[1023];
}
__global__ void scatter_kernel(const int* __restrict__ ei, const float* __restrict__ ea) {
    int e = blockIdx.x * blockDim.x + threadIdx.x;
    if (e >= N_EDGES) return;
    int src = ei[e];
    int dst = ei[N_EDGES + e];
    float w = g_dinv[src] * ea[e] * g_dinv[dst];
    int pos = atomicAdd(&g_cursor[dst], 1);
    g_csrc[pos] = src;
    g_cw[pos] = w;
}

// fused: all table @ W1 precomputations. blocks 0-2: layer, 3-13: rel, 14-781: color
__global__ void pre_all(const float* __restrict__ layer_table, const float* __restrict__ rel_table,
                        const float* __restrict__ color_table, const float* __restrict__ W1) {
    __shared__ float s[256];
    int b = blockIdx.x, j = threadIdx.x;
    const float* tab;
    float* outp;
    int Kt, off;
    if (b < 3)       { tab = layer_table + (size_t)b * 250;        outp = g_preL + (size_t)b * F1;        Kt = 250; off = 0; }
    else if (b < 14) { tab = rel_table + (size_t)(b - 3) * 250;    outp = g_preR + (size_t)(b - 3) * F1;  Kt = 250; off = 1250; }
    else {
        int q = b - 14;
        int p = q >> 8, c = q & 255;
        tab = color_table + (size_t)c * 85;
        outp = g_preC + (size_t)q * F1;
        Kt = 85; off = 1500 + 85 * p;
    }
    if (j < Kt) s[j] = tab[j];
    __syncthreads();
    float acc = 0.f;
    for (int k = 0; k < Kt; k++) acc = fmaf(s[k], W1[(size_t)(off + k) * F1 + j], acc);
    outp[j] = acc;
}

// fused: resnet -> fp16 + node base. one block (256 thr) per node.
__global__ void split_base(const float* __restrict__ x) {
    int i = blockIdx.x;
    const float* xr = x + (size_t)i * XCOLS;
    __half* a = g_A2 + (size_t)i * KP1;
    for (int k = threadIdx.x; k < KP1; k += blockDim.x) {
        float v = (k < FS) ? xr[1 + k] : 0.f;
        a[k] = __float2half(v);
    }
    int j = threadIdx.x;
    if (j < 128) {
        int li = (int)xr[0] - 1;
        int ri = __float2int_rn(fabsf(xr[FS + 1]) * 10.0f);
        int c0 = (int)xr[XCOLS - 3];
        int c1 = (int)xr[XCOLS - 2];
        int c2 = (int)xr[XCOLS - 1];
        float4 pa = ((const float4*)(g_preL + (size_t)li * F1))[j];
        float4 pb = ((const float4*)(g_preR + (size_t)ri * F1))[j];
        float4 u = ((const float4*)(g_preC + ((size_t)(0 * 256 + c0)) * F1))[j];
        float4 v = ((const float4*)(g_preC + ((size_t)(1 * 256 + c1)) * F1))[j];
        float4 w = ((const float4*)(g_preC + ((size_t)(2 * 256 + c2)) * F1))[j];
        ((float4*)(g_base + (size_t)i * F1))[j] =
            make_float4(pa.x + pb.x + u.x + v.x + w.x, pa.y + pb.y + u.y + v.y + w.y,
                        pa.z + pb.z + u.z + v.z + w.z, pa.w + pb.w + u.w + v.w + w.w);
    }
}

// one kernel: all three weight matrices -> fp16 transposed
#define W1N (F1 * KP1)
#define W2N (F2 * F1)
#define W3N (F3 * F2)
__global__ void convW(const float* __restrict__ W1, const float* __restrict__ W2,
                      const float* __restrict__ W3) {
    int idx = blockIdx.x * blockDim.x + threadIdx.x;
    if (idx < W1N) {
        int n = idx / KP1, k = idx % KP1;
        float v = (k < FS) ? W1[(size_t)(250 + k) * F1 + n] : 0.f;
        g_W1T[idx] = __float2half(v);
    } else if (idx < W1N + W2N) {
        int q = idx - W1N;
        int n = q / F1, k = q % F1;
        g_W2T[q] = __float2half(W2[(size_t)k * F2 + n]);
    } else if (idx < W1N + W2N + W3N) {
        int q = idx - W1N - W2N;
        int n = q / F2, k = q % F2;
        g_W3T[q] = __float2half(W3[(size_t)k * F3 + n]);
    }
}

// ======================= mma.sync fp16 GEMM (3-stage) =======================
// C[M,Nn] = A[M,Kp] @ B[Nn,Kp]^T (+ base). CTA 128 x BN, BK=64, 256 thr, 8 warps.
template<int BN>
__device__ __forceinline__ void load_stage(const __half* __restrict__ A,
                                           const __half* __restrict__ B,
                                           int bm, int bn, int Kp, int k0, int M,
                                           uint32_t sA, uint32_t sB) {
    int t = threadIdx.x;
#pragma unroll
    for (int i = 0; i < 4; i++) {
        int idx = t + i * 256;
        int row = idx >> 3, seg = idx & 7;
        int gr = bm + row;
        bool p = gr < M;
        const void* src = A + (size_t)(p ? gr : 0) * Kp + k0 + seg * 8;
        cp16(sA + swz(row * 128 + seg * 16), src, p);
    }
#pragma unroll
    for (int i = 0; i < BN * 8 / 256; i++) {
        int idx = t + i * 256;
        int row = idx >> 3, seg = idx & 7;
        const void* src = B + (size_t)(bn + row) * Kp + k0 + seg * 8;
        cp16(sB + swz(row * 128 + seg * 16), src, true);
    }
}

template<int BN, bool ADD_BASE>
__global__ __launch_bounds__(256) void mma_gemm(const __half* __restrict__ A,
                                                const __half* __restrict__ B,
                                                const float* __restrict__ base,
                                                float* __restrict__ C,
                                                int M, int Kp, int Nn) {
    extern __shared__ char smem[];
    constexpr int WN = BN / 2;
    constexpr int SS = (128 + BN) * 128;     // bytes per stage
    uint32_t sb = smem_u32(smem);
    int tid = threadIdx.x, wid = tid >> 5, lane = tid & 31;
    int bm = blockIdx.y * 128, bn = blockIdx.x * BN;
    int wm = (wid & 3) * 32;
    int wn = (wid >> 2) * WN;

    float acc[2][WN / 8][4];
#pragma unroll
    for (int i = 0; i < 2; i++)
#pragma unroll
        for (int j = 0; j < WN / 8; j++)
#pragma unroll
            for (int q = 0; q < 4; q++) acc[i][j][q] = 0.f;

    int nT = Kp >> 6;
    // prologue: stages 0,1
#pragma unroll
    for (int s = 0; s < 2; s++) {
        uint32_t sp = sb + (uint32_t)s * SS;
        load_stage<BN>(A, B, bm, bn, Kp, s * 64, M, sp, sp + 128 * 128);
        CP_COMMIT();
    }

    for (int t = 0; t < nT; t++) {
        if (t + 2 < nT) {
            uint32_t sp = sb + (uint32_t)((t + 2) % 3) * SS;
            load_stage<BN>(A, B, bm, bn, Kp, (t + 2) * 64, M, sp, sp + 128 * 128);
        }
        CP_COMMIT();
        CP_WAIT2();
        __syncthreads();

        uint32_t sA = sb + (uint32_t)(t % 3) * SS;
        uint32_t sB = sA + 128 * 128;
#pragma unroll
        for (int ks = 0; ks < 4; ks++) {
            uint32_t af[2][4];
#pragma unroll
            for (int mi = 0; mi < 2; mi++) {
                int row = wm + mi * 16 + (lane & 15);
                ldsm_x4(af[mi], sA + swz(row * 128 + ks * 32 + ((lane >> 4) << 4)));
            }
#pragma unroll
            for (int nj = 0; nj < WN / 16; nj++) {
                uint32_t bf[4];
                int row = wn + nj * 16 + (lane & 7) + ((lane >> 4) << 3);
                ldsm_x4(bf, sB + swz(row * 128 + ks * 32 + (((lane >> 3) & 1) << 4)));
                mma_f16(acc[0][2 * nj],     af[0], bf);
                mma_f16(acc[0][2 * nj + 1], af[0], bf + 2);
                mma_f16(acc[1][2 * nj],     af[1], bf);
                mma_f16(acc[1][2 * nj + 1], af[1], bf + 2);
            }
        }
        __syncthreads();
    }

#pragma unroll
    for (int mi = 0; mi < 2; mi++) {
#pragma unroll
        for (int nj = 0; nj < WN / 8; nj++) {
            int row = bm + wm + mi * 16 + (lane >> 2);
            int col = bn + wn + nj * 8 + (lane & 3) * 2;
#pragma unroll
            for (int h = 0; h < 2; h++) {
                int r = row + h * 8;
                if (r < M) {
                    float2 v = make_float2(acc[mi][nj][h * 2], acc[mi][nj][h * 2 + 1]);
                    if (ADD_BASE) {
                        float2 b2 = *(const float2*)(base + (size_t)r * Nn + col);
                        v.x += b2.x; v.y += b2.y;
                    }
                    *(float2*)(C + (size_t)r * Nn + col) = v;
                }
            }
        }
    }
}

// ======================= fused CSR aggregation =======================
// h_out[n] = leakyrelu( sum_in t[src]*w + t[n]*dinv^2 + bias )
// SPLIT: write fp16 row (next GEMM A operand). PROJ: fuse final 64->3 projection.
template<int F, int NPB, bool SPLIT, bool PROJ>
__global__ __launch_bounds__(128) void csr_agg(const float* __restrict__ t,
                                               const float* __restrict__ b,
                                               __half* __restrict__ hs,
                                               const float* __restrict__ Wp,
                                               const float* __restrict__ bp,
                                               float* __restrict__ out) {
    constexpr int C = F / 4;
    int node = blockIdx.x * NPB + threadIdx.x / C;
    int ch = threadIdx.x % C;
    if (node >= N_NODES) return;
    int beg = g_rp[node], end = g_rp[node + 1];
    const float4* tv = (const float4*)t;
    float d = g_dinv[node];
    float dd = d * d;
    float4 self = tv[(size_t)node * C + ch];
    float4 bv = ((const float4*)b)[ch];
    float4 acc = make_float4(fmaf(self.x, dd, bv.x), fmaf(self.y, dd, bv.y),
                             fmaf(self.z, dd, bv.z), fmaf(self.w, dd, bv.w));
    int i = beg;
    for (; i + 4 <= end; i += 4) {
        int s0 = g_csrc[i], s1 = g_csrc[i + 1], s2 = g_csrc[i + 2], s3 = g_csrc[i + 3];
        float w0 = g_cw[i], w1 = g_cw[i + 1], w2 = g_cw[i + 2], w3 = g_cw[i + 3];
        float4 v0 = tv[(size_t)s0 * C + ch];
        float4 v1 = tv[(size_t)s1 * C + ch];
        float4 v2 = tv[(size_t)s2 * C + ch];
        float4 v3 = tv[(size_t)s3 * C + ch];
        acc.x += v0.x * w0 + v1.x * w1 + v2.x * w2 + v3.x * w3;
        acc.y += v0.y * w0 + v1.y * w1 + v2.y * w2 + v3.y * w3;
        acc.z += v0.z * w0 + v1.z * w1 + v2.z * w2 + v3.z * w3;
        acc.w += v0.w * w0 + v1.w * w1 + v2.w * w2 + v3.w * w3;
    }
    for (; i < end; i++) {
        int s0 = g_csrc[i];
        float w0 = g_cw[i];
        float4 v0 = tv[(size_t)s0 * C + ch];
        acc.x += v0.x * w0; acc.y += v0.y * w0; acc.z += v0.z * w0; acc.w += v0.w * w0;
    }
    float f[4] = {acc.x, acc.y, acc.z, acc.w};
#pragma unroll
    for (int q = 0; q < 4; q++) f[q] = f[q] > 0.f ? f[q] : 0.01f * f[q];
    if (SPLIT) {
        __half h[4];
#pragma unroll
        for (int q = 0; q < 4; q++) h[q] = __float2half(f[q]);
        *(uint2*)(hs + (size_t)node * F + ch * 4) = *(uint2*)h;
    }
    if (PROJ) {
        float a0 = 0.f, a1 = 0.f, a2 = 0.f;
#pragma unroll
        for (int q = 0; q < 4; q++) {
            int k = ch * 4 + q;
            a0 = fmaf(f[q], __ldg(Wp + k * 3 + 0), a0);
            a1 = fmaf(f[q], __ldg(Wp + k * 3 + 1), a1);
            a2 = fmaf(f[q], __ldg(Wp + k * 3 + 2), a2);
        }
#pragma unroll
        for (int off = C / 2; off; off >>= 1) {
            a0 += __shfl_down_sync(0xffffffffu, a0, off, C);
            a1 += __shfl_down_sync(0xffffffffu, a1, off, C);
            a2 += __shfl_down_sync(0xffffffffu, a2, off, C);
        }
        if (ch == 0) {
            out[(size_t)node * 3 + 0] = a0 + bp[0];
            out[(size_t)node * 3 + 1] = a1 + bp[1];
            out[(size_t)node * 3 + 2] = a2 + bp[2];
        }
    }
}

// ======================= launch =======================
extern "C" void kernel_launch(void* const* d_in, const int* in_sizes, int n_in,
                              void* d_out, int out_size) {
    const float* x           = (const float*)d_in[0];
    const int*   edge_index  = (const int*)  d_in[1];
    const float* edge_attr   = (const float*)d_in[2];
    const float* layer_table = (const float*)d_in[3];
    const float* rel_table   = (const float*)d_in[4];
    const float* color_table = (const float*)d_in[5];
    const float* W1 = (const float*)d_in[6];
    const float* b1 = (const float*)d_in[7];
    const float* W2 = (const float*)d_in[8];
    const float* b2 = (const float*)d_in[9];
    const float* W3 = (const float*)d_in[10];
    const float* b3 = (const float*)d_in[11];
    const float* Wp = (const float*)d_in[12];
    const float* bp = (const float*)d_in[13];
    float* out = (float*)d_out;

    __half *p_A2, *p_h2s, *p_W1T, *p_W2T, *p_W3T;
    float *p_base, *p_t;
    cudaGetSymbolAddress((void**)&p_A2,   g_A2);
    cudaGetSymbolAddress((void**)&p_h2s,  g_h2s);
    cudaGetSymbolAddress((void**)&p_W1T,  g_W1T);
    cudaGetSymbolAddress((void**)&p_W2T,  g_W2T);
    cudaGetSymbolAddress((void**)&p_W3T,  g_W3T);
    cudaGetSymbolAddress((void**)&p_base, g_base);
    cudaGetSymbolAddress((void**)&p_t,    g_t);

    const int T = 256;
    const int SM128 = 3 * (128 + 128) * 128;   // 98304
    const int SM64  = 3 * (128 + 64) * 128;    // 73728
    cudaFuncSetAttribute(mma_gemm<128, true>,  cudaFuncAttributeMaxDynamicSharedMemorySize, SM128);
    cudaFuncSetAttribute(mma_gemm<128, false>, cudaFuncAttributeMaxDynamicSharedMemorySize, SM128);
    cudaFuncSetAttribute(mma_gemm<64,  false>, cudaFuncAttributeMaxDynamicSharedMemorySize, SM64);

    // graph prep
    zero_both<<<(N_NODES + T - 1) / T, T>>>();
    deg_kernel<<<(N_EDGES + T - 1) / T, T>>>(edge_index, edge_attr);
    scan_kernel<<<1, 1024>>>();
    scatter_kernel<<<(N_EDGES + T - 1) / T, T>>>(edge_index, edge_attr);

    // all weights -> fp16 transposed (single kernel)
    convW<<<(W1N + W2N + W3N + T - 1) / T, T>>>(W1, W2, W3);
    // table precomputations + node base + resnet fp16
    pre_all<<<782, 512>>>(layer_table, rel_table, color_table, W1);
    split_base<<<N_NODES, T>>>(x);

    const int MT = (N_NODES + 127) / 128;   // 157

    // ---- layer 1 ----
    mma_gemm<128, true><<<dim3(F1 / 128, MT), T, SM128>>>(p_A2, p_W1T, p_base, p_t, N_NODES, KP1, F1);
    csr_agg<F1, 1, true, false><<<N_NODES, 128>>>(p_t, b1, p_h2s, nullptr, nullptr, nullptr);

    // ---- layer 2 ----
    mma_gemm<128, false><<<dim3(F2 / 128, MT), T, SM128>>>(p_h2s, p_W2T, nullptr, p_t, N_NODES, F1, F2);
    csr_agg<F2, 2, true, false><<<(N_NODES + 1) / 2, 128>>>(p_t, b2, p_h2s, nullptr, nullptr, nullptr);

    // ---- layer 3 (projection fused) ----
    mma_gemm<64, false><<<dim3(F3 / 64, MT), T, SM64>>>(p_h2s, p_W3T, nullptr, p_t, N_NODES, F2, F3);
    csr_agg<F3, 8, false, true><<<(N_NODES + 7) / 8, 128>>>(p_t, b3, nullptr, Wp, bp, out);
}

// round 10
// speedup vs baseline: 4.8328x; 1.0493x over previous
#include <cuda_runtime.h>
#include <cuda_fp16.h>
#include <math.h>
#include <stdint.h>

#define N_NODES 20000
#define N_EDGES 320000
#define FS      1000
#define XCOLS   1005
#define F1      512
#define F2      256
#define F3      64
#define KP1     1024             // padded resnet K

// ======================= static scratch =======================
__device__ __half g_A2 [(size_t)N_NODES * KP1];     // fp16 resnet (A operand, layer1)
__device__ __half g_h2s[(size_t)N_NODES * F1];      // fp16 activations (A operand, layers 2-3)
__device__ __half g_W1T[(size_t)F1 * KP1];          // fp16 transposed weights
__device__ __half g_W2T[(size_t)F2 * F1];
__device__ __half g_W3T[(size_t)F3 * F2];
__device__ float g_base[(size_t)N_NODES * F1];
__device__ float g_t   [(size_t)N_NODES * F1];      // fp16 view for layers 1-2, fp32 for layer 3
__device__ float g_dinv[N_NODES];
__device__ float g_preL[3 * F1];
__device__ float g_preR[11 * F1];
__device__ float g_preC[3 * 256 * F1];
// CSR
__device__ int   g_degi[N_NODES];
__device__ int   g_rp[N_NODES + 1];
__device__ int   g_cursor[N_NODES];
__device__ int   g_csrc[N_EDGES];
__device__ float g_cw[N_EDGES];

// ======================= PTX helpers (portable, sm_80+) =======================
__device__ __forceinline__ uint32_t smem_u32(const void* p) {
    uint32_t a;
    asm("{ .reg .u64 t; cvta.to.shared.u64 t, %1; cvt.u32.u64 %0, t; }" : "=r"(a) : "l"(p));
    return a;
}
__device__ __forceinline__ void cp16(uint32_t dst, const void* src, bool pred) {
    int sz = pred ? 16 : 0;
    asm volatile("cp.async.cg.shared.global [%0], [%1], 16, %2;"
                 :: "r"(dst), "l"(src), "r"(sz) : "memory");
}
#define CP_COMMIT() asm volatile("cp.async.commit_group;" ::: "memory")
#define CP_WAIT2()  asm volatile("cp.async.wait_group 2;" ::: "memory")

__device__ __forceinline__ void ldsm_x4(uint32_t* r, uint32_t addr) {
    asm volatile("ldmatrix.sync.aligned.m8n8.x4.shared.b16 {%0,%1,%2,%3}, [%4];"
                 : "=r"(r[0]), "=r"(r[1]), "=r"(r[2]), "=r"(r[3]) : "r"(addr));
}
__device__ __forceinline__ void mma_f16(float* d, const uint32_t* a, const uint32_t* b) {
    asm volatile("mma.sync.aligned.m16n8k16.row.col.f32.f16.f16.f32 "
                 "{%0,%1,%2,%3}, {%4,%5,%6,%7}, {%8,%9}, {%0,%1,%2,%3};"
                 : "+f"(d[0]), "+f"(d[1]), "+f"(d[2]), "+f"(d[3])
                 : "r"(a[0]), "r"(a[1]), "r"(a[2]), "r"(a[3]), "r"(b[0]), "r"(b[1]));
}
__device__ __forceinline__ uint32_t swz(uint32_t off) { return off ^ ((off >> 3) & 0x70); }

// ======================= prep kernels =======================
__global__ void zero_both() {
    int i = blockIdx.x * blockDim.x + threadIdx.x;
    if (i < N_NODES) { g_dinv[i] = 0.f; g_degi[i] = 0; }
}
__global__ void deg_kernel(const int* __restrict__ ei, const float* __restrict__ ea) {
    int e = blockIdx.x * blockDim.x + threadIdx.x;
    if (e < N_EDGES) {
        int dst = ei[N_EDGES + e];
        atomicAdd(&g_dinv[dst], ea[e]);
        atomicAdd(&g_degi[dst], 1);
    }
}
__global__ void scan_kernel() {
    __shared__ int sh[1024];
    const int CH = (N_NODES + 1023) / 1024;
    int tid = threadIdx.x;
    int base = tid * CH;
    int s = 0;
    for (int j = 0; j < CH; j++) {
        int i = base + j;
        if (i < N_NODES) {
            g_dinv[i] = rsqrtf(g_dinv[i] + 1.0f);
            s += g_degi[i];
        }
    }
    sh[tid] = s;
    __syncthreads();
    for (int off = 1; off < 1024; off <<= 1) {
        int v = (tid >= off) ? sh[tid - off] : 0;
        __syncthreads();
        sh[tid] += v;
        __syncthreads();
    }
    int run = tid ? sh[tid - 1] : 0;
    for (int j = 0; j < CH; j++) {
        int i = base + j;
        if (i < N_NODES) {
            g_rp[i] = run;
            g_cursor[i] = run;
            run += g_degi[i];
        }
    }
    if (tid == 1023) g_rp[N_NODES] = sh[1023];
}
__global__ void scatter_kernel(const int* __restrict__ ei, const float* __restrict__ ea) {
    int e = blockIdx.x * blockDim.x + threadIdx.x;
    if (e >= N_EDGES) return;
    int src = ei[e];
    int dst = ei[N_EDGES + e];
    float w = g_dinv[src] * ea[e] * g_dinv[dst];
    int pos = atomicAdd(&g_cursor[dst], 1);
    g_csrc[pos] = src;
    g_cw[pos] = w;
}

// fused: all table @ W1 precomputations. blocks 0-2: layer, 3-13: rel, 14-781: color
__global__ void pre_all(const float* __restrict__ layer_table, const float* __restrict__ rel_table,
                        const float* __restrict__ color_table, const float* __restrict__ W1) {
    __shared__ float s[256];
    int b = blockIdx.x, j = threadIdx.x;
    const float* tab;
    float* outp;
    int Kt, off;
    if (b < 3)       { tab = layer_table + (size_t)b * 250;        outp = g_preL + (size_t)b * F1;        Kt = 250; off = 0; }
    else if (b < 14) { tab = rel_table + (size_t)(b - 3) * 250;    outp = g_preR + (size_t)(b - 3) * F1;  Kt = 250; off = 1250; }
    else {
        int q = b - 14;
        int p = q >> 8, c = q & 255;
        tab = color_table + (size_t)c * 85;
        outp = g_preC + (size_t)q * F1;
        Kt = 85; off = 1500 + 85 * p;
    }
    if (j < Kt) s[j] = tab[j];
    __syncthreads();
    float acc = 0.f;
    for (int k = 0; k < Kt; k++) acc = fmaf(s[k], W1[(size_t)(off + k) * F1 + j], acc);
    outp[j] = acc;
}

// fused: resnet -> fp16 + node base. one block (256 thr) per node.
__global__ void split_base(const float* __restrict__ x) {
    int i = blockIdx.x;
    const float* xr = x + (size_t)i * XCOLS;
    __half* a = g_A2 + (size_t)i * KP1;
    for (int k = threadIdx.x; k < KP1; k += blockDim.x) {
        float v = (k < FS) ? xr[1 + k] : 0.f;
        a[k] = __float2half(v);
    }
    int j = threadIdx.x;
    if (j < 128) {
        int li = (int)xr[0] - 1;
        int ri = __float2int_rn(fabsf(xr[FS + 1]) * 10.0f);
        int c0 = (int)xr[XCOLS - 3];
        int c1 = (int)xr[XCOLS - 2];
        int c2 = (int)xr[XCOLS - 1];
        float4 pa = ((const float4*)(g_preL + (size_t)li * F1))[j];
        float4 pb = ((const float4*)(g_preR + (size_t)ri * F1))[j];
        float4 u = ((const float4*)(g_preC + ((size_t)(0 * 256 + c0)) * F1))[j];
        float4 v = ((const float4*)(g_preC + ((size_t)(1 * 256 + c1)) * F1))[j];
        float4 w = ((const float4*)(g_preC + ((size_t)(2 * 256 + c2)) * F1))[j];
        ((float4*)(g_base + (size_t)i * F1))[j] =
            make_float4(pa.x + pb.x + u.x + v.x + w.x, pa.y + pb.y + u.y + v.y + w.y,
                        pa.z + pb.z + u.z + v.z + w.z, pa.w + pb.w + u.w + v.w + w.w);
    }
}

// one kernel: all three weight matrices -> fp16 transposed
#define W1N (F1 * KP1)
#define W2N (F2 * F1)
#define W3N (F3 * F2)
__global__ void convW(const float* __restrict__ W1, const float* __restrict__ W2,
                      const float* __restrict__ W3) {
    int idx = blockIdx.x * blockDim.x + threadIdx.x;
    if (idx < W1N) {
        int n = idx / KP1, k = idx % KP1;
        float v = (k < FS) ? W1[(size_t)(250 + k) * F1 + n] : 0.f;
        g_W1T[idx] = __float2half(v);
    } else if (idx < W1N + W2N) {
        int q = idx - W1N;
        int n = q / F1, k = q % F1;
        g_W2T[q] = __float2half(W2[(size_t)k * F2 + n]);
    } else if (idx < W1N + W2N + W3N) {
        int q = idx - W1N - W2N;
        int n = q / F2, k = q % F2;
        g_W3T[q] = __float2half(W3[(size_t)k * F3 + n]);
    }
}

// ======================= mma.sync fp16 GEMM (3-stage) =======================
// C[M,Nn] = A[M,Kp] @ B[Nn,Kp]^T (+ base). CTA 128 x BN, BK=64, 256 thr, 8 warps.
// HALF_OUT: store C as fp16 (for gather-bound aggregation layers).
template<int BN>
__device__ __forceinline__ void load_stage(const __half* __restrict__ A,
                                           const __half* __restrict__ B,
                                           int bm, int bn, int Kp, int k0, int M,
                                           uint32_t sA, uint32_t sB) {
    int t = threadIdx.x;
#pragma unroll
    for (int i = 0; i < 4; i++) {
        int idx = t + i * 256;
        int row = idx >> 3, seg = idx & 7;
        int gr = bm + row;
        bool p = gr < M;
        const void* src = A + (size_t)(p ? gr : 0) * Kp + k0 + seg * 8;
        cp16(sA + swz(row * 128 + seg * 16), src, p);
    }
#pragma unroll
    for (int i = 0; i < BN * 8 / 256; i++) {
        int idx = t + i * 256;
        int row = idx >> 3, seg = idx & 7;
        const void* src = B + (size_t)(bn + row) * Kp + k0 + seg * 8;
        cp16(sB + swz(row * 128 + seg * 16), src, true);
    }
}

template<int BN, bool ADD_BASE, bool HALF_OUT>
__global__ __launch_bounds__(256) void mma_gemm(const __half* __restrict__ A,
                                                const __half* __restrict__ B,
                                                const float* __restrict__ base,
                                                void* __restrict__ Cv,
                                                int M, int Kp, int Nn) {
    extern __shared__ char smem[];
    constexpr int WN = BN / 2;
    constexpr int SS = (128 + BN) * 128;     // bytes per stage
    uint32_t sb = smem_u32(smem);
    int tid = threadIdx.x, wid = tid >> 5, lane = tid & 31;
    int bm = blockIdx.y * 128, bn = blockIdx.x * BN;
    int wm = (wid & 3) * 32;
    int wn = (wid >> 2) * WN;

    float acc[2][WN / 8][4];
#pragma unroll
    for (int i = 0; i < 2; i++)
#pragma unroll
        for (int j = 0; j < WN / 8; j++)
#pragma unroll
            for (int q = 0; q < 4; q++) acc[i][j][q] = 0.f;

    int nT = Kp >> 6;
#pragma unroll
    for (int s = 0; s < 2; s++) {
        uint32_t sp = sb + (uint32_t)s * SS;
        load_stage<BN>(A, B, bm, bn, Kp, s * 64, M, sp, sp + 128 * 128);
        CP_COMMIT();
    }

    for (int t = 0; t < nT; t++) {
        if (t + 2 < nT) {
            uint32_t sp = sb + (uint32_t)((t + 2) % 3) * SS;
            load_stage<BN>(A, B, bm, bn, Kp, (t + 2) * 64, M, sp, sp + 128 * 128);
        }
        CP_COMMIT();
        CP_WAIT2();
        __syncthreads();

        uint32_t sA = sb + (uint32_t)(t % 3) * SS;
        uint32_t sB = sA + 128 * 128;
#pragma unroll
        for (int ks = 0; ks < 4; ks++) {
            uint32_t af[2][4];
#pragma unroll
            for (int mi = 0; mi < 2; mi++) {
                int row = wm + mi * 16 + (lane & 15);
                ldsm_x4(af[mi], sA + swz(row * 128 + ks * 32 + ((lane >> 4) << 4)));
            }
#pragma unroll
            for (int nj = 0; nj < WN / 16; nj++) {
                uint32_t bf[4];
                int row = wn + nj * 16 + (lane & 7) + ((lane >> 4) << 3);
                ldsm_x4(bf, sB + swz(row * 128 + ks * 32 + (((lane >> 3) & 1) << 4)));
                mma_f16(acc[0][2 * nj],     af[0], bf);
                mma_f16(acc[0][2 * nj + 1], af[0], bf + 2);
                mma_f16(acc[1][2 * nj],     af[1], bf);
                mma_f16(acc[1][2 * nj + 1], af[1], bf + 2);
            }
        }
        __syncthreads();
    }

#pragma unroll
    for (int mi = 0; mi < 2; mi++) {
#pragma unroll
        for (int nj = 0; nj < WN / 8; nj++) {
            int row = bm + wm + mi * 16 + (lane >> 2);
            int col = bn + wn + nj * 8 + (lane & 3) * 2;
#pragma unroll
            for (int h = 0; h < 2; h++) {
                int r = row + h * 8;
                if (r < M) {
                    float2 v = make_float2(acc[mi][nj][h * 2], acc[mi][nj][h * 2 + 1]);
                    if (ADD_BASE) {
                        float2 b2 = *(const float2*)(base + (size_t)r * Nn + col);
                        v.x += b2.x; v.y += b2.y;
                    }
                    if (HALF_OUT) {
                        *(__half2*)((__half*)Cv + (size_t)r * Nn + col) = __floats2half2_rn(v.x, v.y);
                    } else {
                        *(float2*)((float*)Cv + (size_t)r * Nn + col) = v;
                    }
                }
            }
        }
    }
}

// ======================= fused CSR aggregation (fp16 gather) =======================
// h_out[n] = leakyrelu( sum_in t[src]*w + t[n]*dinv^2 + bias ); t is fp16, 8 halves/thread.
template<int F, int NPB>
__global__ __launch_bounds__(128) void csr_agg_h(const __half* __restrict__ t,
                                                 const float* __restrict__ b,
                                                 __half* __restrict__ hs) {
    constexpr int C = F / 8;
    int node = blockIdx.x * NPB + threadIdx.x / C;
    int ch = threadIdx.x % C;
    if (node >= N_NODES) return;
    int beg = g_rp[node], end = g_rp[node + 1];
    const uint4* tv = (const uint4*)t;
    float d = g_dinv[node];
    float dd = d * d;
    float acc[8];
    {
        uint4 sv = tv[(size_t)node * C + ch];
        const __half2* h2 = (const __half2*)&sv;
        float4 b0 = ((const float4*)b)[ch * 2];
        float4 b1v = ((const float4*)b)[ch * 2 + 1];
        float bb[8] = {b0.x, b0.y, b0.z, b0.w, b1v.x, b1v.y, b1v.z, b1v.w};
#pragma unroll
        for (int q = 0; q < 4; q++) {
            float2 f2 = __half22float2(h2[q]);
            acc[q * 2 + 0] = fmaf(f2.x, dd, bb[q * 2 + 0]);
            acc[q * 2 + 1] = fmaf(f2.y, dd, bb[q * 2 + 1]);
        }
    }
    int i = beg;
    for (; i + 2 <= end; i += 2) {
        int s0 = g_csrc[i], s1 = g_csrc[i + 1];
        float w0 = g_cw[i], w1 = g_cw[i + 1];
        uint4 v0 = tv[(size_t)s0 * C + ch];
        uint4 v1 = tv[(size_t)s1 * C + ch];
        const __half2* a0 = (const __half2*)&v0;
        const __half2* a1 = (const __half2*)&v1;
#pragma unroll
        for (int q = 0; q < 4; q++) {
            float2 f0 = __half22float2(a0[q]);
            float2 f1 = __half22float2(a1[q]);
            acc[q * 2 + 0] += f0.x * w0 + f1.x * w1;
            acc[q * 2 + 1] += f0.y * w0 + f1.y * w1;
        }
    }
    if (i < end) {
        int s0 = g_csrc[i];
        float w0 = g_cw[i];
        uint4 v0 = tv[(size_t)s0 * C + ch];
        const __half2* a0 = (const __half2*)&v0;
#pragma unroll
        for (int q = 0; q < 4; q++) {
            float2 f0 = __half22float2(a0[q]);
            acc[q * 2 + 0] += f0.x * w0;
            acc[q * 2 + 1] += f0.y * w0;
        }
    }
    __half h[8];
#pragma unroll
    for (int q = 0; q < 8; q++) {
        float u = acc[q] > 0.f ? acc[q] : 0.01f * acc[q];
        h[q] = __float2half(u);
    }
    *(uint4*)(hs + (size_t)node * F + ch * 8) = *(uint4*)h;
}

// fp32-gather version with fused 64->3 projection (final layer)
template<int F, int NPB>
__global__ __launch_bounds__(128) void csr_agg_proj(const float* __restrict__ t,
                                                    const float* __restrict__ b,
                                                    const float* __restrict__ Wp,
                                                    const float* __restrict__ bp,
                                                    float* __restrict__ out) {
    constexpr int C = F / 4;
    int node = blockIdx.x * NPB + threadIdx.x / C;
    int ch = threadIdx.x % C;
    if (node >= N_NODES) return;
    int beg = g_rp[node], end = g_rp[node + 1];
    const float4* tv = (const float4*)t;
    float d = g_dinv[node];
    float dd = d * d;
    float4 self = tv[(size_t)node * C + ch];
    float4 bv = ((const float4*)b)[ch];
    float4 acc = make_float4(fmaf(self.x, dd, bv.x), fmaf(self.y, dd, bv.y),
                             fmaf(self.z, dd, bv.z), fmaf(self.w, dd, bv.w));
    int i = beg;
    for (; i + 4 <= end; i += 4) {
        int s0 = g_csrc[i], s1 = g_csrc[i + 1], s2 = g_csrc[i + 2], s3 = g_csrc[i + 3];
        float w0 = g_cw[i], w1 = g_cw[i + 1], w2 = g_cw[i + 2], w3 = g_cw[i + 3];
        float4 v0 = tv[(size_t)s0 * C + ch];
        float4 v1 = tv[(size_t)s1 * C + ch];
        float4 v2 = tv[(size_t)s2 * C + ch];
        float4 v3 = tv[(size_t)s3 * C + ch];
        acc.x += v0.x * w0 + v1.x * w1 + v2.x * w2 + v3.x * w3;
        acc.y += v0.y * w0 + v1.y * w1 + v2.y * w2 + v3.y * w3;
        acc.z += v0.z * w0 + v1.z * w1 + v2.z * w2 + v3.z * w3;
        acc.w += v0.w * w0 + v1.w * w1 + v2.w * w2 + v3.w * w3;
    }
    for (; i < end; i++) {
        int s0 = g_csrc[i];
        float w0 = g_cw[i];
        float4 v0 = tv[(size_t)s0 * C + ch];
        acc.x += v0.x * w0; acc.y += v0.y * w0; acc.z += v0.z * w0; acc.w += v0.w * w0;
    }
    float f[4] = {acc.x, acc.y, acc.z, acc.w};
#pragma unroll
    for (int q = 0; q < 4; q++) f[q] = f[q] > 0.f ? f[q] : 0.01f * f[q];
    float a0 = 0.f, a1 = 0.f, a2 = 0.f;
#pragma unroll
    for (int q = 0; q < 4; q++) {
        int k = ch * 4 + q;
        a0 = fmaf(f[q], __ldg(Wp + k * 3 + 0), a0);
        a1 = fmaf(f[q], __ldg(Wp + k * 3 + 1), a1);
        a2 = fmaf(f[q], __ldg(Wp + k * 3 + 2), a2);
    }
#pragma unroll
    for (int off = C / 2; off; off >>= 1) {
        a0 += __shfl_down_sync(0xffffffffu, a0, off, C);
        a1 += __shfl_down_sync(0xffffffffu, a1, off, C);
        a2 += __shfl_down_sync(0xffffffffu, a2, off, C);
    }
    if (ch == 0) {
        out[(size_t)node * 3 + 0] = a0 + bp[0];
        out[(size_t)node * 3 + 1] = a1 + bp[1];
        out[(size_t)node * 3 + 2] = a2 + bp[2];
    }
}

// ======================= launch =======================
extern "C" void kernel_launch(void* const* d_in, const int* in_sizes, int n_in,
                              void* d_out, int out_size) {
    const float* x           = (const float*)d_in[0];
    const int*   edge_index  = (const int*)  d_in[1];
    const float* edge_attr   = (const float*)d_in[2];
    const float* layer_table = (const float*)d_in[3];
    const float* rel_table   = (const float*)d_in[4];
    const float* color_table = (const float*)d_in[5];
    const float* W1 = (const float*)d_in[6];
    const float* b1 = (const float*)d_in[7];
    const float* W2 = (const float*)d_in[8];
    const float* b2 = (const float*)d_in[9];
    const float* W3 = (const float*)d_in[10];
    const float* b3 = (const float*)d_in[11];
    const float* Wp = (const float*)d_in[12];
    const float* bp = (const float*)d_in[13];
    float* out = (float*)d_out;

    __half *p_A2, *p_h2s, *p_W1T, *p_W2T, *p_W3T;
    float *p_base, *p_t;
    cudaGetSymbolAddress((void**)&p_A2,   g_A2);
    cudaGetSymbolAddress((void**)&p_h2s,  g_h2s);
    cudaGetSymbolAddress((void**)&p_W1T,  g_W1T);
    cudaGetSymbolAddress((void**)&p_W2T,  g_W2T);
    cudaGetSymbolAddress((void**)&p_W3T,  g_W3T);
    cudaGetSymbolAddress((void**)&p_base, g_base);
    cudaGetSymbolAddress((void**)&p_t,    g_t);
    __half* p_th = (__half*)p_t;

    const int T = 256;
    const int SM128 = 3 * (128 + 128) * 128;   // 98304
    const int SM64  = 3 * (128 + 64) * 128;    // 73728
    cudaFuncSetAttribute((const void*)mma_gemm<128, true,  true>,  cudaFuncAttributeMaxDynamicSharedMemorySize, SM128);
    cudaFuncSetAttribute((const void*)mma_gemm<128, false, true>,  cudaFuncAttributeMaxDynamicSharedMemorySize, SM128);
    cudaFuncSetAttribute((const void*)mma_gemm<64,  false, false>, cudaFuncAttributeMaxDynamicSharedMemorySize, SM64);

    // graph prep
    zero_both<<<(N_NODES + T - 1) / T, T>>>();
    deg_kernel<<<(N_EDGES + T - 1) / T, T>>>(edge_index, edge_attr);
    scan_kernel<<<1, 1024>>>();
    scatter_kernel<<<(N_EDGES + T - 1) / T, T>>>(edge_index, edge_attr);

    // weights -> fp16 transposed; table precomputations; node base + resnet fp16
    convW<<<(W1N + W2N + W3N + T - 1) / T, T>>>(W1, W2, W3);
    pre_all<<<782, 512>>>(layer_table, rel_table, color_table, W1);
    split_base<<<N_NODES, T>>>(x);

    const int MT = (N_NODES + 127) / 128;   // 157

    // ---- layer 1 (t stored fp16) ----
    mma_gemm<128, true, true><<<dim3(F1 / 128, MT), T, SM128>>>(p_A2, p_W1T, p_base, p_th, N_NODES, KP1, F1);
    csr_agg_h<F1, 2><<<(N_NODES + 1) / 2, 128>>>(p_th, b1, p_h2s);

    // ---- layer 2 (t stored fp16) ----
    mma_gemm<128, false, true><<<dim3(F2 / 128, MT), T, SM128>>>(p_h2s, p_W2T, nullptr, p_th, N_NODES, F1, F2);
    csr_agg_h<F2, 4><<<(N_NODES + 3) / 4, 128>>>(p_th, b2, p_h2s);

    // ---- layer 3 (t fp32, projection fused) ----
    mma_gemm<64, false, false><<<dim3(F3 / 64, MT), T, SM64>>>(p_h2s, p_W3T, nullptr, p_t, N_NODES, F2, F3);
    csr_agg_proj<F3, 8><<<(N_NODES + 7) / 8, 128>>>(p_t, b3, Wp, bp, out);
}

// round 11
// speedup vs baseline: 4.9126x; 1.0165x over previous
#include <cuda_runtime.h>
#include <cuda_fp16.h>
#include <math.h>
#include <stdint.h>

#define N_NODES 20000
#define N_EDGES 320000
#define FS      1000
#define XCOLS   1005
#define F1      512
#define F2      256
#define F3      64
#define KP1     1024             // padded resnet K

// ======================= static scratch =======================
__device__ __half g_A2 [(size_t)N_NODES * KP1];     // fp16 resnet (A operand, layer1)
__device__ __half g_h2s[(size_t)N_NODES * F1];      // fp16 activations (A operand, layers 2-3)
__device__ __half g_W1T[(size_t)F1 * KP1];          // fp16 transposed weights
__device__ __half g_W2T[(size_t)F2 * F1];
__device__ __half g_W3T[(size_t)F3 * F2];
__device__ float g_base[(size_t)N_NODES * F1];
__device__ float g_t   [(size_t)N_NODES * F1];      // fp16 view layers 1-2, fp32 layer 3
__device__ float g_dinv[N_NODES];
__device__ float g_preL[3 * F1];
__device__ float g_preR[11 * F1];
__device__ float g_preC[3 * 256 * F1];
// CSR (fused (src, w) records)
__device__ int   g_degi[N_NODES];
__device__ int   g_rp[N_NODES + 1];
__device__ int   g_cursor[N_NODES];
__device__ int2  g_edge[N_EDGES];                   // .x = src, .y = w bits

// ======================= PTX helpers (portable, sm_80+) =======================
__device__ __forceinline__ uint32_t smem_u32(const void* p) {
    uint32_t a;
    asm("{ .reg .u64 t; cvta.to.shared.u64 t, %1; cvt.u32.u64 %0, t; }" : "=r"(a) : "l"(p));
    return a;
}
__device__ __forceinline__ void cp16(uint32_t dst, const void* src, bool pred) {
    int sz = pred ? 16 : 0;
    asm volatile("cp.async.cg.shared.global [%0], [%1], 16, %2;"
                 :: "r"(dst), "l"(src), "r"(sz) : "memory");
}
#define CP_COMMIT() asm volatile("cp.async.commit_group;" ::: "memory")
#define CP_WAIT2()  asm volatile("cp.async.wait_group 2;" ::: "memory")

__device__ __forceinline__ void ldsm_x4(uint32_t* r, uint32_t addr) {
    asm volatile("ldmatrix.sync.aligned.m8n8.x4.shared.b16 {%0,%1,%2,%3}, [%4];"
                 : "=r"(r[0]), "=r"(r[1]), "=r"(r[2]), "=r"(r[3]) : "r"(addr));
}
__device__ __forceinline__ void mma_f16(float* d, const uint32_t* a, const uint32_t* b) {
    asm volatile("mma.sync.aligned.m16n8k16.row.col.f32.f16.f16.f32 "
                 "{%0,%1,%2,%3}, {%4,%5,%6,%7}, {%8,%9}, {%0,%1,%2,%3};"
                 : "+f"(d[0]), "+f"(d[1]), "+f"(d[2]), "+f"(d[3])
                 : "r"(a[0]), "r"(a[1]), "r"(a[2]), "r"(a[3]), "r"(b[0]), "r"(b[1]));
}
__device__ __forceinline__ uint32_t swz(uint32_t off) { return off ^ ((off >> 3) & 0x70); }

// ======================= prep kernels =======================
__global__ void zero_both() {
    int i = blockIdx.x * blockDim.x + threadIdx.x;
    if (i < N_NODES) { g_dinv[i] = 0.f; g_degi[i] = 0; }
}
__global__ void deg_kernel(const int* __restrict__ ei, const float* __restrict__ ea) {
    int e = blockIdx.x * blockDim.x + threadIdx.x;
    if (e < N_EDGES) {
        int dst = ei[N_EDGES + e];
        atomicAdd(&g_dinv[dst], ea[e]);
        atomicAdd(&g_degi[dst], 1);
    }
}
__global__ void scan_kernel() {
    __shared__ int sh[1024];
    const int CH = (N_NODES + 1023) / 1024;
    int tid = threadIdx.x;
    int base = tid * CH;
    int s = 0;
    for (int j = 0; j < CH; j++) {
        int i = base + j;
        if (i < N_NODES) {
            g_dinv[i] = rsqrtf(g_dinv[i] + 1.0f);
            s += g_degi[i];
        }
    }
    sh[tid] = s;
    __syncthreads();
    for (int off = 1; off < 1024; off <<= 1) {
        int v = (tid >= off) ? sh[tid - off] : 0;
        __syncthreads();
        sh[tid] += v;
        __syncthreads();
    }
    int run = tid ? sh[tid - 1] : 0;
    for (int j = 0; j < CH; j++) {
        int i = base + j;
        if (i < N_NODES) {
            g_rp[i] = run;
            g_cursor[i] = run;
            run += g_degi[i];
        }
    }
    if (tid == 1023) g_rp[N_NODES] = sh[1023];
}
__global__ void scatter_kernel(const int* __restrict__ ei, const float* __restrict__ ea) {
    int e = blockIdx.x * blockDim.x + threadIdx.x;
    if (e >= N_EDGES) return;
    int src = ei[e];
    int dst = ei[N_EDGES + e];
    float w = g_dinv[src] * ea[e] * g_dinv[dst];
    int pos = atomicAdd(&g_cursor[dst], 1);
    g_edge[pos] = make_int2(src, __float_as_int(w));
}

// fused: all table @ W1 precomputations. blocks 0-2: layer, 3-13: rel, 14-781: color
__global__ void pre_all(const float* __restrict__ layer_table, const float* __restrict__ rel_table,
                        const float* __restrict__ color_table, const float* __restrict__ W1) {
    __shared__ float s[256];
    int b = blockIdx.x, j = threadIdx.x;
    const float* tab;
    float* outp;
    int Kt, off;
    if (b < 3)       { tab = layer_table + (size_t)b * 250;        outp = g_preL + (size_t)b * F1;        Kt = 250; off = 0; }
    else if (b < 14) { tab = rel_table + (size_t)(b - 3) * 250;    outp = g_preR + (size_t)(b - 3) * F1;  Kt = 250; off = 1250; }
    else {
        int q = b - 14;
        int p = q >> 8, c = q & 255;
        tab = color_table + (size_t)c * 85;
        outp = g_preC + (size_t)q * F1;
        Kt = 85; off = 1500 + 85 * p;
    }
    if (j < Kt) s[j] = tab[j];
    __syncthreads();
    float acc = 0.f;
    for (int k = 0; k < Kt; k++) acc = fmaf(s[k], W1[(size_t)(off + k) * F1 + j], acc);
    outp[j] = acc;
}

// fused: resnet -> fp16 + node base. one block (256 thr) per node.
__global__ void split_base(const float* __restrict__ x) {
    int i = blockIdx.x;
    const float* xr = x + (size_t)i * XCOLS;
    __half* a = g_A2 + (size_t)i * KP1;
    for (int k = threadIdx.x; k < KP1; k += blockDim.x) {
        float v = (k < FS) ? xr[1 + k] : 0.f;
        a[k] = __float2half(v);
    }
    int j = threadIdx.x;
    if (j < 128) {
        int li = (int)xr[0] - 1;
        int ri = __float2int_rn(fabsf(xr[FS + 1]) * 10.0f);
        int c0 = (int)xr[XCOLS - 3];
        int c1 = (int)xr[XCOLS - 2];
        int c2 = (int)xr[XCOLS - 1];
        float4 pa = ((const float4*)(g_preL + (size_t)li * F1))[j];
        float4 pb = ((const float4*)(g_preR + (size_t)ri * F1))[j];
        float4 u = ((const float4*)(g_preC + ((size_t)(0 * 256 + c0)) * F1))[j];
        float4 v = ((const float4*)(g_preC + ((size_t)(1 * 256 + c1)) * F1))[j];
        float4 w = ((const float4*)(g_preC + ((size_t)(2 * 256 + c2)) * F1))[j];
        ((float4*)(g_base + (size_t)i * F1))[j] =
            make_float4(pa.x + pb.x + u.x + v.x + w.x, pa.y + pb.y + u.y + v.y + w.y,
                        pa.z + pb.z + u.z + v.z + w.z, pa.w + pb.w + u.w + v.w + w.w);
    }
}

// one kernel: all three weight matrices -> fp16 transposed
#define W1N (F1 * KP1)
#define W2N (F2 * F1)
#define W3N (F3 * F2)
__global__ void convW(const float* __restrict__ W1, const float* __restrict__ W2,
                      const float* __restrict__ W3) {
    int idx = blockIdx.x * blockDim.x + threadIdx.x;
    if (idx < W1N) {
        int n = idx / KP1, k = idx % KP1;
        float v = (k < FS) ? W1[(size_t)(250 + k) * F1 + n] : 0.f;
        g_W1T[idx] = __float2half(v);
    } else if (idx < W1N + W2N) {
        int q = idx - W1N;
        int n = q / F1, k = q % F1;
        g_W2T[q] = __float2half(W2[(size_t)k * F2 + n]);
    } else if (idx < W1N + W2N + W3N) {
        int q = idx - W1N - W2N;
        int n = q / F2, k = q % F2;
        g_W3T[q] = __float2half(W3[(size_t)k * F3 + n]);
    }
}

// ======================= mma.sync fp16 GEMM (3-stage) =======================
template<int BN>
__device__ __forceinline__ void load_stage(const __half* __restrict__ A,
                                           const __half* __restrict__ B,
                                           int bm, int bn, int Kp, int k0, int M,
                                           uint32_t sA, uint32_t sB) {
    int t = threadIdx.x;
#pragma unroll
    for (int i = 0; i < 4; i++) {
        int idx = t + i * 256;
        int row = idx >> 3, seg = idx & 7;
        int gr = bm + row;
        bool p = gr < M;
        const void* src = A + (size_t)(p ? gr : 0) * Kp + k0 + seg * 8;
        cp16(sA + swz(row * 128 + seg * 16), src, p);
    }
#pragma unroll
    for (int i = 0; i < BN * 8 / 256; i++) {
        int idx = t + i * 256;
        int row = idx >> 3, seg = idx & 7;
        const void* src = B + (size_t)(bn + row) * Kp + k0 + seg * 8;
        cp16(sB + swz(row * 128 + seg * 16), src, true);
    }
}

template<int BN, bool ADD_BASE, bool HALF_OUT>
__global__ __launch_bounds__(256) void mma_gemm(const __half* __restrict__ A,
                                                const __half* __restrict__ B,
                                                const float* __restrict__ base,
                                                void* __restrict__ Cv,
                                                int M, int Kp, int Nn) {
    extern __shared__ char smem[];
    constexpr int WN = BN / 2;
    constexpr int SS = (128 + BN) * 128;
    uint32_t sb = smem_u32(smem);
    int tid = threadIdx.x, wid = tid >> 5, lane = tid & 31;
    int bm = blockIdx.y * 128, bn = blockIdx.x * BN;
    int wm = (wid & 3) * 32;
    int wn = (wid >> 2) * WN;

    float acc[2][WN / 8][4];
#pragma unroll
    for (int i = 0; i < 2; i++)
#pragma unroll
        for (int j = 0; j < WN / 8; j++)
#pragma unroll
            for (int q = 0; q < 4; q++) acc[i][j][q] = 0.f;

    int nT = Kp >> 6;
#pragma unroll
    for (int s = 0; s < 2; s++) {
        uint32_t sp = sb + (uint32_t)s * SS;
        load_stage<BN>(A, B, bm, bn, Kp, s * 64, M, sp, sp + 128 * 128);
        CP_COMMIT();
    }

    for (int t = 0; t < nT; t++) {
        if (t + 2 < nT) {
            uint32_t sp = sb + (uint32_t)((t + 2) % 3) * SS;
            load_stage<BN>(A, B, bm, bn, Kp, (t + 2) * 64, M, sp, sp + 128 * 128);
        }
        CP_COMMIT();
        CP_WAIT2();
        __syncthreads();

        uint32_t sA = sb + (uint32_t)(t % 3) * SS;
        uint32_t sB = sA + 128 * 128;
#pragma unroll
        for (int ks = 0; ks < 4; ks++) {
            uint32_t af[2][4];
#pragma unroll
            for (int mi = 0; mi < 2; mi++) {
                int row = wm + mi * 16 + (lane & 15);
                ldsm_x4(af[mi], sA + swz(row * 128 + ks * 32 + ((lane >> 4) << 4)));
            }
#pragma unroll
            for (int nj = 0; nj < WN / 16; nj++) {
                uint32_t bf[4];
                int row = wn + nj * 16 + (lane & 7) + ((lane >> 4) << 3);
                ldsm_x4(bf, sB + swz(row * 128 + ks * 32 + (((lane >> 3) & 1) << 4)));
                mma_f16(acc[0][2 * nj],     af[0], bf);
                mma_f16(acc[0][2 * nj + 1], af[0], bf + 2);
                mma_f16(acc[1][2 * nj],     af[1], bf);
                mma_f16(acc[1][2 * nj + 1], af[1], bf + 2);
            }
        }
        __syncthreads();
    }

#pragma unroll
    for (int mi = 0; mi < 2; mi++) {
#pragma unroll
        for (int nj = 0; nj < WN / 8; nj++) {
            int row = bm + wm + mi * 16 + (lane >> 2);
            int col = bn + wn + nj * 8 + (lane & 3) * 2;
#pragma unroll
            for (int h = 0; h < 2; h++) {
                int r = row + h * 8;
                if (r < M) {
                    float2 v = make_float2(acc[mi][nj][h * 2], acc[mi][nj][h * 2 + 1]);
                    if (ADD_BASE) {
                        float2 b2 = *(const float2*)(base + (size_t)r * Nn + col);
                        v.x += b2.x; v.y += b2.y;
                    }
                    if (HALF_OUT) {
                        *(__half2*)((__half*)Cv + (size_t)r * Nn + col) = __floats2half2_rn(v.x, v.y);
                    } else {
                        *(float2*)((float*)Cv + (size_t)r * Nn + col) = v;
                    }
                }
            }
        }
    }
}

// ======================= fused CSR aggregation (fp16 gather, 4-way MLP) =======================
template<int F, int NPB>
__global__ __launch_bounds__(128) void csr_agg_h(const __half* __restrict__ t,
                                                 const float* __restrict__ b,
                                                 __half* __restrict__ hs) {
    constexpr int C = F / 8;
    int node = blockIdx.x * NPB + threadIdx.x / C;
    int ch = threadIdx.x % C;
    if (node >= N_NODES) return;
    int beg = g_rp[node], end = g_rp[node + 1];
    const uint4* tv = (const uint4*)t;
    float d = g_dinv[node];
    float dd = d * d;
    float acc[8];
    {
        uint4 sv = tv[(size_t)node * C + ch];
        const __half2* h2 = (const __half2*)&sv;
        float4 b0 = ((const float4*)b)[ch * 2];
        float4 b1v = ((const float4*)b)[ch * 2 + 1];
        float bb[8] = {b0.x, b0.y, b0.z, b0.w, b1v.x, b1v.y, b1v.z, b1v.w};
#pragma unroll
        for (int q = 0; q < 4; q++) {
            float2 f2 = __half22float2(h2[q]);
            acc[q * 2 + 0] = fmaf(f2.x, dd, bb[q * 2 + 0]);
            acc[q * 2 + 1] = fmaf(f2.y, dd, bb[q * 2 + 1]);
        }
    }
    int i = beg;
    for (; i + 4 <= end; i += 4) {
        int2 e0 = g_edge[i], e1 = g_edge[i + 1], e2 = g_edge[i + 2], e3 = g_edge[i + 3];
        uint4 v0 = tv[(size_t)e0.x * C + ch];
        uint4 v1 = tv[(size_t)e1.x * C + ch];
        uint4 v2 = tv[(size_t)e2.x * C + ch];
        uint4 v3 = tv[(size_t)e3.x * C + ch];
        float w0 = __int_as_float(e0.y), w1 = __int_as_float(e1.y);
        float w2 = __int_as_float(e2.y), w3 = __int_as_float(e3.y);
        const __half2* a0 = (const __half2*)&v0;
        const __half2* a1 = (const __half2*)&v1;
        const __half2* a2 = (const __half2*)&v2;
        const __half2* a3 = (const __half2*)&v3;
#pragma unroll
        for (int q = 0; q < 4; q++) {
            float2 f0 = __half22float2(a0[q]);
            float2 f1 = __half22float2(a1[q]);
            float2 f2 = __half22float2(a2[q]);
            float2 f3 = __half22float2(a3[q]);
            acc[q * 2 + 0] += f0.x * w0 + f1.x * w1 + f2.x * w2 + f3.x * w3;
            acc[q * 2 + 1] += f0.y * w0 + f1.y * w1 + f2.y * w2 + f3.y * w3;
        }
    }
    for (; i < end; i++) {
        int2 e0 = g_edge[i];
        float w0 = __int_as_float(e0.y);
        uint4 v0 = tv[(size_t)e0.x * C + ch];
        const __half2* a0 = (const __half2*)&v0;
#pragma unroll
        for (int q = 0; q < 4; q++) {
            float2 f0 = __half22float2(a0[q]);
            acc[q * 2 + 0] += f0.x * w0;
            acc[q * 2 + 1] += f0.y * w0;
        }
    }
    __half h[8];
#pragma unroll
    for (int q = 0; q < 8; q++) {
        float u = acc[q] > 0.f ? acc[q] : 0.01f * acc[q];
        h[q] = __float2half(u);
    }
    *(uint4*)(hs + (size_t)node * F + ch * 8) = *(uint4*)h;
}

// fp32-gather version with fused 64->3 projection (final layer)
template<int F, int NPB>
__global__ __launch_bounds__(128) void csr_agg_proj(const float* __restrict__ t,
                                                    const float* __restrict__ b,
                                                    const float* __restrict__ Wp,
                                                    const float* __restrict__ bp,
                                                    float* __restrict__ out) {
    constexpr int C = F / 4;
    int node = blockIdx.x * NPB + threadIdx.x / C;
    int ch = threadIdx.x % C;
    if (node >= N_NODES) return;
    int beg = g_rp[node], end = g_rp[node + 1];
    const float4* tv = (const float4*)t;
    float d = g_dinv[node];
    float dd = d * d;
    float4 self = tv[(size_t)node * C + ch];
    float4 bv = ((const float4*)b)[ch];
    float4 acc = make_float4(fmaf(self.x, dd, bv.x), fmaf(self.y, dd, bv.y),
                             fmaf(self.z, dd, bv.z), fmaf(self.w, dd, bv.w));
    int i = beg;
    for (; i + 4 <= end; i += 4) {
        int2 e0 = g_edge[i], e1 = g_edge[i + 1], e2 = g_edge[i + 2], e3 = g_edge[i + 3];
        float4 v0 = tv[(size_t)e0.x * C + ch];
        float4 v1 = tv[(size_t)e1.x * C + ch];
        float4 v2 = tv[(size_t)e2.x * C + ch];
        float4 v3 = tv[(size_t)e3.x * C + ch];
        float w0 = __int_as_float(e0.y), w1 = __int_as_float(e1.y);
        float w2 = __int_as_float(e2.y), w3 = __int_as_float(e3.y);
        acc.x += v0.x * w0 + v1.x * w1 + v2.x * w2 + v3.x * w3;
        acc.y += v0.y * w0 + v1.y * w1 + v2.y * w2 + v3.y * w3;
        acc.z += v0.z * w0 + v1.z * w1 + v2.z * w2 + v3.z * w3;
        acc.w += v0.w * w0 + v1.w * w1 + v2.w * w2 + v3.w * w3;
    }
    for (; i < end; i++) {
        int2 e0 = g_edge[i];
        float w0 = __int_as_float(e0.y);
        float4 v0 = tv[(size_t)e0.x * C + ch];
        acc.x += v0.x * w0; acc.y += v0.y * w0; acc.z += v0.z * w0; acc.w += v0.w * w0;
    }
    float f[4] = {acc.x, acc.y, acc.z, acc.w};
#pragma unroll
    for (int q = 0; q < 4; q++) f[q] = f[q] > 0.f ? f[q] : 0.01f * f[q];
    float a0 = 0.f, a1 = 0.f, a2 = 0.f;
#pragma unroll
    for (int q = 0; q < 4; q++) {
        int k = ch * 4 + q;
        a0 = fmaf(f[q], __ldg(Wp + k * 3 + 0), a0);
        a1 = fmaf(f[q], __ldg(Wp + k * 3 + 1), a1);
        a2 = fmaf(f[q], __ldg(Wp + k * 3 + 2), a2);
    }
#pragma unroll
    for (int off = C / 2; off; off >>= 1) {
        a0 += __shfl_down_sync(0xffffffffu, a0, off, C);
        a1 += __shfl_down_sync(0xffffffffu, a1, off, C);
        a2 += __shfl_down_sync(0xffffffffu, a2, off, C);
    }
    if (ch == 0) {
        out[(size_t)node * 3 + 0] = a0 + bp[0];
        out[(size_t)node * 3 + 1] = a1 + bp[1];
        out[(size_t)node * 3 + 2] = a2 + bp[2];
    }
}

// ======================= launch =======================
extern "C" void kernel_launch(void* const* d_in, const int* in_sizes, int n_in,
                              void* d_out, int out_size) {
    const float* x           = (const float*)d_in[0];
    const int*   edge_index  = (const int*)  d_in[1];
    const float* edge_attr   = (const float*)d_in[2];
    const float* layer_table = (const float*)d_in[3];
    const float* rel_table   = (const float*)d_in[4];
    const float* color_table = (const float*)d_in[5];
    const float* W1 = (const float*)d_in[6];
    const float* b1 = (const float*)d_in[7];
    const float* W2 = (const float*)d_in[8];
    const float* b2 = (const float*)d_in[9];
    const float* W3 = (const float*)d_in[10];
    const float* b3 = (const float*)d_in[11];
    const float* Wp = (const float*)d_in[12];
    const float* bp = (const float*)d_in[13];
    float* out = (float*)d_out;

    __half *p_A2, *p_h2s, *p_W1T, *p_W2T, *p_W3T;
    float *p_base, *p_t;
    cudaGetSymbolAddress((void**)&p_A2,   g_A2);
    cudaGetSymbolAddress((void**)&p_h2s,  g_h2s);
    cudaGetSymbolAddress((void**)&p_W1T,  g_W1T);
    cudaGetSymbolAddress((void**)&p_W2T,  g_W2T);
    cudaGetSymbolAddress((void**)&p_W3T,  g_W3T);
    cudaGetSymbolAddress((void**)&p_base, g_base);
    cudaGetSymbolAddress((void**)&p_t,    g_t);
    __half* p_th = (__half*)p_t;

    const int T = 256;
    const int SM128 = 3 * (128 + 128) * 128;   // 98304
    const int SM64  = 3 * (128 + 64) * 128;    // 73728
    cudaFuncSetAttribute((const void*)mma_gemm<128, true,  true>,  cudaFuncAttributeMaxDynamicSharedMemorySize, SM128);
    cudaFuncSetAttribute((const void*)mma_gemm<128, false, true>,  cudaFuncAttributeMaxDynamicSharedMemorySize, SM128);
    cudaFuncSetAttribute((const void*)mma_gemm<64,  false, false>, cudaFuncAttributeMaxDynamicSharedMemorySize, SM64);

    // graph prep
    zero_both<<<(N_NODES + T - 1) / T, T>>>();
    deg_kernel<<<(N_EDGES + T - 1) / T, T>>>(edge_index, edge_attr);
    scan_kernel<<<1, 1024>>>();
    scatter_kernel<<<(N_EDGES + T - 1) / T, T>>>(edge_index, edge_attr);

    // weights -> fp16 transposed; table precomputations; node base + resnet fp16
    convW<<<(W1N + W2N + W3N + T - 1) / T, T>>>(W1, W2, W3);
    pre_all<<<782, 512>>>(layer_table, rel_table, color_table, W1);
    split_base<<<N_NODES, T>>>(x);

    const int MT = (N_NODES + 127) / 128;   // 157

    // ---- layer 1 (t stored fp16) ----
    mma_gemm<128, true, true><<<dim3(F1 / 128, MT), T, SM128>>>(p_A2, p_W1T, p_base, p_th, N_NODES, KP1, F1);
    csr_agg_h<F1, 2><<<(N_NODES + 1) / 2, 128>>>(p_th, b1, p_h2s);

    // ---- layer 2 (t stored fp16) ----
    mma_gemm<128, false, true><<<dim3(F2 / 128, MT), T, SM128>>>(p_h2s, p_W2T, nullptr, p_th, N_NODES, F1, F2);
    csr_agg_h<F2, 4><<<(N_NODES + 3) / 4, 128>>>(p_th, b2, p_h2s);

    // ---- layer 3 (t fp32, projection fused) ----
    mma_gemm<64, false, false><<<dim3(F3 / 64, MT), T, SM64>>>(p_h2s, p_W3T, nullptr, p_t, N_NODES, F2, F3);
    csr_agg_proj<F3, 8><<<(N_NODES + 7) / 8, 128>>>(p_t, b3, Wp, bp, out);
}

// round 12
// speedup vs baseline: 5.1242x; 1.0431x over previous
#include <cuda_runtime.h>
#include <cuda_fp16.h>
#include <math.h>
#include <stdint.h>

#define N_NODES 20000
#define N_EDGES 320000
#define FS      1000
#define XCOLS   1005
#define F1      512
#define F2      256
#define F3      64
#define KP1     1024             // padded resnet K

// ======================= static scratch =======================
__device__ __half g_A2 [(size_t)N_NODES * KP1];     // fp16 resnet (A operand, layer1)
__device__ __half g_h2s[(size_t)N_NODES * F1];      // fp16 activations (A operand, layers 2-3)
__device__ __half g_W1T[(size_t)F1 * KP1];          // fp16 transposed weights
__device__ __half g_W2T[(size_t)F2 * F1];
__device__ __half g_W3T[(size_t)F3 * F2];
__device__ float g_base[(size_t)N_NODES * F1];
__device__ float g_t   [(size_t)N_NODES * F1];      // fp16 view layers 1-2, fp32 layer 3
__device__ float g_dinv[N_NODES];
__device__ float g_preL[3 * F1];
__device__ float g_preR[11 * F1];
__device__ float g_preC[3 * 256 * F1];
// CSR (fused (src, w) records)
__device__ int   g_degi[N_NODES];
__device__ int   g_rp[N_NODES + 1];
__device__ int   g_cursor[N_NODES];
__device__ int2  g_edge[N_EDGES];                   // .x = src, .y = w bits

// ======================= PTX helpers (portable, sm_80+) =======================
__device__ __forceinline__ uint32_t smem_u32(const void* p) {
    uint32_t a;
    asm("{ .reg .u64 t; cvta.to.shared.u64 t, %1; cvt.u32.u64 %0, t; }" : "=r"(a) : "l"(p));
    return a;
}
__device__ __forceinline__ void cp16(uint32_t dst, const void* src, bool pred) {
    int sz = pred ? 16 : 0;
    asm volatile("cp.async.cg.shared.global [%0], [%1], 16, %2;"
                 :: "r"(dst), "l"(src), "r"(sz) : "memory");
}
#define CP_COMMIT() asm volatile("cp.async.commit_group;" ::: "memory")
#define CP_WAIT2()  asm volatile("cp.async.wait_group 2;" ::: "memory")

__device__ __forceinline__ void ldsm_x4(uint32_t* r, uint32_t addr) {
    asm volatile("ldmatrix.sync.aligned.m8n8.x4.shared.b16 {%0,%1,%2,%3}, [%4];"
                 : "=r"(r[0]), "=r"(r[1]), "=r"(r[2]), "=r"(r[3]) : "r"(addr));
}
__device__ __forceinline__ void mma_f16(float* d, const uint32_t* a, const uint32_t* b) {
    asm volatile("mma.sync.aligned.m16n8k16.row.col.f32.f16.f16.f32 "
                 "{%0,%1,%2,%3}, {%4,%5,%6,%7}, {%8,%9}, {%0,%1,%2,%3};"
                 : "+f"(d[0]), "+f"(d[1]), "+f"(d[2]), "+f"(d[3])
                 : "r"(a[0]), "r"(a[1]), "r"(a[2]), "r"(a[3]), "r"(b[0]), "r"(b[1]));
}
__device__ __forceinline__ uint32_t swz(uint32_t off) { return off ^ ((off >> 3) & 0x70); }

// ======================= prep kernels =======================
__global__ void zero_both() {
    int i = blockIdx.x * blockDim.x + threadIdx.x;
    if (i < N_NODES) { g_dinv[i] = 0.f; g_degi[i] = 0; }
}
__global__ void deg_kernel(const int* __restrict__ ei, const float* __restrict__ ea) {
    int e = blockIdx.x * blockDim.x + threadIdx.x;
    if (e < N_EDGES) {
        int dst = ei[N_EDGES + e];
        atomicAdd(&g_dinv[dst], ea[e]);
        atomicAdd(&g_degi[dst], 1);
    }
}
__global__ void scan_kernel() {
    __shared__ int sh[1024];
    const int CH = (N_NODES + 1023) / 1024;
    int tid = threadIdx.x;
    int base = tid * CH;
    int s = 0;
    for (int j = 0; j < CH; j++) {
        int i = base + j;
        if (i < N_NODES) {
            g_dinv[i] = rsqrtf(g_dinv[i] + 1.0f);
            s += g_degi[i];
        }
    }
    sh[tid] = s;
    __syncthreads();
    for (int off = 1; off < 1024; off <<= 1) {
        int v = (tid >= off) ? sh[tid - off] : 0;
        __syncthreads();
        sh[tid] += v;
        __syncthreads();
    }
    int run = tid ? sh[tid - 1] : 0;
    for (int j = 0; j < CH; j++) {
        int i = base + j;
        if (i < N_NODES) {
            g_rp[i] = run;
            g_cursor[i] = run;
            run += g_degi[i];
        }
    }
    if (tid == 1023) g_rp[N_NODES] = sh[1023];
}
__global__ void scatter_kernel(const int* __restrict__ ei, const float* __restrict__ ea) {
    int e = blockIdx.x * blockDim.x + threadIdx.x;
    if (e >= N_EDGES) return;
    int src = ei[e];
    int dst = ei[N_EDGES + e];
    float w = g_dinv[src] * ea[e] * g_dinv[dst];
    int pos = atomicAdd(&g_cursor[dst], 1);
    g_edge[pos] = make_int2(src, __float_as_int(w));
}

// fused: all table @ W1 precomputations. blocks 0-2: layer, 3-13: rel, 14-781: color
__global__ void pre_all(const float* __restrict__ layer_table, const float* __restrict__ rel_table,
                        const float* __restrict__ color_table, const float* __restrict__ W1) {
    __shared__ float s[256];
    int b = blockIdx.x, j = threadIdx.x;
    const float* tab;
    float* outp;
    int Kt, off;
    if (b < 3)       { tab = layer_table + (size_t)b * 250;        outp = g_preL + (size_t)b * F1;        Kt = 250; off = 0; }
    else if (b < 14) { tab = rel_table + (size_t)(b - 3) * 250;    outp = g_preR + (size_t)(b - 3) * F1;  Kt = 250; off = 1250; }
    else {
        int q = b - 14;
        int p = q >> 8, c = q & 255;
        tab = color_table + (size_t)c * 85;
        outp = g_preC + (size_t)q * F1;
        Kt = 85; off = 1500 + 85 * p;
    }
    if (j < Kt) s[j] = tab[j];
    __syncthreads();
    float acc = 0.f;
    for (int k = 0; k < Kt; k++) acc = fmaf(s[k], W1[(size_t)(off + k) * F1 + j], acc);
    outp[j] = acc;
}

// fused: resnet -> fp16 + node base. one block (256 thr) per node.
__global__ void split_base(const float* __restrict__ x) {
    int i = blockIdx.x;
    const float* xr = x + (size_t)i * XCOLS;
    __half* a = g_A2 + (size_t)i * KP1;
    for (int k = threadIdx.x; k < KP1; k += blockDim.x) {
        float v = (k < FS) ? xr[1 + k] : 0.f;
        a[k] = __float2half(v);
    }
    int j = threadIdx.x;
    if (j < 128) {
        int li = (int)xr[0] - 1;
        int ri = __float2int_rn(fabsf(xr[FS + 1]) * 10.0f);
        int c0 = (int)xr[XCOLS - 3];
        int c1 = (int)xr[XCOLS - 2];
        int c2 = (int)xr[XCOLS - 1];
        float4 pa = ((const float4*)(g_preL + (size_t)li * F1))[j];
        float4 pb = ((const float4*)(g_preR + (size_t)ri * F1))[j];
        float4 u = ((const float4*)(g_preC + ((size_t)(0 * 256 + c0)) * F1))[j];
        float4 v = ((const float4*)(g_preC + ((size_t)(1 * 256 + c1)) * F1))[j];
        float4 w = ((const float4*)(g_preC + ((size_t)(2 * 256 + c2)) * F1))[j];
        ((float4*)(g_base + (size_t)i * F1))[j] =
            make_float4(pa.x + pb.x + u.x + v.x + w.x, pa.y + pb.y + u.y + v.y + w.y,
                        pa.z + pb.z + u.z + v.z + w.z, pa.w + pb.w + u.w + v.w + w.w);
    }
}

// one kernel: all three weight matrices -> fp16 transposed
#define W1N (F1 * KP1)
#define W2N (F2 * F1)
#define W3N (F3 * F2)
__global__ void convW(const float* __restrict__ W1, const float* __restrict__ W2,
                      const float* __restrict__ W3) {
    int idx = blockIdx.x * blockDim.x + threadIdx.x;
    if (idx < W1N) {
        int n = idx / KP1, k = idx % KP1;
        float v = (k < FS) ? W1[(size_t)(250 + k) * F1 + n] : 0.f;
        g_W1T[idx] = __float2half(v);
    } else if (idx < W1N + W2N) {
        int q = idx - W1N;
        int n = q / F1, k = q % F1;
        g_W2T[q] = __float2half(W2[(size_t)k * F2 + n]);
    } else if (idx < W1N + W2N + W3N) {
        int q = idx - W1N - W2N;
        int n = q / F2, k = q % F2;
        g_W3T[q] = __float2half(W3[(size_t)k * F3 + n]);
    }
}

// ======================= mma.sync fp16 GEMM (3-stage, 2 CTAs/SM) =======================
template<int BN>
__device__ __forceinline__ void load_stage(const __half* __restrict__ A,
                                           const __half* __restrict__ B,
                                           int bm, int bn, int Kp, int k0, int M,
                                           uint32_t sA, uint32_t sB) {
    int t = threadIdx.x;
#pragma unroll
    for (int i = 0; i < 4; i++) {
        int idx = t + i * 256;
        int row = idx >> 3, seg = idx & 7;
        int gr = bm + row;
        bool p = gr < M;
        const void* src = A + (size_t)(p ? gr : 0) * Kp + k0 + seg * 8;
        cp16(sA + swz(row * 128 + seg * 16), src, p);
    }
#pragma unroll
    for (int i = 0; i < BN * 8 / 256; i++) {
        int idx = t + i * 256;
        int row = idx >> 3, seg = idx & 7;
        const void* src = B + (size_t)(bn + row) * Kp + k0 + seg * 8;
        cp16(sB + swz(row * 128 + seg * 16), src, true);
    }
}

template<int BN, bool ADD_BASE, bool HALF_OUT>
__global__ __launch_bounds__(256, 2) void mma_gemm(const __half* __restrict__ A,
                                                   const __half* __restrict__ B,
                                                   const float* __restrict__ base,
                                                   void* __restrict__ Cv,
                                                   int M, int Kp, int Nn) {
    extern __shared__ char smem[];
    constexpr int WN = BN / 2;
    constexpr int SS = (128 + BN) * 128;
    uint32_t sb = smem_u32(smem);
    int tid = threadIdx.x, wid = tid >> 5, lane = tid & 31;
    int bm = blockIdx.y * 128, bn = blockIdx.x * BN;
    int wm = (wid & 3) * 32;
    int wn = (wid >> 2) * WN;

    float acc[2][WN / 8][4];
#pragma unroll
    for (int i = 0; i < 2; i++)
#pragma unroll
        for (int j = 0; j < WN / 8; j++)
#pragma unroll
            for (int q = 0; q < 4; q++) acc[i][j][q] = 0.f;

    int nT = Kp >> 6;
#pragma unroll
    for (int s = 0; s < 2; s++) {
        uint32_t sp = sb + (uint32_t)s * SS;
        load_stage<BN>(A, B, bm, bn, Kp, s * 64, M, sp, sp + 128 * 128);
        CP_COMMIT();
    }

    for (int t = 0; t < nT; t++) {
        if (t + 2 < nT) {
            uint32_t sp = sb + (uint32_t)((t + 2) % 3) * SS;
            load_stage<BN>(A, B, bm, bn, Kp, (t + 2) * 64, M, sp, sp + 128 * 128);
        }
        CP_COMMIT();
        CP_WAIT2();
        __syncthreads();

        uint32_t sA = sb + (uint32_t)(t % 3) * SS;
        uint32_t sB = sA + 128 * 128;
#pragma unroll
        for (int ks = 0; ks < 4; ks++) {
            uint32_t af[2][4];
#pragma unroll
            for (int mi = 0; mi < 2; mi++) {
                int row = wm + mi * 16 + (lane & 15);
                ldsm_x4(af[mi], sA + swz(row * 128 + ks * 32 + ((lane >> 4) << 4)));
            }
#pragma unroll
            for (int nj = 0; nj < WN / 16; nj++) {
                uint32_t bf[4];
                int row = wn + nj * 16 + (lane & 7) + ((lane >> 4) << 3);
                ldsm_x4(bf, sB + swz(row * 128 + ks * 32 + (((lane >> 3) & 1) << 4)));
                mma_f16(acc[0][2 * nj],     af[0], bf);
                mma_f16(acc[0][2 * nj + 1], af[0], bf + 2);
                mma_f16(acc[1][2 * nj],     af[1], bf);
                mma_f16(acc[1][2 * nj + 1], af[1], bf + 2);
            }
        }
        __syncthreads();
    }

#pragma unroll
    for (int mi = 0; mi < 2; mi++) {
#pragma unroll
        for (int nj = 0; nj < WN / 8; nj++) {
            int row = bm + wm + mi * 16 + (lane >> 2);
            int col = bn + wn + nj * 8 + (lane & 3) * 2;
#pragma unroll
            for (int h = 0; h < 2; h++) {
                int r = row + h * 8;
                if (r < M) {
                    float2 v = make_float2(acc[mi][nj][h * 2], acc[mi][nj][h * 2 + 1]);
                    if (ADD_BASE) {
                        float2 b2 = *(const float2*)(base + (size_t)r * Nn + col);
                        v.x += b2.x; v.y += b2.y;
                    }
                    if (HALF_OUT) {
                        *(__half2*)((__half*)Cv + (size_t)r * Nn + col) = __floats2half2_rn(v.x, v.y);
                    } else {
                        *(float2*)((float*)Cv + (size_t)r * Nn + col) = v;
                    }
                }
            }
        }
    }
}

// ======================= fused CSR aggregation (fp16 gather, edge prefetch) =======================
template<int F, int NPB>
__global__ __launch_bounds__(128) void csr_agg_h(const __half* __restrict__ t,
                                                 const float* __restrict__ b,
                                                 __half* __restrict__ hs) {
    constexpr int C = F / 8;
    int node = blockIdx.x * NPB + threadIdx.x / C;
    int ch = threadIdx.x % C;
    if (node >= N_NODES) return;
    int beg = g_rp[node], end = g_rp[node + 1];
    const uint4* tv = (const uint4*)t;
    float d = g_dinv[node];
    float dd = d * d;
    float acc[8];
    {
        uint4 sv = tv[(size_t)node * C + ch];
        const __half2* h2 = (const __half2*)&sv;
        float4 b0 = ((const float4*)b)[ch * 2];
        float4 b1v = ((const float4*)b)[ch * 2 + 1];
        float bb[8] = {b0.x, b0.y, b0.z, b0.w, b1v.x, b1v.y, b1v.z, b1v.w};
#pragma unroll
        for (int q = 0; q < 4; q++) {
            float2 f2 = __half22float2(h2[q]);
            acc[q * 2 + 0] = fmaf(f2.x, dd, bb[q * 2 + 0]);
            acc[q * 2 + 1] = fmaf(f2.y, dd, bb[q * 2 + 1]);
        }
    }
    int stop = beg + ((end - beg) & ~3);
    int i = beg;
    int2 e0, e1, e2, e3;
    if (i < stop) {
        e0 = g_edge[i]; e1 = g_edge[i + 1]; e2 = g_edge[i + 2]; e3 = g_edge[i + 3];
    }
    while (i < stop) {
        int j = i + 4;
        int2 f0, f1, f2n, f3;
        if (j < stop) {                       // prefetch next batch of edges
            f0 = g_edge[j]; f1 = g_edge[j + 1]; f2n = g_edge[j + 2]; f3 = g_edge[j + 3];
        }
        uint4 v0 = tv[(size_t)e0.x * C + ch];
        uint4 v1 = tv[(size_t)e1.x * C + ch];
        uint4 v2 = tv[(size_t)e2.x * C + ch];
        uint4 v3 = tv[(size_t)e3.x * C + ch];
        float w0 = __int_as_float(e0.y), w1 = __int_as_float(e1.y);
        float w2 = __int_as_float(e2.y), w3 = __int_as_float(e3.y);
        const __half2* a0 = (const __half2*)&v0;
        const __half2* a1 = (const __half2*)&v1;
        const __half2* a2 = (const __half2*)&v2;
        const __half2* a3 = (const __half2*)&v3;
#pragma unroll
        for (int q = 0; q < 4; q++) {
            float2 g0 = __half22float2(a0[q]);
            float2 g1 = __half22float2(a1[q]);
            float2 g2 = __half22float2(a2[q]);
            float2 g3 = __half22float2(a3[q]);
            acc[q * 2 + 0] += g0.x * w0 + g1.x * w1 + g2.x * w2 + g3.x * w3;
            acc[q * 2 + 1] += g0.y * w0 + g1.y * w1 + g2.y * w2 + g3.y * w3;
        }
        e0 = f0; e1 = f1; e2 = f2n; e3 = f3;
        i = j;
    }
    for (; i < end; i++) {
        int2 eo = g_edge[i];
        float w0 = __int_as_float(eo.y);
        uint4 v0 = tv[(size_t)eo.x * C + ch];
        const __half2* a0 = (const __half2*)&v0;
#pragma unroll
        for (int q = 0; q < 4; q++) {
            float2 g0 = __half22float2(a0[q]);
            acc[q * 2 + 0] += g0.x * w0;
            acc[q * 2 + 1] += g0.y * w0;
        }
    }
    __half h[8];
#pragma unroll
    for (int q = 0; q < 8; q++) {
        float u = acc[q] > 0.f ? acc[q] : 0.01f * acc[q];
        h[q] = __float2half(u);
    }
    *(uint4*)(hs + (size_t)node * F + ch * 8) = *(uint4*)h;
}

// fp32-gather version with fused 64->3 projection (final layer)
template<int F, int NPB>
__global__ __launch_bounds__(128) void csr_agg_proj(const float* __restrict__ t,
                                                    const float* __restrict__ b,
                                                    const float* __restrict__ Wp,
                                                    const float* __restrict__ bp,
                                                    float* __restrict__ out) {
    constexpr int C = F / 4;
    int node = blockIdx.x * NPB + threadIdx.x / C;
    int ch = threadIdx.x % C;
    if (node >= N_NODES) return;
    int beg = g_rp[node], end = g_rp[node + 1];
    const float4* tv = (const float4*)t;
    float d = g_dinv[node];
    float dd = d * d;
    float4 self = tv[(size_t)node * C + ch];
    float4 bv = ((const float4*)b)[ch];
    float4 acc = make_float4(fmaf(self.x, dd, bv.x), fmaf(self.y, dd, bv.y),
                             fmaf(self.z, dd, bv.z), fmaf(self.w, dd, bv.w));
    int stop = beg + ((end - beg) & ~3);
    int i = beg;
    int2 e0, e1, e2, e3;
    if (i < stop) {
        e0 = g_edge[i]; e1 = g_edge[i + 1]; e2 = g_edge[i + 2]; e3 = g_edge[i + 3];
    }
    while (i < stop) {
        int j = i + 4;
        int2 f0, f1, f2n, f3;
        if (j < stop) {
            f0 = g_edge[j]; f1 = g_edge[j + 1]; f2n = g_edge[j + 2]; f3 = g_edge[j + 3];
        }
        float4 v0 = tv[(size_t)e0.x * C + ch];
        float4 v1 = tv[(size_t)e1.x * C + ch];
        float4 v2 = tv[(size_t)e2.x * C + ch];
        float4 v3 = tv[(size_t)e3.x * C + ch];
        float w0 = __int_as_float(e0.y), w1 = __int_as_float(e1.y);
        float w2 = __int_as_float(e2.y), w3 = __int_as_float(e3.y);
        acc.x += v0.x * w0 + v1.x * w1 + v2.x * w2 + v3.x * w3;
        acc.y += v0.y * w0 + v1.y * w1 + v2.y * w2 + v3.y * w3;
        acc.z += v0.z * w0 + v1.z * w1 + v2.z * w2 + v3.z * w3;
        acc.w += v0.w * w0 + v1.w * w1 + v2.w * w2 + v3.w * w3;
        e0 = f0; e1 = f1; e2 = f2n; e3 = f3;
        i = j;
    }
    for (; i < end; i++) {
        int2 eo = g_edge[i];
        float w0 = __int_as_float(eo.y);
        float4 v0 = tv[(size_t)eo.x * C + ch];
        acc.x += v0.x * w0; acc.y += v0.y * w0; acc.z += v0.z * w0; acc.w += v0.w * w0;
    }
    float f[4] = {acc.x, acc.y, acc.z, acc.w};
#pragma unroll
    for (int q = 0; q < 4; q++) f[q] = f[q] > 0.f ? f[q] : 0.01f * f[q];
    float a0 = 0.f, a1 = 0.f, a2 = 0.f;
#pragma unroll
    for (int q = 0; q < 4; q++) {
        int k = ch * 4 + q;
        a0 = fmaf(f[q], __ldg(Wp + k * 3 + 0), a0);
        a1 = fmaf(f[q], __ldg(Wp + k * 3 + 1), a1);
        a2 = fmaf(f[q], __ldg(Wp + k * 3 + 2), a2);
    }
#pragma unroll
    for (int off = C / 2; off; off >>= 1) {
        a0 += __shfl_down_sync(0xffffffffu, a0, off, C);
        a1 += __shfl_down_sync(0xffffffffu, a1, off, C);
        a2 += __shfl_down_sync(0xffffffffu, a2, off, C);
    }
    if (ch == 0) {
        out[(size_t)node * 3 + 0] = a0 + bp[0];
        out[(size_t)node * 3 + 1] = a1 + bp[1];
        out[(size_t)node * 3 + 2] = a2 + bp[2];
    }
}

// ======================= launch =======================
extern "C" void kernel_launch(void* const* d_in, const int* in_sizes, int n_in,
                              void* d_out, int out_size) {
    const float* x           = (const float*)d_in[0];
    const int*   edge_index  = (const int*)  d_in[1];
    const float* edge_attr   = (const float*)d_in[2];
    const float* layer_table = (const float*)d_in[3];
    const float* rel_table   = (const float*)d_in[4];
    const float* color_table = (const float*)d_in[5];
    const float* W1 = (const float*)d_in[6];
    const float* b1 = (const float*)d_in[7];
    const float* W2 = (const float*)d_in[8];
    const float* b2 = (const float*)d_in[9];
    const float* W3 = (const float*)d_in[10];
    const float* b3 = (const float*)d_in[11];
    const float* Wp = (const float*)d_in[12];
    const float* bp = (const float*)d_in[13];
    float* out = (float*)d_out;

    __half *p_A2, *p_h2s, *p_W1T, *p_W2T, *p_W3T;
    float *p_base, *p_t;
    cudaGetSymbolAddress((void**)&p_A2,   g_A2);
    cudaGetSymbolAddress((void**)&p_h2s,  g_h2s);
    cudaGetSymbolAddress((void**)&p_W1T,  g_W1T);
    cudaGetSymbolAddress((void**)&p_W2T,  g_W2T);
    cudaGetSymbolAddress((void**)&p_W3T,  g_W3T);
    cudaGetSymbolAddress((void**)&p_base, g_base);
    cudaGetSymbolAddress((void**)&p_t,    g_t);
    __half* p_th = (__half*)p_t;

    const int T = 256;
    const int SM128 = 3 * (128 + 128) * 128;   // 98304
    const int SM64  = 3 * (128 + 64) * 128;    // 73728
    cudaFuncSetAttribute((const void*)mma_gemm<128, true,  true>,  cudaFuncAttributeMaxDynamicSharedMemorySize, SM128);
    cudaFuncSetAttribute((const void*)mma_gemm<128, false, true>,  cudaFuncAttributeMaxDynamicSharedMemorySize, SM128);
    cudaFuncSetAttribute((const void*)mma_gemm<64,  false, false>, cudaFuncAttributeMaxDynamicSharedMemorySize, SM64);

    // graph prep
    zero_both<<<(N_NODES + T - 1) / T, T>>>();
    deg_kernel<<<(N_EDGES + T - 1) / T, T>>>(edge_index, edge_attr);
    scan_kernel<<<1, 1024>>>();
    scatter_kernel<<<(N_EDGES + T - 1) / T, T>>>(edge_index, edge_attr);

    // weights -> fp16 transposed; table precomputations; node base + resnet fp16
    convW<<<(W1N + W2N + W3N + T - 1) / T, T>>>(W1, W2, W3);
    pre_all<<<782, 512>>>(layer_table, rel_table, color_table, W1);
    split_base<<<N_NODES, T>>>(x);

    const int MT = (N_NODES + 127) / 128;   // 157

    // ---- layer 1 (t stored fp16) ----
    mma_gemm<128, true, true><<<dim3(F1 / 128, MT), T, SM128>>>(p_A2, p_W1T, p_base, p_th, N_NODES, KP1, F1);
    csr_agg_h<F1, 2><<<(N_NODES + 1) / 2, 128>>>(p_th, b1, p_h2s);

    // ---- layer 2 (t stored fp16) ----
    mma_gemm<128, false, true><<<dim3(F2 / 128, MT), T, SM128>>>(p_h2s, p_W2T, nullptr, p_th, N_NODES, F1, F2);
    csr_agg_h<F2, 4><<<(N_NODES + 3) / 4, 128>>>(p_th, b2, p_h2s);

    // ---- layer 3 (t fp32, projection fused) ----
    mma_gemm<64, false, false><<<dim3(F3 / 64, MT), T, SM64>>>(p_h2s, p_W3T, nullptr, p_t, N_NODES, F2, F3);
    csr_agg_proj<F3, 8><<<(N_NODES + 7) / 8, 128>>>(p_t, b3, Wp, bp, out);
}

// round 13
// speedup vs baseline: 5.4848x; 1.0704x over previous
#include <cuda_runtime.h>
#include <cuda_fp16.h>
#include <math.h>
#include <stdint.h>

#define N_NODES 20000
#define N_EDGES 320000
#define FS      1000
#define XCOLS   1005
#define F1      512
#define F2      256
#define F3      64
#define KP1     1024             // padded resnet K

// ======================= static scratch =======================
__device__ __half g_A2 [(size_t)N_NODES * KP1];
__device__ __half g_h2s[(size_t)N_NODES * F1];
__device__ __half g_W1T[(size_t)F1 * KP1];
__device__ __half g_W2T[(size_t)F2 * F1];
__device__ __half g_W3T[(size_t)F3 * F2];
__device__ float g_base[(size_t)N_NODES * F1];
__device__ float g_t   [(size_t)N_NODES * F1];
__device__ float g_dinv[N_NODES];
__device__ float g_preL[3 * F1];
__device__ float g_preR[11 * F1];
__device__ float g_preC[3 * 256 * F1];
__device__ int   g_degi[N_NODES];
__device__ int   g_rp[N_NODES + 1];
__device__ int   g_cursor[N_NODES];
__device__ int2  g_edge[N_EDGES];

// ======================= PTX helpers =======================
__device__ __forceinline__ uint32_t smem_u32(const void* p) {
    uint32_t a;
    asm("{ .reg .u64 t; cvta.to.shared.u64 t, %1; cvt.u32.u64 %0, t; }" : "=r"(a) : "l"(p));
    return a;
}
__device__ __forceinline__ void cp16(uint32_t dst, const void* src, bool pred) {
    int sz = pred ? 16 : 0;
    asm volatile("cp.async.cg.shared.global [%0], [%1], 16, %2;"
                 :: "r"(dst), "l"(src), "r"(sz) : "memory");
}
#define CP_COMMIT() asm volatile("cp.async.commit_group;" ::: "memory")
#define CP_WAIT2()  asm volatile("cp.async.wait_group 2;" ::: "memory")

__device__ __forceinline__ void ldsm_x4(uint32_t* r, uint32_t addr) {
    asm volatile("ldmatrix.sync.aligned.m8n8.x4.shared.b16 {%0,%1,%2,%3}, [%4];"
                 : "=r"(r[0]), "=r"(r[1]), "=r"(r[2]), "=r"(r[3]) : "r"(addr));
}
__device__ __forceinline__ void mma_f16(float* d, const uint32_t* a, const uint32_t* b) {
    asm volatile("mma.sync.aligned.m16n8k16.row.col.f32.f16.f16.f32 "
                 "{%0,%1,%2,%3}, {%4,%5,%6,%7}, {%8,%9}, {%0,%1,%2,%3};"
                 : "+f"(d[0]), "+f"(d[1]), "+f"(d[2]), "+f"(d[3])
                 : "r"(a[0]), "r"(a[1]), "r"(a[2]), "r"(a[3]), "r"(b[0]), "r"(b[1]));
}
__device__ __forceinline__ uint32_t swz(uint32_t off) { return off ^ ((off >> 3) & 0x70); }

// ======================= prep kernels =======================
__global__ void zero_both() {
    int i = blockIdx.x * blockDim.x + threadIdx.x;
    if (i < N_NODES) { g_dinv[i] = 0.f; g_degi[i] = 0; }
}
__global__ void deg_kernel(const int* __restrict__ ei, const float* __restrict__ ea) {
    int e = blockIdx.x * blockDim.x + threadIdx.x;
    if (e < N_EDGES) {
        int dst = ei[N_EDGES + e];
        atomicAdd(&g_dinv[dst], ea[e]);
        atomicAdd(&g_degi[dst], 1);
    }
}
__global__ void scan_kernel() {
    __shared__ int sh[1024];
    const int CH = (N_NODES + 1023) / 1024;
    int tid = threadIdx.x;
    int base = tid * CH;
    int s = 0;
    for (int j = 0; j < CH; j++) {
        int i = base + j;
        if (i < N_NODES) {
            g_dinv[i] = rsqrtf(g_dinv[i] + 1.0f);
            s += g_degi[i];
        }
    }
    sh[tid] = s;
    __syncthreads();
    for (int off = 1; off < 1024; off <<= 1) {
        int v = (tid >= off) ? sh[tid - off] : 0;
        __syncthreads();
        sh[tid] += v;
        __syncthreads();
    }
    int run = tid ? sh[tid - 1] : 0;
    for (int j = 0; j < CH; j++) {
        int i = base + j;
        if (i < N_NODES) {
            g_rp[i] = run;
            g_cursor[i] = run;
            run += g_degi[i];
        }
    }
    if (tid == 1023) g_rp[N_NODES] = sh[1023];
}
__global__ void scatter_kernel(const int* __restrict__ ei, const float* __restrict__ ea) {
    int e = blockIdx.x * blockDim.x + threadIdx.x;
    if (e >= N_EDGES) return;
    int src = ei[e];
    int dst = ei[N_EDGES + e];
    float w = g_dinv[src] * ea[e] * g_dinv[dst];
    int pos = atomicAdd(&g_cursor[dst], 1);
    g_edge[pos] = make_int2(src, __float_as_int(w));
}

__global__ void pre_all(const float* __restrict__ layer_table, const float* __restrict__ rel_table,
                        const float* __restrict__ color_table, const float* __restrict__ W1) {
    __shared__ float s[256];
    int b = blockIdx.x, j = threadIdx.x;
    const float* tab;
    float* outp;
    int Kt, off;
    if (b < 3)       { tab = layer_table + (size_t)b * 250;        outp = g_preL + (size_t)b * F1;        Kt = 250; off = 0; }
    else if (b < 14) { tab = rel_table + (size_t)(b - 3) * 250;    outp = g_preR + (size_t)(b - 3) * F1;  Kt = 250; off = 1250; }
    else {
        int q = b - 14;
        int p = q >> 8, c = q & 255;
        tab = color_table + (size_t)c * 85;
        outp = g_preC + (size_t)q * F1;
        Kt = 85; off = 1500 + 85 * p;
    }
    if (j < Kt) s[j] = tab[j];
    __syncthreads();
    float acc = 0.f;
    for (int k = 0; k < Kt; k++) acc = fmaf(s[k], W1[(size_t)(off + k) * F1 + j], acc);
    outp[j] = acc;
}

__global__ void split_base(const float* __restrict__ x) {
    int i = blockIdx.x;
    const float* xr = x + (size_t)i * XCOLS;
    __half* a = g_A2 + (size_t)i * KP1;
    for (int k = threadIdx.x; k < KP1; k += blockDim.x) {
        float v = (k < FS) ? xr[1 + k] : 0.f;
        a[k] = __float2half(v);
    }
    int j = threadIdx.x;
    if (j < 128) {
        int li = (int)xr[0] - 1;
        int ri = __float2int_rn(fabsf(xr[FS + 1]) * 10.0f);
        int c0 = (int)xr[XCOLS - 3];
        int c1 = (int)xr[XCOLS - 2];
        int c2 = (int)xr[XCOLS - 1];
        float4 pa = ((const float4*)(g_preL + (size_t)li * F1))[j];
        float4 pb = ((const float4*)(g_preR + (size_t)ri * F1))[j];
        float4 u = ((const float4*)(g_preC + ((size_t)(0 * 256 + c0)) * F1))[j];
        float4 v = ((const float4*)(g_preC + ((size_t)(1 * 256 + c1)) * F1))[j];
        float4 w = ((const float4*)(g_preC + ((size_t)(2 * 256 + c2)) * F1))[j];
        ((float4*)(g_base + (size_t)i * F1))[j] =
            make_float4(pa.x + pb.x + u.x + v.x + w.x, pa.y + pb.y + u.y + v.y + w.y,
                        pa.z + pb.z + u.z + v.z + w.z, pa.w + pb.w + u.w + v.w + w.w);
    }
}

#define W1N (F1 * KP1)
#define W2N (F2 * F1)
#define W3N (F3 * F2)
__global__ void convW(const float* __restrict__ W1, const float* __restrict__ W2,
                      const float* __restrict__ W3) {
    int idx = blockIdx.x * blockDim.x + threadIdx.x;
    if (idx < W1N) {
        int n = idx / KP1, k = idx % KP1;
        float v = (k < FS) ? W1[(size_t)(250 + k) * F1 + n] : 0.f;
        g_W1T[idx] = __float2half(v);
    } else if (idx < W1N + W2N) {
        int q = idx - W1N;
        int n = q / F1, k = q % F1;
        g_W2T[q] = __float2half(W2[(size_t)k * F2 + n]);
    } else if (idx < W1N + W2N + W3N) {
        int q = idx - W1N - W2N;
        int n = q / F2, k = q % F2;
        g_W3T[q] = __float2half(W3[(size_t)k * F3 + n]);
    }
}

// ======================= mma.sync fp16 GEMM (3-stage, 2 CTAs/SM) =======================
template<int BN>
__device__ __forceinline__ void load_stage(const __half* __restrict__ A,
                                           const __half* __restrict__ B,
                                           int bm, int bn, int Kp, int k0, int M,
                                           uint32_t sA, uint32_t sB) {
    int t = threadIdx.x;
#pragma unroll
    for (int i = 0; i < 4; i++) {
        int idx = t + i * 256;
        int row = idx >> 3, seg = idx & 7;
        int gr = bm + row;
        bool p = gr < M;
        const void* src = A + (size_t)(p ? gr : 0) * Kp + k0 + seg * 8;
        cp16(sA + swz(row * 128 + seg * 16), src, p);
    }
#pragma unroll
    for (int i = 0; i < BN * 8 / 256; i++) {
        int idx = t + i * 256;
        int row = idx >> 3, seg = idx & 7;
        const void* src = B + (size_t)(bn + row) * Kp + k0 + seg * 8;
        cp16(sB + swz(row * 128 + seg * 16), src, true);
    }
}

template<int BN, bool ADD_BASE, bool HALF_OUT>
__global__ __launch_bounds__(256, 2) void mma_gemm(const __half* __restrict__ A,
                                                   const __half* __restrict__ B,
                                                   const float* __restrict__ base,
                                                   void* __restrict__ Cv,
                                                   int M, int Kp, int Nn) {
    extern __shared__ char smem[];
    constexpr int WN = BN / 2;
    constexpr int SS = (128 + BN) * 128;
    uint32_t sb = smem_u32(smem);
    int tid = threadIdx.x, wid = tid >> 5, lane = tid & 31;
    int bm = blockIdx.y * 128, bn = blockIdx.x * BN;
    int wm = (wid & 3) * 32;
    int wn = (wid >> 2) * WN;

    float acc[2][WN / 8][4];
#pragma unroll
    for (int i = 0; i < 2; i++)
#pragma unroll
        for (int j = 0; j < WN / 8; j++)
#pragma unroll
            for (int q = 0; q < 4; q++) acc[i][j][q] = 0.f;

    int nT = Kp >> 6;
#pragma unroll
    for (int s = 0; s < 2; s++) {
        uint32_t sp = sb + (uint32_t)s * SS;
        load_stage<BN>(A, B, bm, bn, Kp, s * 64, M, sp, sp + 128 * 128);
        CP_COMMIT();
    }

    for (int t = 0; t < nT; t++) {
        if (t + 2 < nT) {
            uint32_t sp = sb + (uint32_t)((t + 2) % 3) * SS;
            load_stage<BN>(A, B, bm, bn, Kp, (t + 2) * 64, M, sp, sp + 128 * 128);
        }
        CP_COMMIT();
        CP_WAIT2();
        __syncthreads();

        uint32_t sA = sb + (uint32_t)(t % 3) * SS;
        uint32_t sB = sA + 128 * 128;
#pragma unroll
        for (int ks = 0; ks < 4; ks++) {
            uint32_t af[2][4];
#pragma unroll
            for (int mi = 0; mi < 2; mi++) {
                int row = wm + mi * 16 + (lane & 15);
                ldsm_x4(af[mi], sA + swz(row * 128 + ks * 32 + ((lane >> 4) << 4)));
            }
#pragma unroll
            for (int nj = 0; nj < WN / 16; nj++) {
                uint32_t bf[4];
                int row = wn + nj * 16 + (lane & 7) + ((lane >> 4) << 3);
                ldsm_x4(bf, sB + swz(row * 128 + ks * 32 + (((lane >> 3) & 1) << 4)));
                mma_f16(acc[0][2 * nj],     af[0], bf);
                mma_f16(acc[0][2 * nj + 1], af[0], bf + 2);
                mma_f16(acc[1][2 * nj],     af[1], bf);
                mma_f16(acc[1][2 * nj + 1], af[1], bf + 2);
            }
        }
        __syncthreads();
    }

#pragma unroll
    for (int mi = 0; mi < 2; mi++) {
#pragma unroll
        for (int nj = 0; nj < WN / 8; nj++) {
            int row = bm + wm + mi * 16 + (lane >> 2);
            int col = bn + wn + nj * 8 + (lane & 3) * 2;
#pragma unroll
            for (int h = 0; h < 2; h++) {
                int r = row + h * 8;
                if (r < M) {
                    float2 v = make_float2(acc[mi][nj][h * 2], acc[mi][nj][h * 2 + 1]);
                    if (ADD_BASE) {
                        float2 b2 = *(const float2*)(base + (size_t)r * Nn + col);
                        v.x += b2.x; v.y += b2.y;
                    }
                    if (HALF_OUT) {
                        *(__half2*)((__half*)Cv + (size_t)r * Nn + col) = __floats2half2_rn(v.x, v.y);
                    } else {
                        *(float2*)((float*)Cv + (size_t)r * Nn + col) = v;
                    }
                }
            }
        }
    }
}

// ======================= fused CSR aggregation (fp16 gather, edge prefetch) =======================
template<int F, int NPB>
__global__ __launch_bounds__(128) void csr_agg_h(const __half* __restrict__ t,
                                                 const float* __restrict__ b,
                                                 __half* __restrict__ hs) {
    constexpr int C = F / 8;
    int node = blockIdx.x * NPB + threadIdx.x / C;
    int ch = threadIdx.x % C;
    if (node >= N_NODES) return;
    int beg = g_rp[node], end = g_rp[node + 1];
    const uint4* tv = (const uint4*)t;
    float d = g_dinv[node];
    float dd = d * d;
    float acc[8];
    {
        uint4 sv = tv[(size_t)node * C + ch];
        const __half2* h2 = (const __half2*)&sv;
        float4 b0 = ((const float4*)b)[ch * 2];
        float4 b1v = ((const float4*)b)[ch * 2 + 1];
        float bb[8] = {b0.x, b0.y, b0.z, b0.w, b1v.x, b1v.y, b1v.z, b1v.w};
#pragma unroll
        for (int q = 0; q < 4; q++) {
            float2 f2 = __half22float2(h2[q]);
            acc[q * 2 + 0] = fmaf(f2.x, dd, bb[q * 2 + 0]);
            acc[q * 2 + 1] = fmaf(f2.y, dd, bb[q * 2 + 1]);
        }
    }
    int stop = beg + ((end - beg) & ~3);
    int i = beg;
    int2 e0, e1, e2, e3;
    if (i < stop) {
        e0 = g_edge[i]; e1 = g_edge[i + 1]; e2 = g_edge[i + 2]; e3 = g_edge[i + 3];
    }
    while (i < stop) {
        int j = i + 4;
        int2 f0, f1, f2n, f3;
        if (j < stop) {
            f0 = g_edge[j]; f1 = g_edge[j + 1]; f2n = g_edge[j + 2]; f3 = g_edge[j + 3];
        }
        uint4 v0 = tv[(size_t)e0.x * C + ch];
        uint4 v1 = tv[(size_t)e1.x * C + ch];
        uint4 v2 = tv[(size_t)e2.x * C + ch];
        uint4 v3 = tv[(size_t)e3.x * C + ch];
        float w0 = __int_as_float(e0.y), w1 = __int_as_float(e1.y);
        float w2 = __int_as_float(e2.y), w3 = __int_as_float(e3.y);
        const __half2* a0 = (const __half2*)&v0;
        const __half2* a1 = (const __half2*)&v1;
        const __half2* a2 = (const __half2*)&v2;
        const __half2* a3 = (const __half2*)&v3;
#pragma unroll
        for (int q = 0; q < 4; q++) {
            float2 g0 = __half22float2(a0[q]);
            float2 g1 = __half22float2(a1[q]);
            float2 g2 = __half22float2(a2[q]);
            float2 g3 = __half22float2(a3[q]);
            acc[q * 2 + 0] += g0.x * w0 + g1.x * w1 + g2.x * w2 + g3.x * w3;
            acc[q * 2 + 1] += g0.y * w0 + g1.y * w1 + g2.y * w2 + g3.y * w3;
        }
        e0 = f0; e1 = f1; e2 = f2n; e3 = f3;
        i = j;
    }
    for (; i < end; i++) {
        int2 eo = g_edge[i];
        float w0 = __int_as_float(eo.y);
        uint4 v0 = tv[(size_t)eo.x * C + ch];
        const __half2* a0 = (const __half2*)&v0;
#pragma unroll
        for (int q = 0; q < 4; q++) {
            float2 g0 = __half22float2(a0[q]);
            acc[q * 2 + 0] += g0.x * w0;
            acc[q * 2 + 1] += g0.y * w0;
        }
    }
    __half h[8];
#pragma unroll
    for (int q = 0; q < 8; q++) {
        float u = acc[q] > 0.f ? acc[q] : 0.01f * acc[q];
        h[q] = __float2half(u);
    }
    *(uint4*)(hs + (size_t)node * F + ch * 8) = *(uint4*)h;
}

template<int F, int NPB>
__global__ __launch_bounds__(128) void csr_agg_proj(const float* __restrict__ t,
                                                    const float* __restrict__ b,
                                                    const float* __restrict__ Wp,
                                                    const float* __restrict__ bp,
                                                    float* __restrict__ out) {
    constexpr int C = F / 4;
    int node = blockIdx.x * NPB + threadIdx.x / C;
    int ch = threadIdx.x % C;
    if (node >= N_NODES) return;
    int beg = g_rp[node], end = g_rp[node + 1];
    const float4* tv = (const float4*)t;
    float d = g_dinv[node];
    float dd = d * d;
    float4 self = tv[(size_t)node * C + ch];
    float4 bv = ((const float4*)b)[ch];
    float4 acc = make_float4(fmaf(self.x, dd, bv.x), fmaf(self.y, dd, bv.y),
                             fmaf(self.z, dd, bv.z), fmaf(self.w, dd, bv.w));
    int stop = beg + ((end - beg) & ~3);
    int i = beg;
    int2 e0, e1, e2, e3;
    if (i < stop) {
        e0 = g_edge[i]; e1 = g_edge[i + 1]; e2 = g_edge[i + 2]; e3 = g_edge[i + 3];
    }
    while (i < stop) {
        int j = i + 4;
        int2 f0, f1, f2n, f3;
        if (j < stop) {
            f0 = g_edge[j]; f1 = g_edge[j + 1]; f2n = g_edge[j + 2]; f3 = g_edge[j + 3];
        }
        float4 v0 = tv[(size_t)e0.x * C + ch];
        float4 v1 = tv[(size_t)e1.x * C + ch];
        float4 v2 = tv[(size_t)e2.x * C + ch];
        float4 v3 = tv[(size_t)e3.x * C + ch];
        float w0 = __int_as_float(e0.y), w1 = __int_as_float(e1.y);
        float w2 = __int_as_float(e2.y), w3 = __int_as_float(e3.y);
        acc.x += v0.x * w0 + v1.x * w1 + v2.x * w2 + v3.x * w3;
        acc.y += v0.y * w0 + v1.y * w1 + v2.y * w2 + v3.y * w3;
        acc.z += v0.z * w0 + v1.z * w1 + v2.z * w2 + v3.z * w3;
        acc.w += v0.w * w0 + v1.w * w1 + v2.w * w2 + v3.w * w3;
        e0 = f0; e1 = f1; e2 = f2n; e3 = f3;
        i = j;
    }
    for (; i < end; i++) {
        int2 eo = g_edge[i];
        float w0 = __int_as_float(eo.y);
        float4 v0 = tv[(size_t)eo.x * C + ch];
        acc.x += v0.x * w0; acc.y += v0.y * w0; acc.z += v0.z * w0; acc.w += v0.w * w0;
    }
    float f[4] = {acc.x, acc.y, acc.z, acc.w};
#pragma unroll
    for (int q = 0; q < 4; q++) f[q] = f[q] > 0.f ? f[q] : 0.01f * f[q];
    float a0 = 0.f, a1 = 0.f, a2 = 0.f;
#pragma unroll
    for (int q = 0; q < 4; q++) {
        int k = ch * 4 + q;
        a0 = fmaf(f[q], __ldg(Wp + k * 3 + 0), a0);
        a1 = fmaf(f[q], __ldg(Wp + k * 3 + 1), a1);
        a2 = fmaf(f[q], __ldg(Wp + k * 3 + 2), a2);
    }
#pragma unroll
    for (int off = C / 2; off; off >>= 1) {
        a0 += __shfl_down_sync(0xffffffffu, a0, off, C);
        a1 += __shfl_down_sync(0xffffffffu, a1, off, C);
        a2 += __shfl_down_sync(0xffffffffu, a2, off, C);
    }
    if (ch == 0) {
        out[(size_t)node * 3 + 0] = a0 + bp[0];
        out[(size_t)node * 3 + 1] = a1 + bp[1];
        out[(size_t)node * 3 + 2] = a2 + bp[2];
    }
}

// ======================= launch =======================
extern "C" void kernel_launch(void* const* d_in, const int* in_sizes, int n_in,
                              void* d_out, int out_size) {
    const float* x           = (const float*)d_in[0];
    const int*   edge_index  = (const int*)  d_in[1];
    const float* edge_attr   = (const float*)d_in[2];
    const float* layer_table = (const float*)d_in[3];
    const float* rel_table   = (const float*)d_in[4];
    const float* color_table = (const float*)d_in[5];
    const float* W1 = (const float*)d_in[6];
    const float* b1 = (const float*)d_in[7];
    const float* W2 = (const float*)d_in[8];
    const float* b2 = (const float*)d_in[9];
    const float* W3 = (const float*)d_in[10];
    const float* b3 = (const float*)d_in[11];
    const float* Wp = (const float*)d_in[12];
    const float* bp = (const float*)d_in[13];
    float* out = (float*)d_out;

    __half *p_A2, *p_h2s, *p_W1T, *p_W2T, *p_W3T;
    float *p_base, *p_t;
    cudaGetSymbolAddress((void**)&p_A2,   g_A2);
    cudaGetSymbolAddress((void**)&p_h2s,  g_h2s);
    cudaGetSymbolAddress((void**)&p_W1T,  g_W1T);
    cudaGetSymbolAddress((void**)&p_W2T,  g_W2T);
    cudaGetSymbolAddress((void**)&p_W3T,  g_W3T);
    cudaGetSymbolAddress((void**)&p_base, g_base);
    cudaGetSymbolAddress((void**)&p_t,    g_t);
    __half* p_th = (__half*)p_t;

    const int T = 256;
    const int SM128 = 3 * (128 + 128) * 128;   // 98304
    const int SM64  = 3 * (128 + 64) * 128;    // 73728
    cudaFuncSetAttribute((const void*)mma_gemm<128, true,  true>,  cudaFuncAttributeMaxDynamicSharedMemorySize, SM128);
    cudaFuncSetAttribute((const void*)mma_gemm<128, false, true>,  cudaFuncAttributeMaxDynamicSharedMemorySize, SM128);
    cudaFuncSetAttribute((const void*)mma_gemm<64,  false, false>, cudaFuncAttributeMaxDynamicSharedMemorySize, SM64);

    // Fork a side branch for the CSR build (independent of GEMM-input prep + GEMM1).
    // In capture mode this records two parallel graph branches; streams/events are
    // NOT destroyed here (destroying a captured stream before EndCapture is illegal);
    // they hold no tracked device memory.
    cudaStream_t s2;
    cudaStreamCreateWithFlags(&s2, cudaStreamNonBlocking);
    cudaEvent_t evFork, evJoin;
    cudaEventCreateWithFlags(&evFork, cudaEventDisableTiming);
    cudaEventCreateWithFlags(&evJoin, cudaEventDisableTiming);

    cudaEventRecord(evFork, 0);
    cudaStreamWaitEvent(s2, evFork, 0);

    // ---- side branch: graph prep (CSR) ----
    zero_both<<<(N_NODES + T - 1) / T, T, 0, s2>>>();
    deg_kernel<<<(N_EDGES + T - 1) / T, T, 0, s2>>>(edge_index, edge_attr);
    scan_kernel<<<1, 1024, 0, s2>>>();
    scatter_kernel<<<(N_EDGES + T - 1) / T, T, 0, s2>>>(edge_index, edge_attr);
    cudaEventRecord(evJoin, s2);

    // ---- main branch: GEMM inputs + GEMM1 ----
    convW<<<(W1N + W2N + W3N + T - 1) / T, T>>>(W1, W2, W3);
    pre_all<<<782, 512>>>(layer_table, rel_table, color_table, W1);
    split_base<<<N_NODES, T>>>(x);

    const int MT = (N_NODES + 127) / 128;   // 157

    mma_gemm<128, true, true><<<dim3(F1 / 128, MT), T, SM128>>>(p_A2, p_W1T, p_base, p_th, N_NODES, KP1, F1);

    // join: aggregation needs the CSR
    cudaStreamWaitEvent(0, evJoin, 0);

    csr_agg_h<F1, 2><<<(N_NODES + 1) / 2, 128>>>(p_th, b1, p_h2s);

    // ---- layer 2 ----
    mma_gemm<128, false, true><<<dim3(F2 / 128, MT), T, SM128>>>(p_h2s, p_W2T, nullptr, p_th, N_NODES, F1, F2);
    csr_agg_h<F2, 4><<<(N_NODES + 3) / 4, 128>>>(p_th, b2, p_h2s);

    // ---- layer 3 (projection fused) ----
    mma_gemm<64, false, false><<<dim3(F3 / 64, MT), T, SM64>>>(p_h2s, p_W3T, nullptr, p_t, N_NODES, F2, F3);
    csr_agg_proj<F3, 8><<<(N_NODES + 7) / 8, 128>>>(p_t, b3, Wp, bp, out);
}

// round 15
// speedup vs baseline: 5.6845x; 1.0364x over previous
#include <cuda_runtime.h>
#include <cuda_fp16.h>
#include <math.h>
#include <stdint.h>

#define N_NODES 20000
#define N_EDGES 320000
#define FS      1000
#define XCOLS   1005
#define F1      512
#define F2      256
#define F3      64
#define KP1     1024             // padded resnet K

// ======================= static scratch =======================
__device__ __half g_A2 [(size_t)N_NODES * KP1];
__device__ __half g_h2s[(size_t)N_NODES * F1];   // layer-1 activations (GEMM2 input)
__device__ __half g_h3s[(size_t)N_NODES * F2];   // layer-2 activations (GEMM3 input) -- no aliasing with g_h2s
__device__ __half g_W1T[(size_t)F1 * KP1];
__device__ __half g_W2T[(size_t)F2 * F1];
__device__ __half g_W3T[(size_t)F3 * F2];
__device__ float g_base[(size_t)N_NODES * F1];
__device__ float g_t   [(size_t)N_NODES * F1];
__device__ float g_dinv[N_NODES];
__device__ float g_preL[3 * F1];
__device__ float g_preR[11 * F1];
__device__ float g_preC[3 * 256 * F1];
__device__ int   g_degi[N_NODES];
__device__ int   g_rp[N_NODES + 1];
__device__ int   g_cursor[N_NODES];
__device__ int2  g_edge[N_EDGES];

// ======================= PTX helpers =======================
__device__ __forceinline__ uint32_t smem_u32(const void* p) {
    uint32_t a;
    asm("{ .reg .u64 t; cvta.to.shared.u64 t, %1; cvt.u32.u64 %0, t; }" : "=r"(a) : "l"(p));
    return a;
}
__device__ __forceinline__ void cp16(uint32_t dst, const void* src, bool pred) {
    int sz = pred ? 16 : 0;
    asm volatile("cp.async.cg.shared.global [%0], [%1], 16, %2;"
                 :: "r"(dst), "l"(src), "r"(sz) : "memory");
}
#define CP_COMMIT() asm volatile("cp.async.commit_group;" ::: "memory")
#define CP_WAIT2()  asm volatile("cp.async.wait_group 2;" ::: "memory")

__device__ __forceinline__ void ldsm_x4(uint32_t* r, uint32_t addr) {
    asm volatile("ldmatrix.sync.aligned.m8n8.x4.shared.b16 {%0,%1,%2,%3}, [%4];"
                 : "=r"(r[0]), "=r"(r[1]), "=r"(r[2]), "=r"(r[3]) : "r"(addr));
}
__device__ __forceinline__ void mma_f16(float* d, const uint32_t* a, const uint32_t* b) {
    asm volatile("mma.sync.aligned.m16n8k16.row.col.f32.f16.f16.f32 "
                 "{%0,%1,%2,%3}, {%4,%5,%6,%7}, {%8,%9}, {%0,%1,%2,%3};"
                 : "+f"(d[0]), "+f"(d[1]), "+f"(d[2]), "+f"(d[3])
                 : "r"(a[0]), "r"(a[1]), "r"(a[2]), "r"(a[3]), "r"(b[0]), "r"(b[1]));
}
__device__ __forceinline__ uint32_t swz(uint32_t off) { return off ^ ((off >> 3) & 0x70); }

// ======================= prep kernels =======================
__global__ void zero_both() {
    int i = blockIdx.x * blockDim.x + threadIdx.x;
    if (i < N_NODES) { g_dinv[i] = 0.f; g_degi[i] = 0; }
}
__global__ void deg_kernel(const int* __restrict__ ei, const float* __restrict__ ea) {
    int e = blockIdx.x * blockDim.x + threadIdx.x;
    if (e < N_EDGES) {
        int dst = ei[N_EDGES + e];
        atomicAdd(&g_dinv[dst], ea[e]);
        atomicAdd(&g_degi[dst], 1);
    }
}
__global__ void scan_kernel() {
    __shared__ int sh[1024];
    const int CH = (N_NODES + 1023) / 1024;
    int tid = threadIdx.x;
    int base = tid * CH;
    int s = 0;
    for (int j = 0; j < CH; j++) {
        int i = base + j;
        if (i < N_NODES) {
            g_dinv[i] = rsqrtf(g_dinv[i] + 1.0f);
            s += g_degi[i];
        }
    }
    sh[tid] = s;
    __syncthreads();
    for (int off = 1; off < 1024; off <<= 1) {
        int v = (tid >= off) ? sh[tid - off] : 0;
        __syncthreads();
        sh[tid] += v;
        __syncthreads();
    }
    int run = tid ? sh[tid - 1] : 0;
    for (int j = 0; j < CH; j++) {
        int i = base + j;
        if (i < N_NODES) {
            g_rp[i] = run;
            g_cursor[i] = run;
            run += g_degi[i];
        }
    }
    if (tid == 1023) g_rp[N_NODES] = sh[1023];
}
__global__ void scatter_kernel(const int* __restrict__ ei, const float* __restrict__ ea) {
    int e = blockIdx.x * blockDim.x + threadIdx.x;
    if (e >= N_EDGES) return;
    int src = ei[e];
    int dst = ei[N_EDGES + e];
    float w = g_dinv[src] * ea[e] * g_dinv[dst];
    int pos = atomicAdd(&g_cursor[dst], 1);
    g_edge[pos] = make_int2(src, __float_as_int(w));
}

__global__ void pre_all(const float* __restrict__ layer_table, const float* __restrict__ rel_table,
                        const float* __restrict__ color_table, const float* __restrict__ W1) {
    __shared__ float s[256];
    int b = blockIdx.x, j = threadIdx.x;
    const float* tab;
    float* outp;
    int Kt, off;
    if (b < 3)       { tab = layer_table + (size_t)b * 250;        outp = g_preL + (size_t)b * F1;        Kt = 250; off = 0; }
    else if (b < 14) { tab = rel_table + (size_t)(b - 3) * 250;    outp = g_preR + (size_t)(b - 3) * F1;  Kt = 250; off = 1250; }
    else {
        int q = b - 14;
        int p = q >> 8, c = q & 255;
        tab = color_table + (size_t)c * 85;
        outp = g_preC + (size_t)q * F1;
        Kt = 85; off = 1500 + 85 * p;
    }
    if (j < Kt) s[j] = tab[j];
    __syncthreads();
    float acc = 0.f;
    for (int k = 0; k < Kt; k++) acc = fmaf(s[k], W1[(size_t)(off + k) * F1 + j], acc);
    outp[j] = acc;
}

__global__ void split_base(const float* __restrict__ x) {
    int i = blockIdx.x;
    const float* xr = x + (size_t)i * XCOLS;
    __half* a = g_A2 + (size_t)i * KP1;
    for (int k = threadIdx.x; k < KP1; k += blockDim.x) {
        float v = (k < FS) ? xr[1 + k] : 0.f;
        a[k] = __float2half(v);
    }
    int j = threadIdx.x;
    if (j < 128) {
        int li = (int)xr[0] - 1;
        int ri = __float2int_rn(fabsf(xr[FS + 1]) * 10.0f);
        int c0 = (int)xr[XCOLS - 3];
        int c1 = (int)xr[XCOLS - 2];
        int c2 = (int)xr[XCOLS - 1];
        float4 pa = ((const float4*)(g_preL + (size_t)li * F1))[j];
        float4 pb = ((const float4*)(g_preR + (size_t)ri * F1))[j];
        float4 u = ((const float4*)(g_preC + ((size_t)(0 * 256 + c0)) * F1))[j];
        float4 v = ((const float4*)(g_preC + ((size_t)(1 * 256 + c1)) * F1))[j];
        float4 w = ((const float4*)(g_preC + ((size_t)(2 * 256 + c2)) * F1))[j];
        ((float4*)(g_base + (size_t)i * F1))[j] =
            make_float4(pa.x + pb.x + u.x + v.x + w.x, pa.y + pb.y + u.y + v.y + w.y,
                        pa.z + pb.z + u.z + v.z + w.z, pa.w + pb.w + u.w + v.w + w.w);
    }
}

#define W1N (F1 * KP1)
#define W2N (F2 * F1)
#define W3N (F3 * F2)
__global__ void convW(const float* __restrict__ W1, const float* __restrict__ W2,
                      const float* __restrict__ W3) {
    int idx = blockIdx.x * blockDim.x + threadIdx.x;
    if (idx < W1N) {
        int n = idx / KP1, k = idx % KP1;
        float v = (k < FS) ? W1[(size_t)(250 + k) * F1 + n] : 0.f;
        g_W1T[idx] = __float2half(v);
    } else if (idx < W1N + W2N) {
        int q = idx - W1N;
        int n = q / F1, k = q % F1;
        g_W2T[q] = __float2half(W2[(size_t)k * F2 + n]);
    } else if (idx < W1N + W2N + W3N) {
        int q = idx - W1N - W2N;
        int n = q / F2, k = q % F2;
        g_W3T[q] = __float2half(W3[(size_t)k * F3 + n]);
    }
}

// ======================= mma.sync fp16 GEMM (3-stage, 2 CTAs/SM, bn0 offset) =======================
template<int BN>
__device__ __forceinline__ void load_stage(const __half* __restrict__ A,
                                           const __half* __restrict__ B,
                                           int bm, int bn, int Kp, int k0, int M,
                                           uint32_t sA, uint32_t sB) {
    int t = threadIdx.x;
#pragma unroll
    for (int i = 0; i < 4; i++) {
        int idx = t + i * 256;
        int row = idx >> 3, seg = idx & 7;
        int gr = bm + row;
        bool p = gr < M;
        const void* src = A + (size_t)(p ? gr : 0) * Kp + k0 + seg * 8;
        cp16(sA + swz(row * 128 + seg * 16), src, p);
    }
#pragma unroll
    for (int i = 0; i < BN * 8 / 256; i++) {
        int idx = t + i * 256;
        int row = idx >> 3, seg = idx & 7;
        const void* src = B + (size_t)(bn + row) * Kp + k0 + seg * 8;
        cp16(sB + swz(row * 128 + seg * 16), src, true);
    }
}

template<int BN, bool ADD_BASE, bool HALF_OUT>
__global__ __launch_bounds__(256, 2) void mma_gemm(const __half* __restrict__ A,
                                                   const __half* __restrict__ B,
                                                   const float* __restrict__ base,
                                                   void* __restrict__ Cv,
                                                   int M, int Kp, int Nn, int bn0) {
    extern __shared__ char smem[];
    constexpr int WN = BN / 2;
    constexpr int SS = (128 + BN) * 128;
    uint32_t sb = smem_u32(smem);
    int tid = threadIdx.x, wid = tid >> 5, lane = tid & 31;
    int bm = blockIdx.y * 128, bn = bn0 + blockIdx.x * BN;
    int wm = (wid & 3) * 32;
    int wn = (wid >> 2) * WN;

    float acc[2][WN / 8][4];
#pragma unroll
    for (int i = 0; i < 2; i++)
#pragma unroll
        for (int j = 0; j < WN / 8; j++)
#pragma unroll
            for (int q = 0; q < 4; q++) acc[i][j][q] = 0.f;

    int nT = Kp >> 6;
#pragma unroll
    for (int s = 0; s < 2; s++) {
        uint32_t sp = sb + (uint32_t)s * SS;
        load_stage<BN>(A, B, bm, bn, Kp, s * 64, M, sp, sp + 128 * 128);
        CP_COMMIT();
    }

    for (int t = 0; t < nT; t++) {
        if (t + 2 < nT) {
            uint32_t sp = sb + (uint32_t)((t + 2) % 3) * SS;
            load_stage<BN>(A, B, bm, bn, Kp, (t + 2) * 64, M, sp, sp + 128 * 128);
        }
        CP_COMMIT();
        CP_WAIT2();
        __syncthreads();

        uint32_t sA = sb + (uint32_t)(t % 3) * SS;
        uint32_t sB = sA + 128 * 128;
#pragma unroll
        for (int ks = 0; ks < 4; ks++) {
            uint32_t af[2][4];
#pragma unroll
            for (int mi = 0; mi < 2; mi++) {
                int row = wm + mi * 16 + (lane & 15);
                ldsm_x4(af[mi], sA + swz(row * 128 + ks * 32 + ((lane >> 4) << 4)));
            }
#pragma unroll
            for (int nj = 0; nj < WN / 16; nj++) {
                uint32_t bf[4];
                int row = wn + nj * 16 + (lane & 7) + ((lane >> 4) << 3);
                ldsm_x4(bf, sB + swz(row * 128 + ks * 32 + (((lane >> 3) & 1) << 4)));
                mma_f16(acc[0][2 * nj],     af[0], bf);
                mma_f16(acc[0][2 * nj + 1], af[0], bf + 2);
                mma_f16(acc[1][2 * nj],     af[1], bf);
                mma_f16(acc[1][2 * nj + 1], af[1], bf + 2);
            }
        }
        __syncthreads();
    }

#pragma unroll
    for (int mi = 0; mi < 2; mi++) {
#pragma unroll
        for (int nj = 0; nj < WN / 8; nj++) {
            int row = bm + wm + mi * 16 + (lane >> 2);
            int col = bn + wn + nj * 8 + (lane & 3) * 2;
#pragma unroll
            for (int h = 0; h < 2; h++) {
                int r = row + h * 8;
                if (r < M) {
                    float2 v = make_float2(acc[mi][nj][h * 2], acc[mi][nj][h * 2 + 1]);
                    if (ADD_BASE) {
                        float2 b2 = *(const float2*)(base + (size_t)r * Nn + col);
                        v.x += b2.x; v.y += b2.y;
                    }
                    if (HALF_OUT) {
                        *(__half2*)((__half*)Cv + (size_t)r * Nn + col) = __floats2half2_rn(v.x, v.y);
                    } else {
                        *(float2*)((float*)Cv + (size_t)r * Nn + col) = v;
                    }
                }
            }
        }
    }
}

// ======================= fused CSR aggregation (column block, fp16 gather) =======================
template<int F, int COLS, int NPB>
__global__ __launch_bounds__(128) void csr_agg_h(const __half* __restrict__ t,
                                                 const float* __restrict__ b,
                                                 __half* __restrict__ hs, int col0) {
    constexpr int C = COLS / 8;
    constexpr int RS = F / 8;
    int node = blockIdx.x * NPB + threadIdx.x / C;
    int ch = threadIdx.x % C;
    if (node >= N_NODES) return;
    int c8 = (col0 >> 3) + ch;
    int beg = g_rp[node], end = g_rp[node + 1];
    const uint4* tv = (const uint4*)t;
    float d = g_dinv[node];
    float dd = d * d;
    float acc[8];
    {
        uint4 sv = tv[(size_t)node * RS + c8];
        const __half2* h2 = (const __half2*)&sv;
        float4 b0 = ((const float4*)b)[c8 * 2];
        float4 b1v = ((const float4*)b)[c8 * 2 + 1];
        float bb[8] = {b0.x, b0.y, b0.z, b0.w, b1v.x, b1v.y, b1v.z, b1v.w};
#pragma unroll
        for (int q = 0; q < 4; q++) {
            float2 f2 = __half22float2(h2[q]);
            acc[q * 2 + 0] = fmaf(f2.x, dd, bb[q * 2 + 0]);
            acc[q * 2 + 1] = fmaf(f2.y, dd, bb[q * 2 + 1]);
        }
    }
    int stop = beg + ((end - beg) & ~3);
    int i = beg;
    int2 e0, e1, e2, e3;
    if (i < stop) {
        e0 = g_edge[i]; e1 = g_edge[i + 1]; e2 = g_edge[i + 2]; e3 = g_edge[i + 3];
    }
    while (i < stop) {
        int j = i + 4;
        int2 f0, f1, f2n, f3;
        if (j < stop) {
            f0 = g_edge[j]; f1 = g_edge[j + 1]; f2n = g_edge[j + 2]; f3 = g_edge[j + 3];
        }
        uint4 v0 = tv[(size_t)e0.x * RS + c8];
        uint4 v1 = tv[(size_t)e1.x * RS + c8];
        uint4 v2 = tv[(size_t)e2.x * RS + c8];
        uint4 v3 = tv[(size_t)e3.x * RS + c8];
        float w0 = __int_as_float(e0.y), w1 = __int_as_float(e1.y);
        float w2 = __int_as_float(e2.y), w3 = __int_as_float(e3.y);
        const __half2* a0 = (const __half2*)&v0;
        const __half2* a1 = (const __half2*)&v1;
        const __half2* a2 = (const __half2*)&v2;
        const __half2* a3 = (const __half2*)&v3;
#pragma unroll
        for (int q = 0; q < 4; q++) {
            float2 g0 = __half22float2(a0[q]);
            float2 g1 = __half22float2(a1[q]);
            float2 g2 = __half22float2(a2[q]);
            float2 g3 = __half22float2(a3[q]);
            acc[q * 2 + 0] += g0.x * w0 + g1.x * w1 + g2.x * w2 + g3.x * w3;
            acc[q * 2 + 1] += g0.y * w0 + g1.y * w1 + g2.y * w2 + g3.y * w3;
        }
        e0 = f0; e1 = f1; e2 = f2n; e3 = f3;
        i = j;
    }
    for (; i < end; i++) {
        int2 eo = g_edge[i];
        float w0 = __int_as_float(eo.y);
        uint4 v0 = tv[(size_t)eo.x * RS + c8];
        const __half2* a0 = (const __half2*)&v0;
#pragma unroll
        for (int q = 0; q < 4; q++) {
            float2 g0 = __half22float2(a0[q]);
            acc[q * 2 + 0] += g0.x * w0;
            acc[q * 2 + 1] += g0.y * w0;
        }
    }
    __half h[8];
#pragma unroll
    for (int q = 0; q < 8; q++) {
        float u = acc[q] > 0.f ? acc[q] : 0.01f * acc[q];
        h[q] = __float2half(u);
    }
    *(uint4*)(hs + (size_t)node * F + c8 * 8) = *(uint4*)h;
}

template<int F, int NPB>
__global__ __launch_bounds__(128) void csr_agg_proj(const float* __restrict__ t,
                                                    const float* __restrict__ b,
                                                    const float* __restrict__ Wp,
                                                    const float* __restrict__ bp,
                                                    float* __restrict__ out) {
    constexpr int C = F / 4;
    int node = blockIdx.x * NPB + threadIdx.x / C;
    int ch = threadIdx.x % C;
    if (node >= N_NODES) return;
    int beg = g_rp[node], end = g_rp[node + 1];
    const float4* tv = (const float4*)t;
    float d = g_dinv[node];
    float dd = d * d;
    float4 self = tv[(size_t)node * C + ch];
    float4 bv = ((const float4*)b)[ch];
    float4 acc = make_float4(fmaf(self.x, dd, bv.x), fmaf(self.y, dd, bv.y),
                             fmaf(self.z, dd, bv.z), fmaf(self.w, dd, bv.w));
    int stop = beg + ((end - beg) & ~3);
    int i = beg;
    int2 e0, e1, e2, e3;
    if (i < stop) {
        e0 = g_edge[i]; e1 = g_edge[i + 1]; e2 = g_edge[i + 2]; e3 = g_edge[i + 3];
    }
    while (i < stop) {
        int j = i + 4;
        int2 f0, f1, f2n, f3;
        if (j < stop) {
            f0 = g_edge[j]; f1 = g_edge[j + 1]; f2n = g_edge[j + 2]; f3 = g_edge[j + 3];
        }
        float4 v0 = tv[(size_t)e0.x * C + ch];
        float4 v1 = tv[(size_t)e1.x * C + ch];
        float4 v2 = tv[(size_t)e2.x * C + ch];
        float4 v3 = tv[(size_t)e3.x * C + ch];
        float w0 = __int_as_float(e0.y), w1 = __int_as_float(e1.y);
        float w2 = __int_as_float(e2.y), w3 = __int_as_float(e3.y);
        acc.x += v0.x * w0 + v1.x * w1 + v2.x * w2 + v3.x * w3;
        acc.y += v0.y * w0 + v1.y * w1 + v2.y * w2 + v3.y * w3;
        acc.z += v0.z * w0 + v1.z * w1 + v2.z * w2 + v3.z * w3;
        acc.w += v0.w * w0 + v1.w * w1 + v2.w * w2 + v3.w * w3;
        e0 = f0; e1 = f1; e2 = f2n; e3 = f3;
        i = j;
    }
    for (; i < end; i++) {
        int2 eo = g_edge[i];
        float w0 = __int_as_float(eo.y);
        float4 v0 = tv[(size_t)eo.x * C + ch];
        acc.x += v0.x * w0; acc.y += v0.y * w0; acc.z += v0.z * w0; acc.w += v0.w * w0;
    }
    float f[4] = {acc.x, acc.y, acc.z, acc.w};
#pragma unroll
    for (int q = 0; q < 4; q++) f[q] = f[q] > 0.f ? f[q] : 0.01f * f[q];
    float a0 = 0.f, a1 = 0.f, a2 = 0.f;
#pragma unroll
    for (int q = 0; q < 4; q++) {
        int k = ch * 4 + q;
        a0 = fmaf(f[q], __ldg(Wp + k * 3 + 0), a0);
        a1 = fmaf(f[q], __ldg(Wp + k * 3 + 1), a1);
        a2 = fmaf(f[q], __ldg(Wp + k * 3 + 2), a2);
    }
#pragma unroll
    for (int off = C / 2; off; off >>= 1) {
        a0 += __shfl_down_sync(0xffffffffu, a0, off, C);
        a1 += __shfl_down_sync(0xffffffffu, a1, off, C);
        a2 += __shfl_down_sync(0xffffffffu, a2, off, C);
    }
    if (ch == 0) {
        out[(size_t)node * 3 + 0] = a0 + bp[0];
        out[(size_t)node * 3 + 1] = a1 + bp[1];
        out[(size_t)node * 3 + 2] = a2 + bp[2];
    }
}

// ======================= launch =======================
extern "C" void kernel_launch(void* const* d_in, const int* in_sizes, int n_in,
                              void* d_out, int out_size) {
    const float* x           = (const float*)d_in[0];
    const int*   edge_index  = (const int*)  d_in[1];
    const float* edge_attr   = (const float*)d_in[2];
    const float* layer_table = (const float*)d_in[3];
    const float* rel_table   = (const float*)d_in[4];
    const float* color_table = (const float*)d_in[5];
    const float* W1 = (const float*)d_in[6];
    const float* b1 = (const float*)d_in[7];
    const float* W2 = (const float*)d_in[8];
    const float* b2 = (const float*)d_in[9];
    const float* W3 = (const float*)d_in[10];
    const float* b3 = (const float*)d_in[11];
    const float* Wp = (const float*)d_in[12];
    const float* bp = (const float*)d_in[13];
    float* out = (float*)d_out;

    __half *p_A2, *p_h2s, *p_h3s, *p_W1T, *p_W2T, *p_W3T;
    float *p_base, *p_t;
    cudaGetSymbolAddress((void**)&p_A2,   g_A2);
    cudaGetSymbolAddress((void**)&p_h2s,  g_h2s);
    cudaGetSymbolAddress((void**)&p_h3s,  g_h3s);
    cudaGetSymbolAddress((void**)&p_W1T,  g_W1T);
    cudaGetSymbolAddress((void**)&p_W2T,  g_W2T);
    cudaGetSymbolAddress((void**)&p_W3T,  g_W3T);
    cudaGetSymbolAddress((void**)&p_base, g_base);
    cudaGetSymbolAddress((void**)&p_t,    g_t);
    __half* p_th = (__half*)p_t;

    const int T = 256;
    const int SM128 = 3 * (128 + 128) * 128;   // 98304
    const int SM64  = 3 * (128 + 64) * 128;    // 73728
    cudaFuncSetAttribute((const void*)mma_gemm<128, true,  true>,  cudaFuncAttributeMaxDynamicSharedMemorySize, SM128);
    cudaFuncSetAttribute((const void*)mma_gemm<128, false, true>,  cudaFuncAttributeMaxDynamicSharedMemorySize, SM128);
    cudaFuncSetAttribute((const void*)mma_gemm<64,  false, false>, cudaFuncAttributeMaxDynamicSharedMemorySize, SM64);

    // Side stream + events: parallel graph branches under capture.
    // Not destroyed mid-capture (illegal); hold no tracked device memory.
    cudaStream_t s2;
    cudaStreamCreateWithFlags(&s2, cudaStreamNonBlocking);
    cudaEvent_t evFork, evG1a, evA1a, evG2a, evA2a;
    cudaEventCreateWithFlags(&evFork, cudaEventDisableTiming);
    cudaEventCreateWithFlags(&evG1a,  cudaEventDisableTiming);
    cudaEventCreateWithFlags(&evA1a,  cudaEventDisableTiming);
    cudaEventCreateWithFlags(&evG2a,  cudaEventDisableTiming);
    cudaEventCreateWithFlags(&evA2a,  cudaEventDisableTiming);

    cudaEventRecord(evFork, 0);
    cudaStreamWaitEvent(s2, evFork, 0);

    // ---- side branch: CSR build ----
    zero_both<<<(N_NODES + T - 1) / T, T, 0, s2>>>();
    deg_kernel<<<(N_EDGES + T - 1) / T, T, 0, s2>>>(edge_index, edge_attr);
    scan_kernel<<<1, 1024, 0, s2>>>();
    scatter_kernel<<<(N_EDGES + T - 1) / T, T, 0, s2>>>(edge_index, edge_attr);

    // ---- main branch: GEMM inputs ----
    convW<<<(W1N + W2N + W3N + T - 1) / T, T>>>(W1, W2, W3);
    pre_all<<<782, 512>>>(layer_table, rel_table, color_table, W1);
    split_base<<<N_NODES, T>>>(x);

    const int MT = (N_NODES + 127) / 128;   // 157

    // ======== layer 1: split-N pipeline (agg writes g_h2s; GEMM1 reads g_A2 — no aliasing) ========
    mma_gemm<128, true, true><<<dim3(2, MT), T, SM128>>>(p_A2, p_W1T, p_base, p_th, N_NODES, KP1, F1, 0);
    cudaEventRecord(evG1a, 0);
    mma_gemm<128, true, true><<<dim3(2, MT), T, SM128>>>(p_A2, p_W1T, p_base, p_th, N_NODES, KP1, F1, 256);

    cudaStreamWaitEvent(s2, evG1a, 0);   // s2 already ordered after CSR build
    csr_agg_h<F1, 256, 4><<<(N_NODES + 3) / 4, 128, 0, s2>>>(p_th, b1, p_h2s, 0);
    cudaEventRecord(evA1a, s2);

    cudaStreamWaitEvent(0, evA1a, 0);    // orders CSR + agg1a before main's agg1b
    csr_agg_h<F1, 256, 4><<<(N_NODES + 3) / 4, 128>>>(p_th, b1, p_h2s, 256);

    // ======== layer 2: split-N pipeline (GEMM2 reads g_h2s; agg2 writes g_h3s — no aliasing) ========
    mma_gemm<128, false, true><<<dim3(1, MT), T, SM128>>>(p_h2s, p_W2T, nullptr, p_th, N_NODES, F1, F2, 0);
    cudaEventRecord(evG2a, 0);
    mma_gemm<128, false, true><<<dim3(1, MT), T, SM128>>>(p_h2s, p_W2T, nullptr, p_th, N_NODES, F1, F2, 128);

    cudaStreamWaitEvent(s2, evG2a, 0);
    csr_agg_h<F2, 128, 8><<<(N_NODES + 7) / 8, 128, 0, s2>>>(p_th, b2, p_h3s, 0);
    cudaEventRecord(evA2a, s2);

    cudaStreamWaitEvent(0, evA2a, 0);
    csr_agg_h<F2, 128, 8><<<(N_NODES + 7) / 8, 128>>>(p_th, b2, p_h3s, 128);

    // ======== layer 3 (serial, projection fused; reads g_h3s) ========
    mma_gemm<64, false, false><<<dim3(1, MT), T, SM64>>>(p_h3s, p_W3T, nullptr, p_t, N_NODES, F2, F3, 0);
    csr_agg_proj<F3, 8><<<(N_NODES + 7) / 8, 128>>>(p_t, b3, Wp, bp, out);
}